// round 1
// baseline (speedup 1.0000x reference)
#include <cuda_runtime.h>

// Problem constants
#define Bsz  2
#define Tn   1024
#define Cn   1024
#define Hn   16
#define HDn  64
#define Vn   50257
#define BTn  2048
#define NBH  32          // B*H

// Scratch (static device globals; no allocation)
__device__ float g_x[BTn * Cn];            // embedded input  [BT, C]
__device__ float g_q[BTn * Cn];            // [B,H,T,HD] (q pre-scaled by C^-0.5)
__device__ float g_k[BTn * Cn];
__device__ float g_v[BTn * Cn];
__device__ float g_p[NBH * Tn * Tn];       // scores -> probs [BH, T, T]
__device__ float g_a[BTn * Cn];            // attention out, head-concat [BT, C]

#define APAD 20
#define BPAD 136
#define BPAD2 72

__device__ __forceinline__ unsigned f2tf(float f) {
    unsigned r;
    asm("cvt.rna.tf32.f32 %0, %1;" : "=r"(r) : "f"(f));
    return r;
}
__device__ __forceinline__ uint4 tf4(float4 v) {
    uint4 r; r.x = f2tf(v.x); r.y = f2tf(v.y); r.z = f2tf(v.z); r.w = f2tf(v.w);
    return r;
}

__device__ __forceinline__ void mma8(float* c, const unsigned* a, const unsigned* b) {
    asm volatile(
        "mma.sync.aligned.m16n8k8.row.col.f32.tf32.tf32.f32 "
        "{%0,%1,%2,%3},{%4,%5,%6,%7},{%8,%9},{%0,%1,%2,%3};"
        : "+f"(c[0]), "+f"(c[1]), "+f"(c[2]), "+f"(c[3])
        : "r"(a[0]), "r"(a[1]), "r"(a[2]), "r"(a[3]), "r"(b[0]), "r"(b[1]));
}

// Warp computes 32 x (NT*8) tile. As: [128][APAD] (tf32 bits), Bs: [16][BP]
template <int NT, int BP>
__device__ __forceinline__ void mma_step(const unsigned* __restrict__ As,
                                         const unsigned* __restrict__ Bs,
                                         float (&c)[2][NT][4],
                                         int m0, int n0, int g, int tig) {
#pragma unroll
    for (int ks = 0; ks < 2; ks++) {
        const int k8 = ks * 8;
        unsigned a[2][4];
#pragma unroll
        for (int mt = 0; mt < 2; mt++) {
            const unsigned* ap = As + (m0 + mt * 16 + g) * APAD + k8 + tig;
            a[mt][0] = ap[0];
            a[mt][1] = ap[8 * APAD];
            a[mt][2] = ap[4];
            a[mt][3] = ap[8 * APAD + 4];
        }
        unsigned b[NT][2];
#pragma unroll
        for (int nt = 0; nt < NT; nt++) {
            const unsigned* bp = Bs + (k8 + tig) * BP + n0 + nt * 8 + g;
            b[nt][0] = bp[0];
            b[nt][1] = bp[4 * BP];
        }
#pragma unroll
        for (int mt = 0; mt < 2; mt++)
#pragma unroll
            for (int nt = 0; nt < NT; nt++) mma8(c[mt][nt], a[mt], b[nt]);
    }
}

// ---------------------------------------------------------------------------
// 1) Embedding: x[b,t,:] = tok_emb[idx[b,t],:] + pos_emb[t,:]
__global__ __launch_bounds__(256) void k_embed(const int* __restrict__ idx,
                                               const float* __restrict__ tok,
                                               const float* __restrict__ pos) {
    int i = blockIdx.x;              // 0..2047
    int t = i & (Tn - 1);
    int token = idx[i];
    const float4* te = (const float4*)(tok + (size_t)token * Cn);
    const float4* pe = (const float4*)(pos + (size_t)t * Cn);
    float4 a = te[threadIdx.x], b = pe[threadIdx.x];
    float4 o;
    o.x = a.x + b.x; o.y = a.y + b.y; o.z = a.z + b.z; o.w = a.w + b.w;
    ((float4*)(g_x + (size_t)i * Cn))[threadIdx.x] = o;
}

// ---------------------------------------------------------------------------
// 2) QKV projection: q[bt, (h,d)] = sum_c x[bt,c] * W[h,c,d]; q scaled 1/32.
//    grid (16, 8, 3) blocks of 256, tile 128x128, K=1024
__global__ __launch_bounds__(256) void k_qkv(const float* __restrict__ Wq,
                                             const float* __restrict__ Wk,
                                             const float* __restrict__ Wv) {
    __shared__ unsigned As[128 * APAD];
    __shared__ unsigned Bs[16 * BPAD];
    const float* W = (blockIdx.z == 0) ? Wq : (blockIdx.z == 1) ? Wk : Wv;
    float* o = (blockIdx.z == 0) ? g_q : (blockIdx.z == 1) ? g_k : g_v;
    const int bm = blockIdx.x, bn = blockIdx.y;
    const int tid = threadIdx.x, lane = tid & 31, warp = tid >> 5;
    const int g = lane >> 2, tig = lane & 3;
    const int m0 = (warp >> 1) * 32, n0 = (warp & 1) * 64;

    float c[2][8][4];
#pragma unroll
    for (int mt = 0; mt < 2; mt++)
#pragma unroll
        for (int nt = 0; nt < 8; nt++)
#pragma unroll
            for (int e = 0; e < 4; e++) c[mt][nt][e] = 0.f;

    // A loader (P1): row-major x, contiguous k
    const int lm = tid & 127, lkk = (tid >> 7) * 8;
    // B loader (P3): W[h][c][d], contiguous along d (=n)
    const int bkk = tid >> 4, bn8 = (tid & 15) * 8;
    const int gn0 = bn * 128 + bn8;
    const int h = gn0 >> 6, d = gn0 & 63;
    const float* Wb = W + (size_t)h * (Cn * HDn) + d;
    const float* Ab = g_x + (size_t)(bm * 128 + lm) * Cn + lkk;

    for (int k0 = 0; k0 < Cn; k0 += 16) {
        float4 a0 = *(const float4*)(Ab + k0);
        float4 a1 = *(const float4*)(Ab + k0 + 4);
        float4 b0 = *(const float4*)(Wb + (size_t)(k0 + bkk) * HDn);
        float4 b1 = *(const float4*)(Wb + (size_t)(k0 + bkk) * HDn + 4);
        __syncthreads();
        *(uint4*)(As + lm * APAD + lkk)     = tf4(a0);
        *(uint4*)(As + lm * APAD + lkk + 4) = tf4(a1);
        *(uint4*)(Bs + bkk * BPAD + bn8)     = tf4(b0);
        *(uint4*)(Bs + bkk * BPAD + bn8 + 4) = tf4(b1);
        __syncthreads();
        mma_step<8, BPAD>(As, Bs, c, m0, n0, g, tig);
    }

    const float scale = (blockIdx.z == 0) ? 0.03125f : 1.0f;
#pragma unroll
    for (int mt = 0; mt < 2; mt++)
#pragma unroll
        for (int nt = 0; nt < 8; nt++) {
            int r = bm * 128 + m0 + mt * 16 + g;
            int cl = bn * 128 + n0 + nt * 8 + 2 * tig;
#pragma unroll
            for (int e = 0; e < 4; e++) {
                int rr = r + ((e >= 2) ? 8 : 0);
                int cc = cl + (e & 1);
                int b2 = rr >> 10, t2 = rr & 1023;
                int hh = cc >> 6, dd = cc & 63;
                o[(((size_t)(b2 * Hn + hh)) * Tn + t2) * HDn + dd] = c[mt][nt][e] * scale;
            }
        }
}

// ---------------------------------------------------------------------------
// 3) Scores: S[bh, t, s] = q[bh,t,:] . k[bh,s,:]   (q pre-scaled)
//    grid (8, 8, 32); blocks fully above the diagonal skipped.
__global__ __launch_bounds__(256) void k_scores() {
    const int bm = blockIdx.x, bn = blockIdx.y, bh = blockIdx.z;
    if (bn > bm) return;
    __shared__ unsigned As[128 * APAD];
    __shared__ unsigned Bs[16 * BPAD];
    const int tid = threadIdx.x, lane = tid & 31, warp = tid >> 5;
    const int g = lane >> 2, tig = lane & 3;
    const int m0 = (warp >> 1) * 32, n0 = (warp & 1) * 64;

    float c[2][8][4];
#pragma unroll
    for (int mt = 0; mt < 2; mt++)
#pragma unroll
        for (int nt = 0; nt < 8; nt++)
#pragma unroll
            for (int e = 0; e < 4; e++) c[mt][nt][e] = 0.f;

    const int lm = tid & 127, lkk = (tid >> 7) * 8;
    const float* Aq = g_q + (size_t)bh * (Tn * HDn) + (size_t)(bm * 128 + lm) * HDn + lkk;
    const float* Bk = g_k + (size_t)bh * (Tn * HDn) + (size_t)(bn * 128 + lm) * HDn + lkk;

    for (int k0 = 0; k0 < HDn; k0 += 16) {
        float4 a0 = *(const float4*)(Aq + k0);
        float4 a1 = *(const float4*)(Aq + k0 + 4);
        float4 b0 = *(const float4*)(Bk + k0);
        float4 b1 = *(const float4*)(Bk + k0 + 4);
        __syncthreads();
        *(uint4*)(As + lm * APAD + lkk)     = tf4(a0);
        *(uint4*)(As + lm * APAD + lkk + 4) = tf4(a1);
        // transpose-store B (P2): element (k0+lkk+j, lm)
        float bv[8] = {b0.x, b0.y, b0.z, b0.w, b1.x, b1.y, b1.z, b1.w};
#pragma unroll
        for (int j = 0; j < 8; j++) Bs[(lkk + j) * BPAD + lm] = f2tf(bv[j]);
        __syncthreads();
        mma_step<8, BPAD>(As, Bs, c, m0, n0, g, tig);
    }

    float* P = g_p + (size_t)bh * (Tn * Tn);
#pragma unroll
    for (int mt = 0; mt < 2; mt++)
#pragma unroll
        for (int nt = 0; nt < 8; nt++) {
            int r = bm * 128 + m0 + mt * 16 + g;
            int cl = bn * 128 + n0 + nt * 8 + 2 * tig;
#pragma unroll
            for (int e = 0; e < 4; e++) {
                int rr = r + ((e >= 2) ? 8 : 0);
                int cc = cl + (e & 1);
                P[(size_t)rr * Tn + cc] = c[mt][nt][e];
            }
        }
}

// ---------------------------------------------------------------------------
// 4) Row softmax over s in [0, t]; zeros written for s > t (full 1024 row).
__global__ __launch_bounds__(256) void k_softmax() {
    const int row = blockIdx.x;          // 0..32767 = bh*1024 + t
    const int t = row & (Tn - 1);
    float* pr = g_p + (size_t)row * Tn;
    const int tid = threadIdx.x;
    const int len = t + 1;

    __shared__ float red[8];
    __shared__ float bval;

    float v[4];
    float mx = -1e30f;
#pragma unroll
    for (int i = 0; i < 4; i++) {
        int s = tid + i * 256;
        v[i] = (s < len) ? pr[s] : -1e30f;
        mx = fmaxf(mx, v[i]);
    }
#pragma unroll
    for (int o = 16; o; o >>= 1) mx = fmaxf(mx, __shfl_xor_sync(0xffffffffu, mx, o));
    if ((tid & 31) == 0) red[tid >> 5] = mx;
    __syncthreads();
    if (tid == 0) {
        float m2 = red[0];
#pragma unroll
        for (int i = 1; i < 8; i++) m2 = fmaxf(m2, red[i]);
        bval = m2;
    }
    __syncthreads();
    mx = bval;

    float sum = 0.f;
#pragma unroll
    for (int i = 0; i < 4; i++) {
        int s = tid + i * 256;
        float e = (s < len) ? __expf(v[i] - mx) : 0.f;
        v[i] = e;
        sum += e;
    }
#pragma unroll
    for (int o = 16; o; o >>= 1) sum += __shfl_xor_sync(0xffffffffu, sum, o);
    if ((tid & 31) == 0) red[tid >> 5] = sum;
    __syncthreads();
    if (tid == 0) {
        float s2 = 0.f;
#pragma unroll
        for (int i = 0; i < 8; i++) s2 += red[i];
        bval = s2;
    }
    __syncthreads();
    const float inv = 1.0f / bval;
#pragma unroll
    for (int i = 0; i < 4; i++) {
        int s = tid + i * 256;
        pr[s] = v[i] * inv;     // v[i]==0 for s>=len -> zero-filled tail
    }
}

// ---------------------------------------------------------------------------
// 5) PV: O[bh,t,d] = sum_s P[bh,t,s] v[bh,s,d]; K truncated at diagonal block.
//    grid (8, 1, 32); block 128x64, warp 32x32.
__global__ __launch_bounds__(256) void k_pv() {
    const int bm = blockIdx.x, bh = blockIdx.z;
    __shared__ unsigned As[128 * APAD];
    __shared__ unsigned Bs[16 * BPAD2];
    const int tid = threadIdx.x, lane = tid & 31, warp = tid >> 5;
    const int g = lane >> 2, tig = lane & 3;
    const int m0 = (warp >> 1) * 32, n0 = (warp & 1) * 32;

    float c[2][4][4];
#pragma unroll
    for (int mt = 0; mt < 2; mt++)
#pragma unroll
        for (int nt = 0; nt < 4; nt++)
#pragma unroll
            for (int e = 0; e < 4; e++) c[mt][nt][e] = 0.f;

    const int lm = tid & 127, lkk = (tid >> 7) * 8;
    const int bkk = tid >> 4, bn4 = (tid & 15) * 4;
    const float* Ap = g_p + (size_t)bh * (Tn * Tn) + (size_t)(bm * 128 + lm) * Tn + lkk;
    const float* Bv = g_v + (size_t)bh * (Tn * HDn) + bn4;
    const int kmax = (bm + 1) * 128;

    for (int k0 = 0; k0 < kmax; k0 += 16) {
        float4 a0 = *(const float4*)(Ap + k0);
        float4 a1 = *(const float4*)(Ap + k0 + 4);
        float4 b0 = *(const float4*)(Bv + (size_t)(k0 + bkk) * HDn);
        __syncthreads();
        *(uint4*)(As + lm * APAD + lkk)     = tf4(a0);
        *(uint4*)(As + lm * APAD + lkk + 4) = tf4(a1);
        *(uint4*)(Bs + bkk * BPAD2 + bn4)   = tf4(b0);
        __syncthreads();
        mma_step<4, BPAD2>(As, Bs, c, m0, n0, g, tig);
    }

    const int b2 = bh >> 4, hh = bh & 15;
#pragma unroll
    for (int mt = 0; mt < 2; mt++)
#pragma unroll
        for (int nt = 0; nt < 4; nt++) {
            int r = bm * 128 + m0 + mt * 16 + g;      // t
            int cl = n0 + nt * 8 + 2 * tig;           // d
#pragma unroll
            for (int e = 0; e < 4; e++) {
                int rr = r + ((e >= 2) ? 8 : 0);
                int cc = cl + (e & 1);
                g_a[((size_t)(b2 * Tn + rr)) * Cn + hh * HDn + cc] = c[mt][nt][e];
            }
        }
}

// ---------------------------------------------------------------------------
// 6) LM head: logits[bt, v] = attn[bt,:] . W_lm[v,:] + b_lm[v]
//    grid (16, 393): M on x so a launch wave shares W_lm slabs in L2.
__global__ __launch_bounds__(256) void k_logits(const float* __restrict__ Wlm,
                                                const float* __restrict__ blm,
                                                float* __restrict__ out) {
    __shared__ unsigned As[128 * APAD];
    __shared__ unsigned Bs[16 * BPAD];
    const int bm = blockIdx.x, bn = blockIdx.y;
    const int tid = threadIdx.x, lane = tid & 31, warp = tid >> 5;
    const int g = lane >> 2, tig = lane & 3;
    const int m0 = (warp >> 1) * 32, n0 = (warp & 1) * 64;

    float c[2][8][4];
#pragma unroll
    for (int mt = 0; mt < 2; mt++)
#pragma unroll
        for (int nt = 0; nt < 8; nt++)
#pragma unroll
            for (int e = 0; e < 4; e++) c[mt][nt][e] = 0.f;

    const int lm = tid & 127, lkk = (tid >> 7) * 8;
    const float* Ab = g_a + (size_t)(bm * 128 + lm) * Cn + lkk;
    const int gn = bn * 128 + lm;
    const bool nvalid = (gn < Vn);
    const float* Bb = Wlm + (size_t)gn * Cn + lkk;

    for (int k0 = 0; k0 < Cn; k0 += 16) {
        float4 a0 = *(const float4*)(Ab + k0);
        float4 a1 = *(const float4*)(Ab + k0 + 4);
        float4 b0, b1;
        if (nvalid) {
            b0 = *(const float4*)(Bb + k0);
            b1 = *(const float4*)(Bb + k0 + 4);
        } else {
            b0 = make_float4(0.f, 0.f, 0.f, 0.f);
            b1 = b0;
        }
        __syncthreads();
        *(uint4*)(As + lm * APAD + lkk)     = tf4(a0);
        *(uint4*)(As + lm * APAD + lkk + 4) = tf4(a1);
        float bv[8] = {b0.x, b0.y, b0.z, b0.w, b1.x, b1.y, b1.z, b1.w};
#pragma unroll
        for (int j = 0; j < 8; j++) Bs[(lkk + j) * BPAD + lm] = f2tf(bv[j]);
        __syncthreads();
        mma_step<8, BPAD>(As, Bs, c, m0, n0, g, tig);
    }

#pragma unroll
    for (int mt = 0; mt < 2; mt++)
#pragma unroll
        for (int nt = 0; nt < 8; nt++) {
            int r = bm * 128 + m0 + mt * 16 + g;
            int cl = bn * 128 + n0 + nt * 8 + 2 * tig;
#pragma unroll
            for (int e = 0; e < 4; e++) {
                int rr = r + ((e >= 2) ? 8 : 0);
                int cc = cl + (e & 1);
                if (cc < Vn) out[(size_t)rr * Vn + cc] = c[mt][nt][e] + blm[cc];
            }
        }
}

// ---------------------------------------------------------------------------
extern "C" void kernel_launch(void* const* d_in, const int* in_sizes, int n_in,
                              void* d_out, int out_size) {
    (void)in_sizes; (void)n_in; (void)out_size;
    const int*   idx = (const int*)d_in[0];
    const float* tok = (const float*)d_in[1];
    const float* pos = (const float*)d_in[2];
    const float* Wq  = (const float*)d_in[3];
    const float* Wk  = (const float*)d_in[4];
    const float* Wv  = (const float*)d_in[5];
    const float* Wlm = (const float*)d_in[6];
    const float* blm = (const float*)d_in[7];
    float* out = (float*)d_out;

    k_embed<<<BTn, 256>>>(idx, tok, pos);
    k_qkv<<<dim3(16, 8, 3), 256>>>(Wq, Wk, Wv);
    k_scores<<<dim3(8, 8, NBH), 256>>>();
    k_softmax<<<NBH * Tn, 256>>>();
    k_pv<<<dim3(8, 1, NBH), 256>>>();
    k_logits<<<dim3(16, 393), 256>>>(Wlm, blm, out);
}

// round 5
// speedup vs baseline: 2.3087x; 2.3087x over previous
#include <cuda_runtime.h>
#include <cuda_fp16.h>
#include <cstdint>

// Problem constants
#define Bsz  2
#define Tn   1024
#define Cn   1024
#define Hn   16
#define HDn  64
#define Vn   50257
#define BTn  2048
#define NBH  32          // B*H

// Scratch (static device globals; no allocation)
__device__ float g_x[BTn * Cn];            // embedded input  [BT, C]
__device__ float g_q[BTn * Cn];            // [B,H,T,HD] (q pre-scaled by C^-0.5)
__device__ float g_k[BTn * Cn];
__device__ float g_v[BTn * Cn];
__device__ float g_p[NBH * Tn * Tn];       // scores -> probs [BH, T, T]
__device__ __half g_ah[BTn * Cn];          // attention out (fp16), head-concat [BT, C]
__device__ __half g_wh[(size_t)Vn * Cn];   // W_lm in fp16

#define APAD 20
#define BPAD 136
#define BPAD2 72

__device__ __forceinline__ unsigned f2tf(float f) {
    unsigned r;
    asm("cvt.rna.tf32.f32 %0, %1;" : "=r"(r) : "f"(f));
    return r;
}
__device__ __forceinline__ uint4 tf4(float4 v) {
    uint4 r; r.x = f2tf(v.x); r.y = f2tf(v.y); r.z = f2tf(v.z); r.w = f2tf(v.w);
    return r;
}

__device__ __forceinline__ void mma8(float* c, const unsigned* a, const unsigned* b) {
    asm volatile(
        "mma.sync.aligned.m16n8k8.row.col.f32.tf32.tf32.f32 "
        "{%0,%1,%2,%3},{%4,%5,%6,%7},{%8,%9},{%0,%1,%2,%3};"
        : "+f"(c[0]), "+f"(c[1]), "+f"(c[2]), "+f"(c[3])
        : "r"(a[0]), "r"(a[1]), "r"(a[2]), "r"(a[3]), "r"(b[0]), "r"(b[1]));
}

template <int NT, int BP>
__device__ __forceinline__ void mma_step(const unsigned* __restrict__ As,
                                         const unsigned* __restrict__ Bs,
                                         float (&c)[2][NT][4],
                                         int m0, int n0, int g, int tig) {
#pragma unroll
    for (int ks = 0; ks < 2; ks++) {
        const int k8 = ks * 8;
        unsigned a[2][4];
#pragma unroll
        for (int mt = 0; mt < 2; mt++) {
            const unsigned* ap = As + (m0 + mt * 16 + g) * APAD + k8 + tig;
            a[mt][0] = ap[0];
            a[mt][1] = ap[8 * APAD];
            a[mt][2] = ap[4];
            a[mt][3] = ap[8 * APAD + 4];
        }
        unsigned b[NT][2];
#pragma unroll
        for (int nt = 0; nt < NT; nt++) {
            const unsigned* bp = Bs + (k8 + tig) * BP + n0 + nt * 8 + g;
            b[nt][0] = bp[0];
            b[nt][1] = bp[4 * BP];
        }
#pragma unroll
        for (int mt = 0; mt < 2; mt++)
#pragma unroll
            for (int nt = 0; nt < NT; nt++) mma8(c[mt][nt], a[mt], b[nt]);
    }
}

// ===========================================================================
// fp16 legacy-mma helpers (sm_80 baseline ISA; compiles on sm_103 plain)
// ===========================================================================
__device__ __forceinline__ uint32_t smem_u32(const void* p) {
    return (uint32_t)__cvta_generic_to_shared(p);
}
__device__ __forceinline__ void mma16(float* c, const unsigned* a, const unsigned* b) {
    asm volatile(
        "mma.sync.aligned.m16n8k16.row.col.f32.f16.f16.f32 "
        "{%0,%1,%2,%3},{%4,%5,%6,%7},{%8,%9},{%0,%1,%2,%3};"
        : "+f"(c[0]), "+f"(c[1]), "+f"(c[2]), "+f"(c[3])
        : "r"(a[0]), "r"(a[1]), "r"(a[2]), "r"(a[3]), "r"(b[0]), "r"(b[1]));
}
__device__ __forceinline__ void ldsm4(unsigned& r0, unsigned& r1, unsigned& r2,
                                      unsigned& r3, uint32_t addr) {
    asm volatile("ldmatrix.sync.aligned.m8n8.x4.shared.b16 {%0,%1,%2,%3}, [%4];"
                 : "=r"(r0), "=r"(r1), "=r"(r2), "=r"(r3) : "r"(addr));
}
__device__ __forceinline__ void cpa16(uint32_t dst, const void* src) {
    asm volatile("cp.async.cg.shared.global [%0], [%1], 16;"
                 :: "r"(dst), "l"(src));
}
__device__ __forceinline__ void cpa16z(uint32_t dst, const void* src, int sz) {
    asm volatile("cp.async.cg.shared.global [%0], [%1], 16, %2;"
                 :: "r"(dst), "l"(src), "r"(sz));
}
#define CPA_COMMIT() asm volatile("cp.async.commit_group;" ::: "memory")
#define CPA_WAIT1()  asm volatile("cp.async.wait_group 1;" ::: "memory")

// ---------------------------------------------------------------------------
// 1) Embedding
__global__ __launch_bounds__(256) void k_embed(const int* __restrict__ idx,
                                               const float* __restrict__ tok,
                                               const float* __restrict__ pos) {
    int i = blockIdx.x;
    int t = i & (Tn - 1);
    int token = idx[i];
    const float4* te = (const float4*)(tok + (size_t)token * Cn);
    const float4* pe = (const float4*)(pos + (size_t)t * Cn);
    float4 a = te[threadIdx.x], b = pe[threadIdx.x];
    float4 o;
    o.x = a.x + b.x; o.y = a.y + b.y; o.z = a.z + b.z; o.w = a.w + b.w;
    ((float4*)(g_x + (size_t)i * Cn))[threadIdx.x] = o;
}

// ---------------------------------------------------------------------------
// 1b) W_lm -> fp16
__global__ __launch_bounds__(256) void k_w2h(const float* __restrict__ W) {
    size_t t = (size_t)blockIdx.x * 256 + threadIdx.x;
    if (t >= ((size_t)Vn * Cn) / 8) return;
    const float4* s = (const float4*)W + t * 2;
    float4 x = s[0], y = s[1];
    __half2 h0 = __floats2half2_rn(x.x, x.y);
    __half2 h1 = __floats2half2_rn(x.z, x.w);
    __half2 h2 = __floats2half2_rn(y.x, y.y);
    __half2 h3 = __floats2half2_rn(y.z, y.w);
    uint4 o;
    o.x = *(unsigned*)&h0; o.y = *(unsigned*)&h1;
    o.z = *(unsigned*)&h2; o.w = *(unsigned*)&h3;
    ((uint4*)g_wh)[t] = o;
}

// ---------------------------------------------------------------------------
// 2) QKV projection (legacy tf32, unchanged)
__global__ __launch_bounds__(256) void k_qkv(const float* __restrict__ Wq,
                                             const float* __restrict__ Wk,
                                             const float* __restrict__ Wv) {
    __shared__ unsigned As[128 * APAD];
    __shared__ unsigned Bs[16 * BPAD];
    const float* W = (blockIdx.z == 0) ? Wq : (blockIdx.z == 1) ? Wk : Wv;
    float* o = (blockIdx.z == 0) ? g_q : (blockIdx.z == 1) ? g_k : g_v;
    const int bm = blockIdx.x, bn = blockIdx.y;
    const int tid = threadIdx.x, lane = tid & 31, warp = tid >> 5;
    const int g = lane >> 2, tig = lane & 3;
    const int m0 = (warp >> 1) * 32, n0 = (warp & 1) * 64;

    float c[2][8][4];
#pragma unroll
    for (int mt = 0; mt < 2; mt++)
#pragma unroll
        for (int nt = 0; nt < 8; nt++)
#pragma unroll
            for (int e = 0; e < 4; e++) c[mt][nt][e] = 0.f;

    const int lm = tid & 127, lkk = (tid >> 7) * 8;
    const int bkk = tid >> 4, bn8 = (tid & 15) * 8;
    const int gn0 = bn * 128 + bn8;
    const int h = gn0 >> 6, d = gn0 & 63;
    const float* Wb = W + (size_t)h * (Cn * HDn) + d;
    const float* Ab = g_x + (size_t)(bm * 128 + lm) * Cn + lkk;

    for (int k0 = 0; k0 < Cn; k0 += 16) {
        float4 a0 = *(const float4*)(Ab + k0);
        float4 a1 = *(const float4*)(Ab + k0 + 4);
        float4 b0 = *(const float4*)(Wb + (size_t)(k0 + bkk) * HDn);
        float4 b1 = *(const float4*)(Wb + (size_t)(k0 + bkk) * HDn + 4);
        __syncthreads();
        *(uint4*)(As + lm * APAD + lkk)     = tf4(a0);
        *(uint4*)(As + lm * APAD + lkk + 4) = tf4(a1);
        *(uint4*)(Bs + bkk * BPAD + bn8)     = tf4(b0);
        *(uint4*)(Bs + bkk * BPAD + bn8 + 4) = tf4(b1);
        __syncthreads();
        mma_step<8, BPAD>(As, Bs, c, m0, n0, g, tig);
    }

    const float scale = (blockIdx.z == 0) ? 0.03125f : 1.0f;
#pragma unroll
    for (int mt = 0; mt < 2; mt++)
#pragma unroll
        for (int nt = 0; nt < 8; nt++) {
            int r = bm * 128 + m0 + mt * 16 + g;
            int cl = bn * 128 + n0 + nt * 8 + 2 * tig;
#pragma unroll
            for (int e = 0; e < 4; e++) {
                int rr = r + ((e >= 2) ? 8 : 0);
                int cc = cl + (e & 1);
                int b2 = rr >> 10, t2 = rr & 1023;
                int hh = cc >> 6, dd = cc & 63;
                o[(((size_t)(b2 * Hn + hh)) * Tn + t2) * HDn + dd] = c[mt][nt][e] * scale;
            }
        }
}

// ---------------------------------------------------------------------------
// 3) Scores (legacy tf32, unchanged)
__global__ __launch_bounds__(256) void k_scores() {
    const int bm = blockIdx.x, bn = blockIdx.y, bh = blockIdx.z;
    if (bn > bm) return;
    __shared__ unsigned As[128 * APAD];
    __shared__ unsigned Bs[16 * BPAD];
    const int tid = threadIdx.x, lane = tid & 31, warp = tid >> 5;
    const int g = lane >> 2, tig = lane & 3;
    const int m0 = (warp >> 1) * 32, n0 = (warp & 1) * 64;

    float c[2][8][4];
#pragma unroll
    for (int mt = 0; mt < 2; mt++)
#pragma unroll
        for (int nt = 0; nt < 8; nt++)
#pragma unroll
            for (int e = 0; e < 4; e++) c[mt][nt][e] = 0.f;

    const int lm = tid & 127, lkk = (tid >> 7) * 8;
    const float* Aq = g_q + (size_t)bh * (Tn * HDn) + (size_t)(bm * 128 + lm) * HDn + lkk;
    const float* Bk = g_k + (size_t)bh * (Tn * HDn) + (size_t)(bn * 128 + lm) * HDn + lkk;

    for (int k0 = 0; k0 < HDn; k0 += 16) {
        float4 a0 = *(const float4*)(Aq + k0);
        float4 a1 = *(const float4*)(Aq + k0 + 4);
        float4 b0 = *(const float4*)(Bk + k0);
        float4 b1 = *(const float4*)(Bk + k0 + 4);
        __syncthreads();
        *(uint4*)(As + lm * APAD + lkk)     = tf4(a0);
        *(uint4*)(As + lm * APAD + lkk + 4) = tf4(a1);
        float bv[8] = {b0.x, b0.y, b0.z, b0.w, b1.x, b1.y, b1.z, b1.w};
#pragma unroll
        for (int j = 0; j < 8; j++) Bs[(lkk + j) * BPAD + lm] = f2tf(bv[j]);
        __syncthreads();
        mma_step<8, BPAD>(As, Bs, c, m0, n0, g, tig);
    }

    float* P = g_p + (size_t)bh * (Tn * Tn);
#pragma unroll
    for (int mt = 0; mt < 2; mt++)
#pragma unroll
        for (int nt = 0; nt < 8; nt++) {
            int r = bm * 128 + m0 + mt * 16 + g;
            int cl = bn * 128 + n0 + nt * 8 + 2 * tig;
#pragma unroll
            for (int e = 0; e < 4; e++) {
                int rr = r + ((e >= 2) ? 8 : 0);
                int cc = cl + (e & 1);
                P[(size_t)rr * Tn + cc] = c[mt][nt][e];
            }
        }
}

// ---------------------------------------------------------------------------
// 4) Row softmax (unchanged)
__global__ __launch_bounds__(256) void k_softmax() {
    const int row = blockIdx.x;
    const int t = row & (Tn - 1);
    float* pr = g_p + (size_t)row * Tn;
    const int tid = threadIdx.x;
    const int len = t + 1;

    __shared__ float red[8];
    __shared__ float bval;

    float v[4];
    float mx = -1e30f;
#pragma unroll
    for (int i = 0; i < 4; i++) {
        int s = tid + i * 256;
        v[i] = (s < len) ? pr[s] : -1e30f;
        mx = fmaxf(mx, v[i]);
    }
#pragma unroll
    for (int o = 16; o; o >>= 1) mx = fmaxf(mx, __shfl_xor_sync(0xffffffffu, mx, o));
    if ((tid & 31) == 0) red[tid >> 5] = mx;
    __syncthreads();
    if (tid == 0) {
        float m2 = red[0];
#pragma unroll
        for (int i = 1; i < 8; i++) m2 = fmaxf(m2, red[i]);
        bval = m2;
    }
    __syncthreads();
    mx = bval;

    float sum = 0.f;
#pragma unroll
    for (int i = 0; i < 4; i++) {
        int s = tid + i * 256;
        float e = (s < len) ? __expf(v[i] - mx) : 0.f;
        v[i] = e;
        sum += e;
    }
#pragma unroll
    for (int o = 16; o; o >>= 1) sum += __shfl_xor_sync(0xffffffffu, sum, o);
    if ((tid & 31) == 0) red[tid >> 5] = sum;
    __syncthreads();
    if (tid == 0) {
        float s2 = 0.f;
#pragma unroll
        for (int i = 0; i < 8; i++) s2 += red[i];
        bval = s2;
    }
    __syncthreads();
    const float inv = 1.0f / bval;
#pragma unroll
    for (int i = 0; i < 4; i++) {
        int s = tid + i * 256;
        pr[s] = v[i] * inv;
    }
}

// ---------------------------------------------------------------------------
// 5) PV (legacy tf32; epilogue emits fp16 into g_ah)
__global__ __launch_bounds__(256) void k_pv() {
    const int bm = blockIdx.x, bh = blockIdx.z;
    __shared__ unsigned As[128 * APAD];
    __shared__ unsigned Bs[16 * BPAD2];
    const int tid = threadIdx.x, lane = tid & 31, warp = tid >> 5;
    const int g = lane >> 2, tig = lane & 3;
    const int m0 = (warp >> 1) * 32, n0 = (warp & 1) * 32;

    float c[2][4][4];
#pragma unroll
    for (int mt = 0; mt < 2; mt++)
#pragma unroll
        for (int nt = 0; nt < 4; nt++)
#pragma unroll
            for (int e = 0; e < 4; e++) c[mt][nt][e] = 0.f;

    const int lm = tid & 127, lkk = (tid >> 7) * 8;
    const int bkk = tid >> 4, bn4 = (tid & 15) * 4;
    const float* Ap = g_p + (size_t)bh * (Tn * Tn) + (size_t)(bm * 128 + lm) * Tn + lkk;
    const float* Bv = g_v + (size_t)bh * (Tn * HDn) + bn4;
    const int kmax = (bm + 1) * 128;

    for (int k0 = 0; k0 < kmax; k0 += 16) {
        float4 a0 = *(const float4*)(Ap + k0);
        float4 a1 = *(const float4*)(Ap + k0 + 4);
        float4 b0 = *(const float4*)(Bv + (size_t)(k0 + bkk) * HDn);
        __syncthreads();
        *(uint4*)(As + lm * APAD + lkk)     = tf4(a0);
        *(uint4*)(As + lm * APAD + lkk + 4) = tf4(a1);
        *(uint4*)(Bs + bkk * BPAD2 + bn4)   = tf4(b0);
        __syncthreads();
        mma_step<4, BPAD2>(As, Bs, c, m0, n0, g, tig);
    }

    const int b2 = bh >> 4, hh = bh & 15;
#pragma unroll
    for (int mt = 0; mt < 2; mt++)
#pragma unroll
        for (int nt = 0; nt < 4; nt++) {
            int r = bm * 128 + m0 + mt * 16 + g;
            int cl = n0 + nt * 8 + 2 * tig;
#pragma unroll
            for (int e = 0; e < 4; e++) {
                int rr = r + ((e >= 2) ? 8 : 0);
                int cc = cl + (e & 1);
                g_ah[((size_t)(b2 * Tn + rr)) * Cn + hh * HDn + cc] =
                    __float2half_rn(c[mt][nt][e]);
            }
        }
}

// ---------------------------------------------------------------------------
// 6) LM head: fp16 mma.m16n8k16, 3-stage cp.async pipeline, ldmatrix frags.
//    Tile 128(M) x 256(N) x 32(K), 256 threads, warp tile 64x64.
//    grid (16, 197): M fastest so a wave shares W_lm slabs in L2.
//    NOTE: out rows have ODD pitch (Vn=50257) -> scalar stores only.
#define A_HALVES (128 * 40)      // padded rows: 32 data + 8 pad halves
#define B_HALVES (256 * 40)
#define STG_BYTES ((A_HALVES + B_HALVES) * 2)   // 30720
#define LOG_SMEM  (3 * STG_BYTES)               // 92160

__global__ __launch_bounds__(256, 1) void k_logits_h(const float* __restrict__ blm,
                                                     float* __restrict__ out) {
    extern __shared__ __align__(16) __half sm[];
    __shared__ float s_bias[256];
    const int tid = threadIdx.x, lane = tid & 31, wid = tid >> 5;
    const int bm = blockIdx.x, bn = blockIdx.y;
    const uint32_t sbase = smem_u32(sm);

    {
        int gc = bn * 256 + tid;
        s_bias[tid] = (gc < Vn) ? blm[gc] : 0.f;
    }

    const __half* gA = g_ah + (size_t)(bm * 128) * Cn;

    auto load_stage = [&](int stage, int kc) {
        const uint32_t sA = sbase + stage * STG_BYTES;
        const uint32_t sB = sA + A_HALVES * 2;
        const int kb = kc * 32;
#pragma unroll
        for (int i = 0; i < 2; i++) {
            int ch = tid + i * 256;
            int r = ch >> 2, c8 = ch & 3;
            cpa16(sA + (r * 40 + c8 * 8) * 2, gA + (size_t)r * Cn + kb + c8 * 8);
        }
#pragma unroll
        for (int i = 0; i < 4; i++) {
            int ch = tid + i * 256;
            int r = ch >> 2, c8 = ch & 3;
            int gn = bn * 256 + r;
            int ok = (gn < Vn);
            const __half* src = g_wh + (size_t)(ok ? gn : 0) * Cn + kb + c8 * 8;
            cpa16z(sB + (r * 40 + c8 * 8) * 2, src, ok ? 16 : 0);
        }
    };

    load_stage(0, 0); CPA_COMMIT();
    load_stage(1, 1); CPA_COMMIT();

    float c[4][8][4];
#pragma unroll
    for (int mt = 0; mt < 4; mt++)
#pragma unroll
        for (int nt = 0; nt < 8; nt++)
#pragma unroll
            for (int e = 0; e < 4; e++) c[mt][nt][e] = 0.f;

    const int sub = lane >> 3, l7 = lane & 7;
    const uint32_t aOff = (((wid >> 2) * 64 + (sub & 1) * 8 + l7) * 40 + (sub >> 1) * 8) * 2;
    const uint32_t bOff = (((wid & 3) * 64 + (sub >> 1) * 8 + l7) * 40 + (sub & 1) * 8) * 2;

    int s_cur = 0, s_nxt = 2;
    for (int it = 0; it < 32; it++) {
        CPA_WAIT1();
        __syncthreads();
        if (it + 2 < 32) load_stage(s_nxt, it + 2);
        CPA_COMMIT();

        const uint32_t aB = sbase + s_cur * STG_BYTES + aOff;
        const uint32_t bB = sbase + s_cur * STG_BYTES + A_HALVES * 2 + bOff;
#pragma unroll
        for (int kt = 0; kt < 2; kt++) {
            unsigned a[4][4];
#pragma unroll
            for (int mt = 0; mt < 4; mt++)
                ldsm4(a[mt][0], a[mt][1], a[mt][2], a[mt][3],
                      aB + (mt * 16 * 40 + kt * 16) * 2);
            unsigned b[8][2];
#pragma unroll
            for (int np = 0; np < 4; np++)
                ldsm4(b[2 * np][0], b[2 * np][1], b[2 * np + 1][0], b[2 * np + 1][1],
                      bB + (np * 16 * 40 + kt * 16) * 2);
#pragma unroll
            for (int mt = 0; mt < 4; mt++)
#pragma unroll
                for (int nt = 0; nt < 8; nt++) mma16(c[mt][nt], a[mt], b[nt]);
        }
        s_cur = (s_cur == 2) ? 0 : s_cur + 1;
        s_nxt = (s_nxt == 2) ? 0 : s_nxt + 1;
    }

    // epilogue — scalar stores (row pitch Vn=50257 is odd; float2 would fault)
    const int wm0 = (wid >> 2) * 64, wn0 = (wid & 3) * 64;
    const int g = lane >> 2, tig = lane & 3;
#pragma unroll
    for (int mt = 0; mt < 4; mt++) {
#pragma unroll
        for (int e2 = 0; e2 < 2; e2++) {
            int row = bm * 128 + wm0 + mt * 16 + g + e2 * 8;
            float* orow = out + (size_t)row * Vn;
#pragma unroll
            for (int nt = 0; nt < 8; nt++) {
                int cl = wn0 + nt * 8 + 2 * tig;
                int col = bn * 256 + cl;
                float v0 = c[mt][nt][e2 * 2 + 0] + s_bias[cl];
                float v1 = c[mt][nt][e2 * 2 + 1] + s_bias[cl + 1];
                if (col < Vn)     orow[col] = v0;
                if (col + 1 < Vn) orow[col + 1] = v1;
            }
        }
    }
}

// ---------------------------------------------------------------------------
extern "C" void kernel_launch(void* const* d_in, const int* in_sizes, int n_in,
                              void* d_out, int out_size) {
    (void)in_sizes; (void)n_in; (void)out_size;
    const int*   idx = (const int*)d_in[0];
    const float* tok = (const float*)d_in[1];
    const float* pos = (const float*)d_in[2];
    const float* Wq  = (const float*)d_in[3];
    const float* Wk  = (const float*)d_in[4];
    const float* Wv  = (const float*)d_in[5];
    const float* Wlm = (const float*)d_in[6];
    const float* blm = (const float*)d_in[7];
    float* out = (float*)d_out;

    cudaFuncSetAttribute(k_logits_h, cudaFuncAttributeMaxDynamicSharedMemorySize,
                         LOG_SMEM);

    k_w2h<<<25129, 256>>>(Wlm);
    k_embed<<<BTn, 256>>>(idx, tok, pos);
    k_qkv<<<dim3(16, 8, 3), 256>>>(Wq, Wk, Wv);
    k_scores<<<dim3(8, 8, NBH), 256>>>();
    k_softmax<<<NBH * Tn, 256>>>();
    k_pv<<<dim3(8, 1, NBH), 256>>>();
    k_logits_h<<<dim3(16, 197), 256, LOG_SMEM>>>(blm, out);
}

// round 6
// speedup vs baseline: 2.7888x; 1.2079x over previous
#include <cuda_runtime.h>
#include <cuda_fp16.h>
#include <cstdint>

// Problem constants
#define Bsz  2
#define Tn   1024
#define Cn   1024
#define Hn   16
#define HDn  64
#define Vn   50257
#define BTn  2048
#define NBH  32          // B*H
#define NBN  197         // ceil(Vn/256)

// Scratch (static device globals; no allocation)
__device__ float g_x[BTn * Cn];
__device__ float g_q[BTn * Cn];
__device__ float g_k[BTn * Cn];
__device__ float g_v[BTn * Cn];
__device__ float g_p[NBH * Tn * Tn];
// Tile-chunked, pre-swizzled fp16 operands for the LM-head GEMM:
// g_ah: [bm:16][kc:16][row:128][64 halves]   (attention out)
// g_wh: [bn:197][kc:16][row:256][64 halves]  (W_lm)
__device__ __align__(128) __half g_ah[BTn * Cn];
__device__ __align__(128) __half g_wh[(size_t)NBN * 16 * 256 * 64];

#define APAD 20
#define BPAD 136
#define BPAD2 72

__device__ __forceinline__ unsigned f2tf(float f) {
    unsigned r;
    asm("cvt.rna.tf32.f32 %0, %1;" : "=r"(r) : "f"(f));
    return r;
}
__device__ __forceinline__ uint4 tf4(float4 v) {
    uint4 r; r.x = f2tf(v.x); r.y = f2tf(v.y); r.z = f2tf(v.z); r.w = f2tf(v.w);
    return r;
}

__device__ __forceinline__ void mma8(float* c, const unsigned* a, const unsigned* b) {
    asm volatile(
        "mma.sync.aligned.m16n8k8.row.col.f32.tf32.tf32.f32 "
        "{%0,%1,%2,%3},{%4,%5,%6,%7},{%8,%9},{%0,%1,%2,%3};"
        : "+f"(c[0]), "+f"(c[1]), "+f"(c[2]), "+f"(c[3])
        : "r"(a[0]), "r"(a[1]), "r"(a[2]), "r"(a[3]), "r"(b[0]), "r"(b[1]));
}

template <int NT, int BP>
__device__ __forceinline__ void mma_step(const unsigned* __restrict__ As,
                                         const unsigned* __restrict__ Bs,
                                         float (&c)[2][NT][4],
                                         int m0, int n0, int g, int tig) {
#pragma unroll
    for (int ks = 0; ks < 2; ks++) {
        const int k8 = ks * 8;
        unsigned a[2][4];
#pragma unroll
        for (int mt = 0; mt < 2; mt++) {
            const unsigned* ap = As + (m0 + mt * 16 + g) * APAD + k8 + tig;
            a[mt][0] = ap[0];
            a[mt][1] = ap[8 * APAD];
            a[mt][2] = ap[4];
            a[mt][3] = ap[8 * APAD + 4];
        }
        unsigned b[NT][2];
#pragma unroll
        for (int nt = 0; nt < NT; nt++) {
            const unsigned* bp = Bs + (k8 + tig) * BP + n0 + nt * 8 + g;
            b[nt][0] = bp[0];
            b[nt][1] = bp[4 * BP];
        }
#pragma unroll
        for (int mt = 0; mt < 2; mt++)
#pragma unroll
            for (int nt = 0; nt < NT; nt++) mma8(c[mt][nt], a[mt], b[nt]);
    }
}

// ===========================================================================
// helpers (sm_80/sm_90 baseline ISA)
// ===========================================================================
__device__ __forceinline__ uint32_t smem_u32(const void* p) {
    return (uint32_t)__cvta_generic_to_shared(p);
}
__device__ __forceinline__ void mma16(float* c, const unsigned* a, const unsigned* b) {
    asm volatile(
        "mma.sync.aligned.m16n8k16.row.col.f32.f16.f16.f32 "
        "{%0,%1,%2,%3},{%4,%5,%6,%7},{%8,%9},{%0,%1,%2,%3};"
        : "+f"(c[0]), "+f"(c[1]), "+f"(c[2]), "+f"(c[3])
        : "r"(a[0]), "r"(a[1]), "r"(a[2]), "r"(a[3]), "r"(b[0]), "r"(b[1]));
}
__device__ __forceinline__ void ldsm4(unsigned& r0, unsigned& r1, unsigned& r2,
                                      unsigned& r3, uint32_t addr) {
    asm volatile("ldmatrix.sync.aligned.m8n8.x4.shared.b16 {%0,%1,%2,%3}, [%4];"
                 : "=r"(r0), "=r"(r1), "=r"(r2), "=r"(r3) : "r"(addr));
}
__device__ __forceinline__ void bulk_g2s(uint32_t dst, const void* src, int bytes,
                                         uint32_t mbar) {
    asm volatile(
        "cp.async.bulk.shared::cluster.global.mbarrier::complete_tx::bytes "
        "[%0], [%1], %2, [%3];"
        :: "r"(dst), "l"(src), "r"(bytes), "r"(mbar) : "memory");
}
#define MBAR_INIT(mbar, cnt) \
    asm volatile("mbarrier.init.shared.b64 [%0], %1;" \
                 :: "r"((uint32_t)(mbar)), "r"((uint32_t)(cnt)) : "memory")
#define MBAR_EXPECT(mbar, tx) \
    asm volatile("mbarrier.arrive.expect_tx.shared.b64 _, [%0], %1;" \
                 :: "r"((uint32_t)(mbar)), "r"((uint32_t)(tx)) : "memory")
#define MBAR_WAIT(mbar, parity) do {                                          \
    uint32_t _m = (uint32_t)(mbar);                                           \
    uint32_t _p = (uint32_t)(parity);                                         \
    asm volatile(                                                             \
        "{\n\t.reg .pred P1;\n\t"                                             \
        "WAIT_LOOP_%=:\n\t"                                                   \
        "mbarrier.try_wait.parity.acquire.cta.shared::cta.b64 P1, [%0], %1, 0x989680;\n\t" \
        "@P1 bra.uni WAIT_DONE_%=;\n\t"                                       \
        "bra.uni WAIT_LOOP_%=;\n\t"                                           \
        "WAIT_DONE_%=:\n\t}"                                                  \
        :: "r"(_m), "r"(_p) : "memory");                                      \
} while (0)

// ---------------------------------------------------------------------------
// 1) Embedding
__global__ __launch_bounds__(256) void k_embed(const int* __restrict__ idx,
                                               const float* __restrict__ tok,
                                               const float* __restrict__ pos) {
    int i = blockIdx.x;
    int t = i & (Tn - 1);
    int token = idx[i];
    const float4* te = (const float4*)(tok + (size_t)token * Cn);
    const float4* pe = (const float4*)(pos + (size_t)t * Cn);
    float4 a = te[threadIdx.x], b = pe[threadIdx.x];
    float4 o;
    o.x = a.x + b.x; o.y = a.y + b.y; o.z = a.z + b.z; o.w = a.w + b.w;
    ((float4*)(g_x + (size_t)i * Cn))[threadIdx.x] = o;
}

// ---------------------------------------------------------------------------
// 1b) W_lm -> fp16, tile-chunked + SW128-swizzled layout.
//     element (v, k): bn=v>>8, r=v&255, kc=k>>6, kk=k&63
//     byte off in chunk = r*128 + ((kk>>3 ^ (r&7))<<4) + (kk&7)*2
__global__ __launch_bounds__(256) void k_w2h(const float* __restrict__ W) {
    int gid = blockIdx.x * 256 + threadIdx.x;     // one 8-half granule each
    if (gid >= Vn * 128) return;
    int v = gid >> 7, g8 = gid & 127;             // kk = g8*8
    const float4* s = (const float4*)(W + (size_t)v * Cn + g8 * 8);
    float4 x = s[0], y = s[1];
    __half2 h0 = __floats2half2_rn(x.x, x.y);
    __half2 h1 = __floats2half2_rn(x.z, x.w);
    __half2 h2 = __floats2half2_rn(y.x, y.y);
    __half2 h3 = __floats2half2_rn(y.z, y.w);
    uint4 o;
    o.x = *(unsigned*)&h0; o.y = *(unsigned*)&h1;
    o.z = *(unsigned*)&h2; o.w = *(unsigned*)&h3;
    int bn = v >> 8, r = v & 255;
    int kc = g8 >> 3, c16 = g8 & 7;
    size_t chunkB = (((size_t)bn * 16 + kc) * (256 * 64)) * 2;
    uint32_t off = (uint32_t)r * 128 + ((unsigned)(c16 ^ (r & 7)) << 4);
    *(uint4*)((char*)g_wh + chunkB + off) = o;
}

// ---------------------------------------------------------------------------
// 2) QKV projection (legacy tf32, unchanged)
__global__ __launch_bounds__(256) void k_qkv(const float* __restrict__ Wq,
                                             const float* __restrict__ Wk,
                                             const float* __restrict__ Wv) {
    __shared__ unsigned As[128 * APAD];
    __shared__ unsigned Bs[16 * BPAD];
    const float* W = (blockIdx.z == 0) ? Wq : (blockIdx.z == 1) ? Wk : Wv;
    float* o = (blockIdx.z == 0) ? g_q : (blockIdx.z == 1) ? g_k : g_v;
    const int bm = blockIdx.x, bn = blockIdx.y;
    const int tid = threadIdx.x, lane = tid & 31, warp = tid >> 5;
    const int g = lane >> 2, tig = lane & 3;
    const int m0 = (warp >> 1) * 32, n0 = (warp & 1) * 64;

    float c[2][8][4];
#pragma unroll
    for (int mt = 0; mt < 2; mt++)
#pragma unroll
        for (int nt = 0; nt < 8; nt++)
#pragma unroll
            for (int e = 0; e < 4; e++) c[mt][nt][e] = 0.f;

    const int lm = tid & 127, lkk = (tid >> 7) * 8;
    const int bkk = tid >> 4, bn8 = (tid & 15) * 8;
    const int gn0 = bn * 128 + bn8;
    const int h = gn0 >> 6, d = gn0 & 63;
    const float* Wb = W + (size_t)h * (Cn * HDn) + d;
    const float* Ab = g_x + (size_t)(bm * 128 + lm) * Cn + lkk;

    for (int k0 = 0; k0 < Cn; k0 += 16) {
        float4 a0 = *(const float4*)(Ab + k0);
        float4 a1 = *(const float4*)(Ab + k0 + 4);
        float4 b0 = *(const float4*)(Wb + (size_t)(k0 + bkk) * HDn);
        float4 b1 = *(const float4*)(Wb + (size_t)(k0 + bkk) * HDn + 4);
        __syncthreads();
        *(uint4*)(As + lm * APAD + lkk)     = tf4(a0);
        *(uint4*)(As + lm * APAD + lkk + 4) = tf4(a1);
        *(uint4*)(Bs + bkk * BPAD + bn8)     = tf4(b0);
        *(uint4*)(Bs + bkk * BPAD + bn8 + 4) = tf4(b1);
        __syncthreads();
        mma_step<8, BPAD>(As, Bs, c, m0, n0, g, tig);
    }

    const float scale = (blockIdx.z == 0) ? 0.03125f : 1.0f;
#pragma unroll
    for (int mt = 0; mt < 2; mt++)
#pragma unroll
        for (int nt = 0; nt < 8; nt++) {
            int r = bm * 128 + m0 + mt * 16 + g;
            int cl = bn * 128 + n0 + nt * 8 + 2 * tig;
#pragma unroll
            for (int e = 0; e < 4; e++) {
                int rr = r + ((e >= 2) ? 8 : 0);
                int cc = cl + (e & 1);
                int b2 = rr >> 10, t2 = rr & 1023;
                int hh = cc >> 6, dd = cc & 63;
                o[(((size_t)(b2 * Hn + hh)) * Tn + t2) * HDn + dd] = c[mt][nt][e] * scale;
            }
        }
}

// ---------------------------------------------------------------------------
// 3) Scores (legacy tf32, unchanged)
__global__ __launch_bounds__(256) void k_scores() {
    const int bm = blockIdx.x, bn = blockIdx.y, bh = blockIdx.z;
    if (bn > bm) return;
    __shared__ unsigned As[128 * APAD];
    __shared__ unsigned Bs[16 * BPAD];
    const int tid = threadIdx.x, lane = tid & 31, warp = tid >> 5;
    const int g = lane >> 2, tig = lane & 3;
    const int m0 = (warp >> 1) * 32, n0 = (warp & 1) * 64;

    float c[2][8][4];
#pragma unroll
    for (int mt = 0; mt < 2; mt++)
#pragma unroll
        for (int nt = 0; nt < 8; nt++)
#pragma unroll
            for (int e = 0; e < 4; e++) c[mt][nt][e] = 0.f;

    const int lm = tid & 127, lkk = (tid >> 7) * 8;
    const float* Aq = g_q + (size_t)bh * (Tn * HDn) + (size_t)(bm * 128 + lm) * HDn + lkk;
    const float* Bk = g_k + (size_t)bh * (Tn * HDn) + (size_t)(bn * 128 + lm) * HDn + lkk;

    for (int k0 = 0; k0 < HDn; k0 += 16) {
        float4 a0 = *(const float4*)(Aq + k0);
        float4 a1 = *(const float4*)(Aq + k0 + 4);
        float4 b0 = *(const float4*)(Bk + k0);
        float4 b1 = *(const float4*)(Bk + k0 + 4);
        __syncthreads();
        *(uint4*)(As + lm * APAD + lkk)     = tf4(a0);
        *(uint4*)(As + lm * APAD + lkk + 4) = tf4(a1);
        float bv[8] = {b0.x, b0.y, b0.z, b0.w, b1.x, b1.y, b1.z, b1.w};
#pragma unroll
        for (int j = 0; j < 8; j++) Bs[(lkk + j) * BPAD + lm] = f2tf(bv[j]);
        __syncthreads();
        mma_step<8, BPAD>(As, Bs, c, m0, n0, g, tig);
    }

    float* P = g_p + (size_t)bh * (Tn * Tn);
#pragma unroll
    for (int mt = 0; mt < 2; mt++)
#pragma unroll
        for (int nt = 0; nt < 8; nt++) {
            int r = bm * 128 + m0 + mt * 16 + g;
            int cl = bn * 128 + n0 + nt * 8 + 2 * tig;
#pragma unroll
            for (int e = 0; e < 4; e++) {
                int rr = r + ((e >= 2) ? 8 : 0);
                int cc = cl + (e & 1);
                P[(size_t)rr * Tn + cc] = c[mt][nt][e];
            }
        }
}

// ---------------------------------------------------------------------------
// 4) Row softmax (unchanged)
__global__ __launch_bounds__(256) void k_softmax() {
    const int row = blockIdx.x;
    const int t = row & (Tn - 1);
    float* pr = g_p + (size_t)row * Tn;
    const int tid = threadIdx.x;
    const int len = t + 1;

    __shared__ float red[8];
    __shared__ float bval;

    float v[4];
    float mx = -1e30f;
#pragma unroll
    for (int i = 0; i < 4; i++) {
        int s = tid + i * 256;
        v[i] = (s < len) ? pr[s] : -1e30f;
        mx = fmaxf(mx, v[i]);
    }
#pragma unroll
    for (int o = 16; o; o >>= 1) mx = fmaxf(mx, __shfl_xor_sync(0xffffffffu, mx, o));
    if ((tid & 31) == 0) red[tid >> 5] = mx;
    __syncthreads();
    if (tid == 0) {
        float m2 = red[0];
#pragma unroll
        for (int i = 1; i < 8; i++) m2 = fmaxf(m2, red[i]);
        bval = m2;
    }
    __syncthreads();
    mx = bval;

    float sum = 0.f;
#pragma unroll
    for (int i = 0; i < 4; i++) {
        int s = tid + i * 256;
        float e = (s < len) ? __expf(v[i] - mx) : 0.f;
        v[i] = e;
        sum += e;
    }
#pragma unroll
    for (int o = 16; o; o >>= 1) sum += __shfl_xor_sync(0xffffffffu, sum, o);
    if ((tid & 31) == 0) red[tid >> 5] = sum;
    __syncthreads();
    if (tid == 0) {
        float s2 = 0.f;
#pragma unroll
        for (int i = 0; i < 8; i++) s2 += red[i];
        bval = s2;
    }
    __syncthreads();
    const float inv = 1.0f / bval;
#pragma unroll
    for (int i = 0; i < 4; i++) {
        int s = tid + i * 256;
        pr[s] = v[i] * inv;
    }
}

// ---------------------------------------------------------------------------
// 5) PV (legacy tf32; epilogue emits fp16 into chunked+swizzled g_ah)
__global__ __launch_bounds__(256) void k_pv() {
    const int bm = blockIdx.x, bh = blockIdx.z;
    __shared__ unsigned As[128 * APAD];
    __shared__ unsigned Bs[16 * BPAD2];
    const int tid = threadIdx.x, lane = tid & 31, warp = tid >> 5;
    const int g = lane >> 2, tig = lane & 3;
    const int m0 = (warp >> 1) * 32, n0 = (warp & 1) * 32;

    float c[2][4][4];
#pragma unroll
    for (int mt = 0; mt < 2; mt++)
#pragma unroll
        for (int nt = 0; nt < 4; nt++)
#pragma unroll
            for (int e = 0; e < 4; e++) c[mt][nt][e] = 0.f;

    const int lm = tid & 127, lkk = (tid >> 7) * 8;
    const int bkk = tid >> 4, bn4 = (tid & 15) * 4;
    const float* Ap = g_p + (size_t)bh * (Tn * Tn) + (size_t)(bm * 128 + lm) * Tn + lkk;
    const float* Bv = g_v + (size_t)bh * (Tn * HDn) + bn4;
    const int kmax = (bm + 1) * 128;

    for (int k0 = 0; k0 < kmax; k0 += 16) {
        float4 a0 = *(const float4*)(Ap + k0);
        float4 a1 = *(const float4*)(Ap + k0 + 4);
        float4 b0 = *(const float4*)(Bv + (size_t)(k0 + bkk) * HDn);
        __syncthreads();
        *(uint4*)(As + lm * APAD + lkk)     = tf4(a0);
        *(uint4*)(As + lm * APAD + lkk + 4) = tf4(a1);
        *(uint4*)(Bs + bkk * BPAD2 + bn4)   = tf4(b0);
        __syncthreads();
        mma_step<4, BPAD2>(As, Bs, c, m0, n0, g, tig);
    }

    const int b2 = bh >> 4, hh = bh & 15;   // kc = hh (since k = hh*64+cc, cc<64)
#pragma unroll
    for (int mt = 0; mt < 2; mt++)
#pragma unroll
        for (int nt = 0; nt < 4; nt++) {
            int r0 = bm * 128 + m0 + mt * 16 + g;
            int cl = n0 + nt * 8 + 2 * tig;
#pragma unroll
            for (int e = 0; e < 4; e++) {
                int rr = r0 + ((e >= 2) ? 8 : 0);
                int cc = cl + (e & 1);
                int row = b2 * Tn + rr;           // 0..2047
                int bma = row >> 7, r = row & 127;
                size_t chunkB = (((size_t)bma * 16 + hh) * (128 * 64)) * 2;
                uint32_t off = (uint32_t)r * 128 +
                               ((unsigned)(((cc >> 3) ^ (r & 7))) << 4) + (cc & 7) * 2;
                *(__half*)((char*)g_ah + chunkB + off) = __float2half_rn(c[mt][nt][e]);
            }
        }
}

// ---------------------------------------------------------------------------
// 6) LM head: fp16 mma.m16n8k16; cp.async.bulk staging (2 bulk ops/stage),
//    3-stage mbarrier ring. Tile 128(M) x 256(N) x 64(K), 256 threads,
//    warp tile 64x64. grid (16, 197): M fastest for L2 B-slab sharing.
//    out rows have ODD pitch (Vn=50257) -> scalar stores.
#define LKCH 16                          // K chunks of 64
#define A_CH_BYTES (128 * 128)           // 16KB
#define B_CH_BYTES (256 * 128)           // 32KB
#define LSTG_BYTES (A_CH_BYTES + B_CH_BYTES)   // 49152
#define LOG_SMEM (3 * LSTG_BYTES)        // 147456

__global__ __launch_bounds__(256, 1) void k_logits_b(const float* __restrict__ blm,
                                                     float* __restrict__ out) {
    extern __shared__ __align__(128) char sm[];
    __shared__ float s_bias[256];
    __shared__ __align__(8) unsigned long long s_mb[3];
    const int tid = threadIdx.x, lane = tid & 31, wid = tid >> 5;
    const int bm = blockIdx.x, bn = blockIdx.y;
    const uint32_t sbase = smem_u32(sm);
    const uint32_t mb0 = smem_u32(&s_mb[0]);

    {
        int gc = bn * 256 + tid;
        s_bias[tid] = (gc < Vn) ? blm[gc] : 0.f;
    }
    if (tid == 0) {
        MBAR_INIT(mb0, 1);
        MBAR_INIT(mb0 + 8, 1);
        MBAR_INIT(mb0 + 16, 1);
    }
    __syncthreads();

    const char* gA = (const char*)g_ah + ((size_t)bm * LKCH) * A_CH_BYTES;
    const char* gB = (const char*)g_wh + ((size_t)bn * LKCH) * B_CH_BYTES;

    if (tid == 0) {
#pragma unroll
        for (int s = 0; s < 3; s++) {
            uint32_t m = mb0 + s * 8;
            uint32_t dst = sbase + s * LSTG_BYTES;
            MBAR_EXPECT(m, LSTG_BYTES);
            bulk_g2s(dst, gA + (size_t)s * A_CH_BYTES, A_CH_BYTES, m);
            bulk_g2s(dst + A_CH_BYTES, gB + (size_t)s * B_CH_BYTES, B_CH_BYTES, m);
        }
    }

    float c[4][8][4];
#pragma unroll
    for (int mt = 0; mt < 4; mt++)
#pragma unroll
        for (int nt = 0; nt < 8; nt++)
#pragma unroll
            for (int e = 0; e < 4; e++) c[mt][nt][e] = 0.f;

    const int wm0 = (wid >> 2) * 64, wn0 = (wid & 3) * 64;
    const int l7 = lane & 7;
    const int rowA = wm0 + (lane & 15);
    const int rowB = wn0 + ((lane >> 4) << 3) + l7;
    const uint32_t aAddr0 = (uint32_t)rowA * 128;
    const uint32_t bAddr0 = A_CH_BYTES + (uint32_t)rowB * 128;
    const int gA16 = lane >> 4;          // A k-granule lane split
    const int gB16 = (lane >> 3) & 1;    // B k-granule lane split

    for (int kc = 0; kc < LKCH; kc++) {
        MBAR_WAIT(mb0 + (kc % 3) * 8, (kc / 3) & 1);
        const uint32_t sb = sbase + (kc % 3) * LSTG_BYTES;
#pragma unroll
        for (int kt = 0; kt < 4; kt++) {
            const uint32_t xA = ((uint32_t)((kt * 2 + gA16) ^ l7)) << 4;
            const uint32_t xB = ((uint32_t)((kt * 2 + gB16) ^ l7)) << 4;
            unsigned a[4][4];
#pragma unroll
            for (int mt = 0; mt < 4; mt++)
                ldsm4(a[mt][0], a[mt][1], a[mt][2], a[mt][3],
                      sb + aAddr0 + mt * (16 * 128) + xA);
            unsigned b[8][2];
#pragma unroll
            for (int np = 0; np < 4; np++)
                ldsm4(b[2 * np][0], b[2 * np][1], b[2 * np + 1][0], b[2 * np + 1][1],
                      sb + bAddr0 + np * (16 * 128) + xB);
#pragma unroll
            for (int mt = 0; mt < 4; mt++)
#pragma unroll
                for (int nt = 0; nt < 8; nt++) mma16(c[mt][nt], a[mt], b[nt]);
        }
        __syncthreads();
        if (tid == 0 && kc + 3 < LKCH) {
            int s = kc % 3;
            uint32_t m = mb0 + s * 8;
            uint32_t dst = sbase + s * LSTG_BYTES;
            MBAR_EXPECT(m, LSTG_BYTES);
            bulk_g2s(dst, gA + (size_t)(kc + 3) * A_CH_BYTES, A_CH_BYTES, m);
            bulk_g2s(dst + A_CH_BYTES, gB + (size_t)(kc + 3) * B_CH_BYTES, B_CH_BYTES, m);
        }
    }

    // epilogue — scalar stores (row pitch Vn=50257 is odd)
    const int g = lane >> 2, tig = lane & 3;
#pragma unroll
    for (int mt = 0; mt < 4; mt++) {
#pragma unroll
        for (int e2 = 0; e2 < 2; e2++) {
            int row = bm * 128 + wm0 + mt * 16 + g + e2 * 8;
            float* orow = out + (size_t)row * Vn;
#pragma unroll
            for (int nt = 0; nt < 8; nt++) {
                int cl = wn0 + nt * 8 + 2 * tig;
                int col = bn * 256 + cl;
                float v0 = c[mt][nt][e2 * 2 + 0] + s_bias[cl];
                float v1 = c[mt][nt][e2 * 2 + 1] + s_bias[cl + 1];
                if (col < Vn)     orow[col] = v0;
                if (col + 1 < Vn) orow[col + 1] = v1;
            }
        }
    }
}

// ---------------------------------------------------------------------------
extern "C" void kernel_launch(void* const* d_in, const int* in_sizes, int n_in,
                              void* d_out, int out_size) {
    (void)in_sizes; (void)n_in; (void)out_size;
    const int*   idx = (const int*)d_in[0];
    const float* tok = (const float*)d_in[1];
    const float* pos = (const float*)d_in[2];
    const float* Wq  = (const float*)d_in[3];
    const float* Wk  = (const float*)d_in[4];
    const float* Wv  = (const float*)d_in[5];
    const float* Wlm = (const float*)d_in[6];
    const float* blm = (const float*)d_in[7];
    float* out = (float*)d_out;

    cudaFuncSetAttribute(k_logits_b, cudaFuncAttributeMaxDynamicSharedMemorySize,
                         LOG_SMEM);

    k_w2h<<<(Vn * 128 + 255) / 256, 256>>>(Wlm);
    k_embed<<<BTn, 256>>>(idx, tok, pos);
    k_qkv<<<dim3(16, 8, 3), 256>>>(Wq, Wk, Wv);
    k_scores<<<dim3(8, 8, NBH), 256>>>();
    k_softmax<<<NBH * Tn, 256>>>();
    k_pv<<<dim3(8, 1, NBH), 256>>>();
    k_logits_b<<<dim3(16, NBN), 256, LOG_SMEM>>>(blm, out);
}

// round 7
// speedup vs baseline: 3.2694x; 1.1724x over previous
#include <cuda_runtime.h>
#include <cuda_fp16.h>
#include <cstdint>

// Problem constants
#define Bsz  2
#define Tn   1024
#define Cn   1024
#define Hn   16
#define HDn  64
#define Vn   50257
#define BTn  2048
#define NBH  32          // B*H
#define NBN  197         // ceil(Vn/256)

// Scratch (static device globals; no allocation)
__device__ float g_x[BTn * Cn];
__device__ float g_q[BTn * Cn];
__device__ float g_k[BTn * Cn];
__device__ float g_v[BTn * Cn];
__device__ float g_p[NBH * Tn * Tn];
// Tile-chunked, pre-swizzled fp16 operands for the LM-head GEMM:
// g_ah: [bm:16][kc:16][row:128][64 halves]   (attention out)
// g_wh: [bn:197][kc:16][row:256][64 halves]  (W_lm)
__device__ __align__(128) __half g_ah[BTn * Cn];
__device__ __align__(128) __half g_wh[(size_t)NBN * 16 * 256 * 64];

#define APAD 20
#define BPAD 136
#define BPAD2 72

__device__ __forceinline__ unsigned f2tf(float f) {
    unsigned r;
    asm("cvt.rna.tf32.f32 %0, %1;" : "=r"(r) : "f"(f));
    return r;
}
__device__ __forceinline__ uint4 tf4(float4 v) {
    uint4 r; r.x = f2tf(v.x); r.y = f2tf(v.y); r.z = f2tf(v.z); r.w = f2tf(v.w);
    return r;
}

__device__ __forceinline__ void mma8(float* c, const unsigned* a, const unsigned* b) {
    asm volatile(
        "mma.sync.aligned.m16n8k8.row.col.f32.tf32.tf32.f32 "
        "{%0,%1,%2,%3},{%4,%5,%6,%7},{%8,%9},{%0,%1,%2,%3};"
        : "+f"(c[0]), "+f"(c[1]), "+f"(c[2]), "+f"(c[3])
        : "r"(a[0]), "r"(a[1]), "r"(a[2]), "r"(a[3]), "r"(b[0]), "r"(b[1]));
}

template <int NT, int BP>
__device__ __forceinline__ void mma_step(const unsigned* __restrict__ As,
                                         const unsigned* __restrict__ Bs,
                                         float (&c)[2][NT][4],
                                         int m0, int n0, int g, int tig) {
#pragma unroll
    for (int ks = 0; ks < 2; ks++) {
        const int k8 = ks * 8;
        unsigned a[2][4];
#pragma unroll
        for (int mt = 0; mt < 2; mt++) {
            const unsigned* ap = As + (m0 + mt * 16 + g) * APAD + k8 + tig;
            a[mt][0] = ap[0];
            a[mt][1] = ap[8 * APAD];
            a[mt][2] = ap[4];
            a[mt][3] = ap[8 * APAD + 4];
        }
        unsigned b[NT][2];
#pragma unroll
        for (int nt = 0; nt < NT; nt++) {
            const unsigned* bp = Bs + (k8 + tig) * BP + n0 + nt * 8 + g;
            b[nt][0] = bp[0];
            b[nt][1] = bp[4 * BP];
        }
#pragma unroll
        for (int mt = 0; mt < 2; mt++)
#pragma unroll
            for (int nt = 0; nt < NT; nt++) mma8(c[mt][nt], a[mt], b[nt]);
    }
}

// ===========================================================================
// helpers (sm_80/sm_90 baseline ISA)
// ===========================================================================
__device__ __forceinline__ uint32_t smem_u32(const void* p) {
    return (uint32_t)__cvta_generic_to_shared(p);
}
__device__ __forceinline__ void mma16(float* c, const unsigned* a, const unsigned* b) {
    asm volatile(
        "mma.sync.aligned.m16n8k16.row.col.f32.f16.f16.f32 "
        "{%0,%1,%2,%3},{%4,%5,%6,%7},{%8,%9},{%0,%1,%2,%3};"
        : "+f"(c[0]), "+f"(c[1]), "+f"(c[2]), "+f"(c[3])
        : "r"(a[0]), "r"(a[1]), "r"(a[2]), "r"(a[3]), "r"(b[0]), "r"(b[1]));
}
__device__ __forceinline__ void ldsm4(unsigned& r0, unsigned& r1, unsigned& r2,
                                      unsigned& r3, uint32_t addr) {
    asm volatile("ldmatrix.sync.aligned.m8n8.x4.shared.b16 {%0,%1,%2,%3}, [%4];"
                 : "=r"(r0), "=r"(r1), "=r"(r2), "=r"(r3) : "r"(addr));
}
__device__ __forceinline__ void bulk_g2s(uint32_t dst, const void* src, int bytes,
                                         uint32_t mbar) {
    asm volatile(
        "cp.async.bulk.shared::cluster.global.mbarrier::complete_tx::bytes "
        "[%0], [%1], %2, [%3];"
        :: "r"(dst), "l"(src), "r"(bytes), "r"(mbar) : "memory");
}
#define MBAR_INIT(mbar, cnt) \
    asm volatile("mbarrier.init.shared.b64 [%0], %1;" \
                 :: "r"((uint32_t)(mbar)), "r"((uint32_t)(cnt)) : "memory")
#define MBAR_EXPECT(mbar, tx) \
    asm volatile("mbarrier.arrive.expect_tx.shared.b64 _, [%0], %1;" \
                 :: "r"((uint32_t)(mbar)), "r"((uint32_t)(tx)) : "memory")
#define MBAR_WAIT(mbar, parity) do {                                          \
    uint32_t _m = (uint32_t)(mbar);                                           \
    uint32_t _p = (uint32_t)(parity);                                         \
    asm volatile(                                                             \
        "{\n\t.reg .pred P1;\n\t"                                             \
        "WAIT_LOOP_%=:\n\t"                                                   \
        "mbarrier.try_wait.parity.acquire.cta.shared::cta.b64 P1, [%0], %1, 0x989680;\n\t" \
        "@P1 bra.uni WAIT_DONE_%=;\n\t"                                       \
        "bra.uni WAIT_LOOP_%=;\n\t"                                           \
        "WAIT_DONE_%=:\n\t}"                                                  \
        :: "r"(_m), "r"(_p) : "memory");                                      \
} while (0)

// ---------------------------------------------------------------------------
// 1) Embedding
__global__ __launch_bounds__(256) void k_embed(const int* __restrict__ idx,
                                               const float* __restrict__ tok,
                                               const float* __restrict__ pos) {
    int i = blockIdx.x;
    int t = i & (Tn - 1);
    int token = idx[i];
    const float4* te = (const float4*)(tok + (size_t)token * Cn);
    const float4* pe = (const float4*)(pos + (size_t)t * Cn);
    float4 a = te[threadIdx.x], b = pe[threadIdx.x];
    float4 o;
    o.x = a.x + b.x; o.y = a.y + b.y; o.z = a.z + b.z; o.w = a.w + b.w;
    ((float4*)(g_x + (size_t)i * Cn))[threadIdx.x] = o;
}

// ---------------------------------------------------------------------------
// 1b) W_lm -> fp16, tile-chunked + SW128-swizzled layout.
__global__ __launch_bounds__(256) void k_w2h(const float* __restrict__ W) {
    int gid = blockIdx.x * 256 + threadIdx.x;     // one 8-half granule each
    if (gid >= Vn * 128) return;
    int v = gid >> 7, g8 = gid & 127;             // kk = g8*8
    const float4* s = (const float4*)(W + (size_t)v * Cn + g8 * 8);
    float4 x = s[0], y = s[1];
    __half2 h0 = __floats2half2_rn(x.x, x.y);
    __half2 h1 = __floats2half2_rn(x.z, x.w);
    __half2 h2 = __floats2half2_rn(y.x, y.y);
    __half2 h3 = __floats2half2_rn(y.z, y.w);
    uint4 o;
    o.x = *(unsigned*)&h0; o.y = *(unsigned*)&h1;
    o.z = *(unsigned*)&h2; o.w = *(unsigned*)&h3;
    int bn = v >> 8, r = v & 255;
    int kc = g8 >> 3, c16 = g8 & 7;
    size_t chunkB = (((size_t)bn * 16 + kc) * (256 * 64)) * 2;
    uint32_t off = (uint32_t)r * 128 + ((unsigned)(c16 ^ (r & 7)) << 4);
    *(uint4*)((char*)g_wh + chunkB + off) = o;
}

// ---------------------------------------------------------------------------
// 2) QKV projection (legacy tf32, unchanged)
__global__ __launch_bounds__(256) void k_qkv(const float* __restrict__ Wq,
                                             const float* __restrict__ Wk,
                                             const float* __restrict__ Wv) {
    __shared__ unsigned As[128 * APAD];
    __shared__ unsigned Bs[16 * BPAD];
    const float* W = (blockIdx.z == 0) ? Wq : (blockIdx.z == 1) ? Wk : Wv;
    float* o = (blockIdx.z == 0) ? g_q : (blockIdx.z == 1) ? g_k : g_v;
    const int bm = blockIdx.x, bn = blockIdx.y;
    const int tid = threadIdx.x, lane = tid & 31, warp = tid >> 5;
    const int g = lane >> 2, tig = lane & 3;
    const int m0 = (warp >> 1) * 32, n0 = (warp & 1) * 64;

    float c[2][8][4];
#pragma unroll
    for (int mt = 0; mt < 2; mt++)
#pragma unroll
        for (int nt = 0; nt < 8; nt++)
#pragma unroll
            for (int e = 0; e < 4; e++) c[mt][nt][e] = 0.f;

    const int lm = tid & 127, lkk = (tid >> 7) * 8;
    const int bkk = tid >> 4, bn8 = (tid & 15) * 8;
    const int gn0 = bn * 128 + bn8;
    const int h = gn0 >> 6, d = gn0 & 63;
    const float* Wb = W + (size_t)h * (Cn * HDn) + d;
    const float* Ab = g_x + (size_t)(bm * 128 + lm) * Cn + lkk;

    for (int k0 = 0; k0 < Cn; k0 += 16) {
        float4 a0 = *(const float4*)(Ab + k0);
        float4 a1 = *(const float4*)(Ab + k0 + 4);
        float4 b0 = *(const float4*)(Wb + (size_t)(k0 + bkk) * HDn);
        float4 b1 = *(const float4*)(Wb + (size_t)(k0 + bkk) * HDn + 4);
        __syncthreads();
        *(uint4*)(As + lm * APAD + lkk)     = tf4(a0);
        *(uint4*)(As + lm * APAD + lkk + 4) = tf4(a1);
        *(uint4*)(Bs + bkk * BPAD + bn8)     = tf4(b0);
        *(uint4*)(Bs + bkk * BPAD + bn8 + 4) = tf4(b1);
        __syncthreads();
        mma_step<8, BPAD>(As, Bs, c, m0, n0, g, tig);
    }

    const float scale = (blockIdx.z == 0) ? 0.03125f : 1.0f;
#pragma unroll
    for (int mt = 0; mt < 2; mt++)
#pragma unroll
        for (int nt = 0; nt < 8; nt++) {
            int r = bm * 128 + m0 + mt * 16 + g;
            int cl = bn * 128 + n0 + nt * 8 + 2 * tig;
#pragma unroll
            for (int e = 0; e < 4; e++) {
                int rr = r + ((e >= 2) ? 8 : 0);
                int cc = cl + (e & 1);
                int b2 = rr >> 10, t2 = rr & 1023;
                int hh = cc >> 6, dd = cc & 63;
                o[(((size_t)(b2 * Hn + hh)) * Tn + t2) * HDn + dd] = c[mt][nt][e] * scale;
            }
        }
}

// ---------------------------------------------------------------------------
// 3) Scores (legacy tf32): lower-triangle-packed grid (36, 1, 32)
__global__ __launch_bounds__(256) void k_scores() {
    const int p = blockIdx.x, bh = blockIdx.z;
    int bm = 0;
    while ((bm + 1) * (bm + 2) / 2 <= p) bm++;
    const int bn = p - bm * (bm + 1) / 2;
    __shared__ unsigned As[128 * APAD];
    __shared__ unsigned Bs[16 * BPAD];
    const int tid = threadIdx.x, lane = tid & 31, warp = tid >> 5;
    const int g = lane >> 2, tig = lane & 3;
    const int m0 = (warp >> 1) * 32, n0 = (warp & 1) * 64;

    float c[2][8][4];
#pragma unroll
    for (int mt = 0; mt < 2; mt++)
#pragma unroll
        for (int nt = 0; nt < 8; nt++)
#pragma unroll
            for (int e = 0; e < 4; e++) c[mt][nt][e] = 0.f;

    const int lm = tid & 127, lkk = (tid >> 7) * 8;
    const float* Aq = g_q + (size_t)bh * (Tn * HDn) + (size_t)(bm * 128 + lm) * HDn + lkk;
    const float* Bk = g_k + (size_t)bh * (Tn * HDn) + (size_t)(bn * 128 + lm) * HDn + lkk;

    for (int k0 = 0; k0 < HDn; k0 += 16) {
        float4 a0 = *(const float4*)(Aq + k0);
        float4 a1 = *(const float4*)(Aq + k0 + 4);
        float4 b0 = *(const float4*)(Bk + k0);
        float4 b1 = *(const float4*)(Bk + k0 + 4);
        __syncthreads();
        *(uint4*)(As + lm * APAD + lkk)     = tf4(a0);
        *(uint4*)(As + lm * APAD + lkk + 4) = tf4(a1);
        float bv[8] = {b0.x, b0.y, b0.z, b0.w, b1.x, b1.y, b1.z, b1.w};
#pragma unroll
        for (int j = 0; j < 8; j++) Bs[(lkk + j) * BPAD + lm] = f2tf(bv[j]);
        __syncthreads();
        mma_step<8, BPAD>(As, Bs, c, m0, n0, g, tig);
    }

    float* P = g_p + (size_t)bh * (Tn * Tn);
#pragma unroll
    for (int mt = 0; mt < 2; mt++)
#pragma unroll
        for (int nt = 0; nt < 8; nt++) {
            int r = bm * 128 + m0 + mt * 16 + g;
            int cl = bn * 128 + n0 + nt * 8 + 2 * tig;
#pragma unroll
            for (int e = 0; e < 4; e++) {
                int rr = r + ((e >= 2) ? 8 : 0);
                int cc = cl + (e & 1);
                P[(size_t)rr * Tn + cc] = c[mt][nt][e];
            }
        }
}

// ---------------------------------------------------------------------------
// 4) Row softmax (unchanged)
__global__ __launch_bounds__(256) void k_softmax() {
    const int row = blockIdx.x;
    const int t = row & (Tn - 1);
    float* pr = g_p + (size_t)row * Tn;
    const int tid = threadIdx.x;
    const int len = t + 1;

    __shared__ float red[8];
    __shared__ float bval;

    float v[4];
    float mx = -1e30f;
#pragma unroll
    for (int i = 0; i < 4; i++) {
        int s = tid + i * 256;
        v[i] = (s < len) ? pr[s] : -1e30f;
        mx = fmaxf(mx, v[i]);
    }
#pragma unroll
    for (int o = 16; o; o >>= 1) mx = fmaxf(mx, __shfl_xor_sync(0xffffffffu, mx, o));
    if ((tid & 31) == 0) red[tid >> 5] = mx;
    __syncthreads();
    if (tid == 0) {
        float m2 = red[0];
#pragma unroll
        for (int i = 1; i < 8; i++) m2 = fmaxf(m2, red[i]);
        bval = m2;
    }
    __syncthreads();
    mx = bval;

    float sum = 0.f;
#pragma unroll
    for (int i = 0; i < 4; i++) {
        int s = tid + i * 256;
        float e = (s < len) ? __expf(v[i] - mx) : 0.f;
        v[i] = e;
        sum += e;
    }
#pragma unroll
    for (int o = 16; o; o >>= 1) sum += __shfl_xor_sync(0xffffffffu, sum, o);
    if ((tid & 31) == 0) red[tid >> 5] = sum;
    __syncthreads();
    if (tid == 0) {
        float s2 = 0.f;
#pragma unroll
        for (int i = 0; i < 8; i++) s2 += red[i];
        bval = s2;
    }
    __syncthreads();
    const float inv = 1.0f / bval;
#pragma unroll
    for (int i = 0; i < 4; i++) {
        int s = tid + i * 256;
        pr[s] = v[i] * inv;
    }
}

// ---------------------------------------------------------------------------
// 5) PV (legacy tf32; epilogue emits fp16 into chunked+swizzled g_ah)
__global__ __launch_bounds__(256) void k_pv() {
    const int bm = blockIdx.x, bh = blockIdx.z;
    __shared__ unsigned As[128 * APAD];
    __shared__ unsigned Bs[16 * BPAD2];
    const int tid = threadIdx.x, lane = tid & 31, warp = tid >> 5;
    const int g = lane >> 2, tig = lane & 3;
    const int m0 = (warp >> 1) * 32, n0 = (warp & 1) * 32;

    float c[2][4][4];
#pragma unroll
    for (int mt = 0; mt < 2; mt++)
#pragma unroll
        for (int nt = 0; nt < 4; nt++)
#pragma unroll
            for (int e = 0; e < 4; e++) c[mt][nt][e] = 0.f;

    const int lm = tid & 127, lkk = (tid >> 7) * 8;
    const int bkk = tid >> 4, bn4 = (tid & 15) * 4;
    const float* Ap = g_p + (size_t)bh * (Tn * Tn) + (size_t)(bm * 128 + lm) * Tn + lkk;
    const float* Bv = g_v + (size_t)bh * (Tn * HDn) + bn4;
    const int kmax = (bm + 1) * 128;

    for (int k0 = 0; k0 < kmax; k0 += 16) {
        float4 a0 = *(const float4*)(Ap + k0);
        float4 a1 = *(const float4*)(Ap + k0 + 4);
        float4 b0 = *(const float4*)(Bv + (size_t)(k0 + bkk) * HDn);
        __syncthreads();
        *(uint4*)(As + lm * APAD + lkk)     = tf4(a0);
        *(uint4*)(As + lm * APAD + lkk + 4) = tf4(a1);
        *(uint4*)(Bs + bkk * BPAD2 + bn4)   = tf4(b0);
        __syncthreads();
        mma_step<4, BPAD2>(As, Bs, c, m0, n0, g, tig);
    }

    const int b2 = bh >> 4, hh = bh & 15;   // kc = hh
#pragma unroll
    for (int mt = 0; mt < 2; mt++)
#pragma unroll
        for (int nt = 0; nt < 4; nt++) {
            int r0 = bm * 128 + m0 + mt * 16 + g;
            int cl = n0 + nt * 8 + 2 * tig;
#pragma unroll
            for (int e = 0; e < 4; e++) {
                int rr = r0 + ((e >= 2) ? 8 : 0);
                int cc = cl + (e & 1);
                int row = b2 * Tn + rr;           // 0..2047
                int bma = row >> 7, r = row & 127;
                size_t chunkB = (((size_t)bma * 16 + hh) * (128 * 64)) * 2;
                uint32_t off = (uint32_t)r * 128 +
                               ((unsigned)(((cc >> 3) ^ (r & 7))) << 4) + (cc & 7) * 2;
                *(__half*)((char*)g_ah + chunkB + off) = __float2half_rn(c[mt][nt][e]);
            }
        }
}

// ---------------------------------------------------------------------------
// 6) LM head: fp16 mma.m16n8k16; cp.async.bulk staging, 3-stage mbarrier ring,
//    fragment double-buffered mainloop, SMEM-staged coalesced epilogue.
//    Tile 128(M) x 256(N) x 64(K), 256 threads, warp tile 64x64.
//    grid (16, 197): M fastest for L2 B-slab sharing.
#define LKCH 16                          // K chunks of 64
#define A_CH_BYTES (128 * 128)           // 16KB
#define B_CH_BYTES (256 * 128)           // 32KB
#define LSTG_BYTES (A_CH_BYTES + B_CH_BYTES)   // 49152
#define LOG_SMEM (3 * LSTG_BYTES)        // 147456
#define OPITCH 264                       // f32 pitch for epilogue staging

struct Frags { unsigned a[4][4]; unsigned b[8][2]; };

__device__ __forceinline__ void load_frags(Frags& f, uint32_t sb, int kt,
                                           uint32_t aAddr0, uint32_t bAddr0,
                                           int gA16, int gB16, int l7) {
    const uint32_t xA = ((uint32_t)((kt * 2 + gA16) ^ l7)) << 4;
    const uint32_t xB = ((uint32_t)((kt * 2 + gB16) ^ l7)) << 4;
#pragma unroll
    for (int mt = 0; mt < 4; mt++)
        ldsm4(f.a[mt][0], f.a[mt][1], f.a[mt][2], f.a[mt][3],
              sb + aAddr0 + mt * (16 * 128) + xA);
#pragma unroll
    for (int np = 0; np < 4; np++)
        ldsm4(f.b[2 * np][0], f.b[2 * np][1], f.b[2 * np + 1][0], f.b[2 * np + 1][1],
              sb + bAddr0 + np * (16 * 128) + xB);
}

__global__ __launch_bounds__(256, 1) void k_logits_b(const float* __restrict__ blm,
                                                     float* __restrict__ out) {
    extern __shared__ __align__(128) char sm[];
    __shared__ float s_bias[256];
    __shared__ __align__(8) unsigned long long s_mb[3];
    const int tid = threadIdx.x, lane = tid & 31, wid = tid >> 5;
    const int bm = blockIdx.x, bn = blockIdx.y;
    const uint32_t sbase = smem_u32(sm);
    const uint32_t mb0 = smem_u32(&s_mb[0]);

    {
        int gc = bn * 256 + tid;
        s_bias[tid] = (gc < Vn) ? blm[gc] : 0.f;
    }
    if (tid == 0) {
        MBAR_INIT(mb0, 1);
        MBAR_INIT(mb0 + 8, 1);
        MBAR_INIT(mb0 + 16, 1);
    }
    __syncthreads();

    const char* gA = (const char*)g_ah + ((size_t)bm * LKCH) * A_CH_BYTES;
    const char* gB = (const char*)g_wh + ((size_t)bn * LKCH) * B_CH_BYTES;

    if (tid == 0) {
#pragma unroll
        for (int s = 0; s < 3; s++) {
            uint32_t m = mb0 + s * 8;
            uint32_t dst = sbase + s * LSTG_BYTES;
            MBAR_EXPECT(m, LSTG_BYTES);
            bulk_g2s(dst, gA + (size_t)s * A_CH_BYTES, A_CH_BYTES, m);
            bulk_g2s(dst + A_CH_BYTES, gB + (size_t)s * B_CH_BYTES, B_CH_BYTES, m);
        }
    }

    float c[4][8][4];
#pragma unroll
    for (int mt = 0; mt < 4; mt++)
#pragma unroll
        for (int nt = 0; nt < 8; nt++)
#pragma unroll
            for (int e = 0; e < 4; e++) c[mt][nt][e] = 0.f;

    const int wm0 = (wid >> 2) * 64, wn0 = (wid & 3) * 64;
    const int l7 = lane & 7;
    const int rowA = wm0 + (lane & 15);
    const int rowB = wn0 + ((lane >> 4) << 3) + l7;
    const uint32_t aAddr0 = (uint32_t)rowA * 128;
    const uint32_t bAddr0 = A_CH_BYTES + (uint32_t)rowB * 128;
    const int gA16 = lane >> 4;
    const int gB16 = (lane >> 3) & 1;

    Frags fr[2];
    MBAR_WAIT(mb0, 0);
    load_frags(fr[0], sbase, 0, aAddr0, bAddr0, gA16, gB16, l7);

    for (int kc = 0; kc < LKCH; kc++) {
        const uint32_t sb = sbase + (kc % 3) * LSTG_BYTES;
#pragma unroll
        for (int kt = 0; kt < 4; kt++) {
            const int cur = kt & 1;
            if (kt < 3)
                load_frags(fr[cur ^ 1], sb, kt + 1, aAddr0, bAddr0, gA16, gB16, l7);
#pragma unroll
            for (int mt = 0; mt < 4; mt++)
#pragma unroll
                for (int nt = 0; nt < 8; nt++) mma16(c[mt][nt], fr[cur].a[mt], fr[cur].b[nt]);
        }
        __syncthreads();
        if (tid == 0 && kc + 3 < LKCH) {
            int s = kc % 3;
            uint32_t m = mb0 + s * 8;
            uint32_t dst = sbase + s * LSTG_BYTES;
            MBAR_EXPECT(m, LSTG_BYTES);
            bulk_g2s(dst, gA + (size_t)(kc + 3) * A_CH_BYTES, A_CH_BYTES, m);
            bulk_g2s(dst + A_CH_BYTES, gB + (size_t)(kc + 3) * B_CH_BYTES, B_CH_BYTES, m);
        }
        if (kc + 1 < LKCH) {
            MBAR_WAIT(mb0 + ((kc + 1) % 3) * 8, ((kc + 1) / 3) & 1);
            load_frags(fr[0], sbase + ((kc + 1) % 3) * LSTG_BYTES, 0,
                       aAddr0, bAddr0, gA16, gB16, l7);
        }
    }

    // ---- epilogue: stage accum (+bias) in SMEM, then coalesced stores ----
    __syncthreads();                       // all warps done reading stage smem
    float* so = (float*)sm;                // 128 x OPITCH floats = 135168 B
    const int g = lane >> 2, tig = lane & 3;
#pragma unroll
    for (int mt = 0; mt < 4; mt++)
#pragma unroll
        for (int e2 = 0; e2 < 2; e2++) {
            int rl = wm0 + mt * 16 + g + e2 * 8;
#pragma unroll
            for (int nt = 0; nt < 8; nt++) {
                int cl = wn0 + nt * 8 + 2 * tig;
                float2 w;
                w.x = c[mt][nt][e2 * 2 + 0] + s_bias[cl];
                w.y = c[mt][nt][e2 * 2 + 1] + s_bias[cl + 1];
                *(float2*)(so + rl * OPITCH + cl) = w;
            }
        }
    __syncthreads();
    // warp wid handles rows wid*16..+15; lane-contiguous scalar stores
#pragma unroll 1
    for (int rr = 0; rr < 16; rr++) {
        int rl = wid * 16 + rr;
        int row = bm * 128 + rl;
        float* orow = out + (size_t)row * Vn;
        const float* srow = so + rl * OPITCH;
#pragma unroll
        for (int j = 0; j < 8; j++) {
            int cl = lane + j * 32;
            int col = bn * 256 + cl;
            if (col < Vn) orow[col] = srow[cl];
        }
    }
}

// ---------------------------------------------------------------------------
extern "C" void kernel_launch(void* const* d_in, const int* in_sizes, int n_in,
                              void* d_out, int out_size) {
    (void)in_sizes; (void)n_in; (void)out_size;
    const int*   idx = (const int*)d_in[0];
    const float* tok = (const float*)d_in[1];
    const float* pos = (const float*)d_in[2];
    const float* Wq  = (const float*)d_in[3];
    const float* Wk  = (const float*)d_in[4];
    const float* Wv  = (const float*)d_in[5];
    const float* Wlm = (const float*)d_in[6];
    const float* blm = (const float*)d_in[7];
    float* out = (float*)d_out;

    cudaFuncSetAttribute(k_logits_b, cudaFuncAttributeMaxDynamicSharedMemorySize,
                         LOG_SMEM);

    k_w2h<<<(Vn * 128 + 255) / 256, 256>>>(Wlm);
    k_embed<<<BTn, 256>>>(idx, tok, pos);
    k_qkv<<<dim3(16, 8, 3), 256>>>(Wq, Wk, Wv);
    k_scores<<<dim3(36, 1, NBH), 256>>>();
    k_softmax<<<NBH * Tn, 256>>>();
    k_pv<<<dim3(8, 1, NBH), 256>>>();
    k_logits_b<<<dim3(16, NBN), 256, LOG_SMEM>>>(blm, out);
}

// round 8
// speedup vs baseline: 3.8806x; 1.1870x over previous
#include <cuda_runtime.h>
#include <cuda_fp16.h>
#include <cstdint>

// Problem constants
#define Bsz  2
#define Tn   1024
#define Cn   1024
#define Hn   16
#define HDn  64
#define Vn   50257
#define BTn  2048
#define NBH  32          // B*H
#define NBN  197         // ceil(Vn/256)

// Scratch (static device globals; no allocation)
__device__ float g_q[BTn * Cn];
__device__ float g_k[BTn * Cn];
__device__ float g_v[BTn * Cn];
__device__ float g_p[NBH * Tn * Tn];
// Chunked, pre-swizzled fp16 operands (A: [.. ][kc][row128][64], B: [..][kc][row256][64])
__device__ __align__(128) __half g_xh[BTn * Cn];                 // embed out (A of QKV)
__device__ __align__(128) __half g_wqkvh[3 * 4 * 16 * 256 * 64]; // Wq/Wk/Wv (B of QKV)
__device__ __align__(128) __half g_ah[BTn * Cn];                 // attn out (A of logits)
__device__ __align__(128) __half g_wh[(size_t)NBN * 16 * 256 * 64]; // W_lm (B of logits)

#define APAD 20
#define BPAD 136
#define BPAD2 72

__device__ __forceinline__ unsigned f2tf(float f) {
    unsigned r;
    asm("cvt.rna.tf32.f32 %0, %1;" : "=r"(r) : "f"(f));
    return r;
}
__device__ __forceinline__ uint4 tf4(float4 v) {
    uint4 r; r.x = f2tf(v.x); r.y = f2tf(v.y); r.z = f2tf(v.z); r.w = f2tf(v.w);
    return r;
}

__device__ __forceinline__ void mma8(float* c, const unsigned* a, const unsigned* b) {
    asm volatile(
        "mma.sync.aligned.m16n8k8.row.col.f32.tf32.tf32.f32 "
        "{%0,%1,%2,%3},{%4,%5,%6,%7},{%8,%9},{%0,%1,%2,%3};"
        : "+f"(c[0]), "+f"(c[1]), "+f"(c[2]), "+f"(c[3])
        : "r"(a[0]), "r"(a[1]), "r"(a[2]), "r"(a[3]), "r"(b[0]), "r"(b[1]));
}

template <int NT, int BP>
__device__ __forceinline__ void mma_step(const unsigned* __restrict__ As,
                                         const unsigned* __restrict__ Bs,
                                         float (&c)[2][NT][4],
                                         int m0, int n0, int g, int tig) {
#pragma unroll
    for (int ks = 0; ks < 2; ks++) {
        const int k8 = ks * 8;
        unsigned a[2][4];
#pragma unroll
        for (int mt = 0; mt < 2; mt++) {
            const unsigned* ap = As + (m0 + mt * 16 + g) * APAD + k8 + tig;
            a[mt][0] = ap[0];
            a[mt][1] = ap[8 * APAD];
            a[mt][2] = ap[4];
            a[mt][3] = ap[8 * APAD + 4];
        }
        unsigned b[NT][2];
#pragma unroll
        for (int nt = 0; nt < NT; nt++) {
            const unsigned* bp = Bs + (k8 + tig) * BP + n0 + nt * 8 + g;
            b[nt][0] = bp[0];
            b[nt][1] = bp[4 * BP];
        }
#pragma unroll
        for (int mt = 0; mt < 2; mt++)
#pragma unroll
            for (int nt = 0; nt < NT; nt++) mma8(c[mt][nt], a[mt], b[nt]);
    }
}

// ===========================================================================
// helpers (sm_80/sm_90 baseline ISA)
// ===========================================================================
__device__ __forceinline__ uint32_t smem_u32(const void* p) {
    return (uint32_t)__cvta_generic_to_shared(p);
}
__device__ __forceinline__ void mma16(float* c, const unsigned* a, const unsigned* b) {
    asm volatile(
        "mma.sync.aligned.m16n8k16.row.col.f32.f16.f16.f32 "
        "{%0,%1,%2,%3},{%4,%5,%6,%7},{%8,%9},{%0,%1,%2,%3};"
        : "+f"(c[0]), "+f"(c[1]), "+f"(c[2]), "+f"(c[3])
        : "r"(a[0]), "r"(a[1]), "r"(a[2]), "r"(a[3]), "r"(b[0]), "r"(b[1]));
}
__device__ __forceinline__ void ldsm4(unsigned& r0, unsigned& r1, unsigned& r2,
                                      unsigned& r3, uint32_t addr) {
    asm volatile("ldmatrix.sync.aligned.m8n8.x4.shared.b16 {%0,%1,%2,%3}, [%4];"
                 : "=r"(r0), "=r"(r1), "=r"(r2), "=r"(r3) : "r"(addr));
}
__device__ __forceinline__ void bulk_g2s(uint32_t dst, const void* src, int bytes,
                                         uint32_t mbar) {
    asm volatile(
        "cp.async.bulk.shared::cluster.global.mbarrier::complete_tx::bytes "
        "[%0], [%1], %2, [%3];"
        :: "r"(dst), "l"(src), "r"(bytes), "r"(mbar) : "memory");
}
#define MBAR_INIT(mbar, cnt) \
    asm volatile("mbarrier.init.shared.b64 [%0], %1;" \
                 :: "r"((uint32_t)(mbar)), "r"((uint32_t)(cnt)) : "memory")
#define MBAR_EXPECT(mbar, tx) \
    asm volatile("mbarrier.arrive.expect_tx.shared.b64 _, [%0], %1;" \
                 :: "r"((uint32_t)(mbar)), "r"((uint32_t)(tx)) : "memory")
#define MBAR_WAIT(mbar, parity) do {                                          \
    uint32_t _m = (uint32_t)(mbar);                                           \
    uint32_t _p = (uint32_t)(parity);                                         \
    asm volatile(                                                             \
        "{\n\t.reg .pred P1;\n\t"                                             \
        "WAIT_LOOP_%=:\n\t"                                                   \
        "mbarrier.try_wait.parity.acquire.cta.shared::cta.b64 P1, [%0], %1, 0x989680;\n\t" \
        "@P1 bra.uni WAIT_DONE_%=;\n\t"                                       \
        "bra.uni WAIT_LOOP_%=;\n\t"                                           \
        "WAIT_DONE_%=:\n\t}"                                                  \
        :: "r"(_m), "r"(_p) : "memory");                                      \
} while (0)

// ---------------------------------------------------------------------------
// 1) Embedding -> fp16 chunked+swizzled A layout (g_xh)
__global__ __launch_bounds__(256) void k_embed(const int* __restrict__ idx,
                                               const float* __restrict__ tok,
                                               const float* __restrict__ pos) {
    int i = blockIdx.x;                   // bt row
    int t = i & (Tn - 1);
    int token = idx[i];
    const float4* te = (const float4*)(tok + (size_t)token * Cn);
    const float4* pe = (const float4*)(pos + (size_t)t * Cn);
    int tid = threadIdx.x;
    float4 a = te[tid], b = pe[tid];
    __half2 h0 = __floats2half2_rn(a.x + b.x, a.y + b.y);
    __half2 h1 = __floats2half2_rn(a.z + b.z, a.w + b.w);
    uint2 o; o.x = *(unsigned*)&h0; o.y = *(unsigned*)&h1;
    int r = i & 127, bm = i >> 7;
    int kc = tid >> 4;                    // k = tid*4; kc = k>>6
    int c16 = (tid >> 1) & 7;
    int hsel = tid & 1;
    size_t base = ((size_t)(bm * 16 + kc)) * 16384;
    uint32_t off = (uint32_t)r * 128 + ((unsigned)(c16 ^ (r & 7)) << 4) + hsel * 8;
    *(uint2*)((char*)g_xh + base + off) = o;
}

// ---------------------------------------------------------------------------
// 1b) W_lm -> fp16, tile-chunked + SW128-swizzled B layout.
__global__ __launch_bounds__(256) void k_w2h(const float* __restrict__ W) {
    int gid = blockIdx.x * 256 + threadIdx.x;     // one 8-half granule each
    if (gid >= Vn * 128) return;
    int v = gid >> 7, g8 = gid & 127;             // kk = g8*8
    const float4* s = (const float4*)(W + (size_t)v * Cn + g8 * 8);
    float4 x = s[0], y = s[1];
    __half2 h0 = __floats2half2_rn(x.x, x.y);
    __half2 h1 = __floats2half2_rn(x.z, x.w);
    __half2 h2 = __floats2half2_rn(y.x, y.y);
    __half2 h3 = __floats2half2_rn(y.z, y.w);
    uint4 o;
    o.x = *(unsigned*)&h0; o.y = *(unsigned*)&h1;
    o.z = *(unsigned*)&h2; o.w = *(unsigned*)&h3;
    int bn = v >> 8, r = v & 255;
    int kc = g8 >> 3, c16 = g8 & 7;
    size_t chunkB = (((size_t)bn * 16 + kc) * (256 * 64)) * 2;
    uint32_t off = (uint32_t)r * 128 + ((unsigned)(c16 ^ (r & 7)) << 4);
    *(uint4*)((char*)g_wh + chunkB + off) = o;
}

// ---------------------------------------------------------------------------
// 1c) Wq/Wk/Wv -> transposed fp16 chunked B layout (n=(h,d) rows, k=c).
//     unit = (mat, h, kc, c16) handled by 64 threads (one per d); coalesced reads.
__global__ __launch_bounds__(256) void k_wqkv(const float* __restrict__ Wq,
                                              const float* __restrict__ Wk,
                                              const float* __restrict__ Wv) {
    int u = blockIdx.x * 4 + (threadIdx.x >> 6);   // 0..6143
    int d = threadIdx.x & 63;
    int mat = u >> 11;                             // /2048
    int rem = u & 2047;
    int h = rem >> 7;
    int kc = (rem >> 3) & 15;
    int c16 = rem & 7;
    const float* W = (mat == 0) ? Wq : (mat == 1) ? Wk : Wv;
    const float* Wb = W + (size_t)h * (Cn * HDn) + d;
    float vals[8];
#pragma unroll
    for (int j = 0; j < 8; j++) {
        int c = kc * 64 + c16 * 8 + j;
        vals[j] = Wb[(size_t)c * HDn];
    }
    __half2 h0 = __floats2half2_rn(vals[0], vals[1]);
    __half2 h1 = __floats2half2_rn(vals[2], vals[3]);
    __half2 h2 = __floats2half2_rn(vals[4], vals[5]);
    __half2 h3 = __floats2half2_rn(vals[6], vals[7]);
    uint4 o;
    o.x = *(unsigned*)&h0; o.y = *(unsigned*)&h1;
    o.z = *(unsigned*)&h2; o.w = *(unsigned*)&h3;
    int bnAll = mat * 4 + (h >> 2);
    int r = (h & 3) * 64 + d;
    size_t chunkB = (((size_t)bnAll * 16 + kc) * (256 * 64)) * 2;
    uint32_t off = (uint32_t)r * 128 + ((unsigned)(c16 ^ (r & 7)) << 4);
    *(uint4*)((char*)g_wqkvh + chunkB + off) = o;
}

// ===========================================================================
// Shared fp16 bulk-pipeline GEMM pieces (proven in k_logits_b)
// ===========================================================================
#define LKCH 16                          // K chunks of 64
#define A_CH_BYTES (128 * 128)           // 16KB
#define B_CH_BYTES (256 * 128)           // 32KB
#define LSTG_BYTES (A_CH_BYTES + B_CH_BYTES)   // 49152
#define LOG_SMEM (3 * LSTG_BYTES)        // 147456
#define OPITCH 264                       // f32 pitch for epilogue staging

struct Frags { unsigned a[4][4]; unsigned b[8][2]; };

__device__ __forceinline__ void load_frags(Frags& f, uint32_t sb, int kt,
                                           uint32_t aAddr0, uint32_t bAddr0,
                                           int gA16, int gB16, int l7) {
    const uint32_t xA = ((uint32_t)((kt * 2 + gA16) ^ l7)) << 4;
    const uint32_t xB = ((uint32_t)((kt * 2 + gB16) ^ l7)) << 4;
#pragma unroll
    for (int mt = 0; mt < 4; mt++)
        ldsm4(f.a[mt][0], f.a[mt][1], f.a[mt][2], f.a[mt][3],
              sb + aAddr0 + mt * (16 * 128) + xA);
#pragma unroll
    for (int np = 0; np < 4; np++)
        ldsm4(f.b[2 * np][0], f.b[2 * np][1], f.b[2 * np + 1][0], f.b[2 * np + 1][1],
              sb + bAddr0 + np * (16 * 128) + xB);
}

// mainloop over LKCH chunks; accumulates into c. Caller sets up mbarriers+first loads.
__device__ __forceinline__ void gemm_mainloop(float (&c)[4][8][4], uint32_t sbase,
                                              uint32_t mb0, const char* gA,
                                              const char* gB, int tid,
                                              uint32_t aAddr0, uint32_t bAddr0,
                                              int gA16, int gB16, int l7) {
    Frags fr[2];
    MBAR_WAIT(mb0, 0);
    load_frags(fr[0], sbase, 0, aAddr0, bAddr0, gA16, gB16, l7);

    for (int kc = 0; kc < LKCH; kc++) {
        const uint32_t sb = sbase + (kc % 3) * LSTG_BYTES;
#pragma unroll
        for (int kt = 0; kt < 4; kt++) {
            const int cur = kt & 1;
            if (kt < 3)
                load_frags(fr[cur ^ 1], sb, kt + 1, aAddr0, bAddr0, gA16, gB16, l7);
#pragma unroll
            for (int mt = 0; mt < 4; mt++)
#pragma unroll
                for (int nt = 0; nt < 8; nt++) mma16(c[mt][nt], fr[cur].a[mt], fr[cur].b[nt]);
        }
        __syncthreads();
        if (tid == 0 && kc + 3 < LKCH) {
            int s = kc % 3;
            uint32_t m = mb0 + s * 8;
            uint32_t dst = sbase + s * LSTG_BYTES;
            MBAR_EXPECT(m, LSTG_BYTES);
            bulk_g2s(dst, gA + (size_t)(kc + 3) * A_CH_BYTES, A_CH_BYTES, m);
            bulk_g2s(dst + A_CH_BYTES, gB + (size_t)(kc + 3) * B_CH_BYTES, B_CH_BYTES, m);
        }
        if (kc + 1 < LKCH) {
            MBAR_WAIT(mb0 + ((kc + 1) % 3) * 8, ((kc + 1) / 3) & 1);
            load_frags(fr[0], sbase + ((kc + 1) % 3) * LSTG_BYTES, 0,
                       aAddr0, bAddr0, gA16, gB16, l7);
        }
    }
}

// ---------------------------------------------------------------------------
// 2) QKV via fp16 bulk pipeline. grid (16, 12): bn 0-3 -> q, 4-7 -> k, 8-11 -> v.
__global__ __launch_bounds__(256, 1) void k_qkv_h() {
    extern __shared__ __align__(128) char sm[];
    __shared__ __align__(8) unsigned long long s_mb[3];
    const int tid = threadIdx.x, lane = tid & 31, wid = tid >> 5;
    const int bm = blockIdx.x, bnAll = blockIdx.y;
    const uint32_t sbase = smem_u32(sm);
    const uint32_t mb0 = smem_u32(&s_mb[0]);

    if (tid == 0) {
        MBAR_INIT(mb0, 1);
        MBAR_INIT(mb0 + 8, 1);
        MBAR_INIT(mb0 + 16, 1);
    }
    __syncthreads();

    const char* gA = (const char*)g_xh + ((size_t)bm * LKCH) * A_CH_BYTES;
    const char* gB = (const char*)g_wqkvh + ((size_t)bnAll * LKCH) * B_CH_BYTES;

    if (tid == 0) {
#pragma unroll
        for (int s = 0; s < 3; s++) {
            uint32_t m = mb0 + s * 8;
            uint32_t dst = sbase + s * LSTG_BYTES;
            MBAR_EXPECT(m, LSTG_BYTES);
            bulk_g2s(dst, gA + (size_t)s * A_CH_BYTES, A_CH_BYTES, m);
            bulk_g2s(dst + A_CH_BYTES, gB + (size_t)s * B_CH_BYTES, B_CH_BYTES, m);
        }
    }

    float c[4][8][4];
#pragma unroll
    for (int mt = 0; mt < 4; mt++)
#pragma unroll
        for (int nt = 0; nt < 8; nt++)
#pragma unroll
            for (int e = 0; e < 4; e++) c[mt][nt][e] = 0.f;

    const int wm0 = (wid >> 2) * 64, wn0 = (wid & 3) * 64;
    const int l7 = lane & 7;
    const uint32_t aAddr0 = (uint32_t)(wm0 + (lane & 15)) * 128;
    const uint32_t bAddr0 = A_CH_BYTES +
                            (uint32_t)(wn0 + ((lane >> 4) << 3) + l7) * 128;
    const int gA16 = lane >> 4, gB16 = (lane >> 3) & 1;

    gemm_mainloop(c, sbase, mb0, gA, gB, tid, aAddr0, bAddr0, gA16, gB16, l7);

    // epilogue: stage (scaled) accum to SMEM, then coalesced scatter to q/k/v
    const int mat = bnAll >> 2;
    const float sc = (mat == 0) ? 0.03125f : 1.0f;
    float* dstM = (mat == 0) ? g_q : (mat == 1) ? g_k : g_v;
    __syncthreads();
    float* so = (float*)sm;
    const int g = lane >> 2, tig = lane & 3;
#pragma unroll
    for (int mt = 0; mt < 4; mt++)
#pragma unroll
        for (int e2 = 0; e2 < 2; e2++) {
            int rl = wm0 + mt * 16 + g + e2 * 8;
#pragma unroll
            for (int nt = 0; nt < 8; nt++) {
                int cl = wn0 + nt * 8 + 2 * tig;
                float2 w;
                w.x = c[mt][nt][e2 * 2 + 0] * sc;
                w.y = c[mt][nt][e2 * 2 + 1] * sc;
                *(float2*)(so + rl * OPITCH + cl) = w;
            }
        }
    __syncthreads();
#pragma unroll 1
    for (int rr = 0; rr < 16; rr++) {
        int rl = wid * 16 + rr;
        int bt = bm * 128 + rl;
        int b = bt >> 10, t = bt & 1023;
        const float* srow = so + rl * OPITCH;
#pragma unroll
        for (int seg = 0; seg < 4; seg++) {
            int h = (bnAll & 3) * 4 + seg;
            float* dst = dstM + (((size_t)(b * Hn + h)) * Tn + t) * HDn;
#pragma unroll
            for (int j = 0; j < 2; j++) {
                int d = lane + j * 32;
                dst[d] = srow[seg * 64 + d];
            }
        }
    }
}

// ---------------------------------------------------------------------------
// 3) Scores (legacy tf32): lower-triangle-packed grid (36, 1, 32)
__global__ __launch_bounds__(256) void k_scores() {
    const int p = blockIdx.x, bh = blockIdx.z;
    int bm = 0;
    while ((bm + 1) * (bm + 2) / 2 <= p) bm++;
    const int bn = p - bm * (bm + 1) / 2;
    __shared__ unsigned As[128 * APAD];
    __shared__ unsigned Bs[16 * BPAD];
    const int tid = threadIdx.x, lane = tid & 31, warp = tid >> 5;
    const int g = lane >> 2, tig = lane & 3;
    const int m0 = (warp >> 1) * 32, n0 = (warp & 1) * 64;

    float c[2][8][4];
#pragma unroll
    for (int mt = 0; mt < 2; mt++)
#pragma unroll
        for (int nt = 0; nt < 8; nt++)
#pragma unroll
            for (int e = 0; e < 4; e++) c[mt][nt][e] = 0.f;

    const int lm = tid & 127, lkk = (tid >> 7) * 8;
    const float* Aq = g_q + (size_t)bh * (Tn * HDn) + (size_t)(bm * 128 + lm) * HDn + lkk;
    const float* Bk = g_k + (size_t)bh * (Tn * HDn) + (size_t)(bn * 128 + lm) * HDn + lkk;

    for (int k0 = 0; k0 < HDn; k0 += 16) {
        float4 a0 = *(const float4*)(Aq + k0);
        float4 a1 = *(const float4*)(Aq + k0 + 4);
        float4 b0 = *(const float4*)(Bk + k0);
        float4 b1 = *(const float4*)(Bk + k0 + 4);
        __syncthreads();
        *(uint4*)(As + lm * APAD + lkk)     = tf4(a0);
        *(uint4*)(As + lm * APAD + lkk + 4) = tf4(a1);
        float bv[8] = {b0.x, b0.y, b0.z, b0.w, b1.x, b1.y, b1.z, b1.w};
#pragma unroll
        for (int j = 0; j < 8; j++) Bs[(lkk + j) * BPAD + lm] = f2tf(bv[j]);
        __syncthreads();
        mma_step<8, BPAD>(As, Bs, c, m0, n0, g, tig);
    }

    float* P = g_p + (size_t)bh * (Tn * Tn);
#pragma unroll
    for (int mt = 0; mt < 2; mt++)
#pragma unroll
        for (int nt = 0; nt < 8; nt++) {
            int r = bm * 128 + m0 + mt * 16 + g;
            int cl = bn * 128 + n0 + nt * 8 + 2 * tig;
#pragma unroll
            for (int e = 0; e < 4; e++) {
                int rr = r + ((e >= 2) ? 8 : 0);
                int cc = cl + (e & 1);
                P[(size_t)rr * Tn + cc] = c[mt][nt][e];
            }
        }
}

// ---------------------------------------------------------------------------
// 4) Row softmax (unchanged)
__global__ __launch_bounds__(256) void k_softmax() {
    const int row = blockIdx.x;
    const int t = row & (Tn - 1);
    float* pr = g_p + (size_t)row * Tn;
    const int tid = threadIdx.x;
    const int len = t + 1;

    __shared__ float red[8];
    __shared__ float bval;

    float v[4];
    float mx = -1e30f;
#pragma unroll
    for (int i = 0; i < 4; i++) {
        int s = tid + i * 256;
        v[i] = (s < len) ? pr[s] : -1e30f;
        mx = fmaxf(mx, v[i]);
    }
#pragma unroll
    for (int o = 16; o; o >>= 1) mx = fmaxf(mx, __shfl_xor_sync(0xffffffffu, mx, o));
    if ((tid & 31) == 0) red[tid >> 5] = mx;
    __syncthreads();
    if (tid == 0) {
        float m2 = red[0];
#pragma unroll
        for (int i = 1; i < 8; i++) m2 = fmaxf(m2, red[i]);
        bval = m2;
    }
    __syncthreads();
    mx = bval;

    float sum = 0.f;
#pragma unroll
    for (int i = 0; i < 4; i++) {
        int s = tid + i * 256;
        float e = (s < len) ? __expf(v[i] - mx) : 0.f;
        v[i] = e;
        sum += e;
    }
#pragma unroll
    for (int o = 16; o; o >>= 1) sum += __shfl_xor_sync(0xffffffffu, sum, o);
    if ((tid & 31) == 0) red[tid >> 5] = sum;
    __syncthreads();
    if (tid == 0) {
        float s2 = 0.f;
#pragma unroll
        for (int i = 0; i < 8; i++) s2 += red[i];
        bval = s2;
    }
    __syncthreads();
    const float inv = 1.0f / bval;
#pragma unroll
    for (int i = 0; i < 4; i++) {
        int s = tid + i * 256;
        pr[s] = v[i] * inv;
    }
}

// ---------------------------------------------------------------------------
// 5) PV (legacy tf32; epilogue emits fp16 into chunked+swizzled g_ah)
__global__ __launch_bounds__(256) void k_pv() {
    const int bm = blockIdx.x, bh = blockIdx.z;
    __shared__ unsigned As[128 * APAD];
    __shared__ unsigned Bs[16 * BPAD2];
    const int tid = threadIdx.x, lane = tid & 31, warp = tid >> 5;
    const int g = lane >> 2, tig = lane & 3;
    const int m0 = (warp >> 1) * 32, n0 = (warp & 1) * 32;

    float c[2][4][4];
#pragma unroll
    for (int mt = 0; mt < 2; mt++)
#pragma unroll
        for (int nt = 0; nt < 4; nt++)
#pragma unroll
            for (int e = 0; e < 4; e++) c[mt][nt][e] = 0.f;

    const int lm = tid & 127, lkk = (tid >> 7) * 8;
    const int bkk = tid >> 4, bn4 = (tid & 15) * 4;
    const float* Ap = g_p + (size_t)bh * (Tn * Tn) + (size_t)(bm * 128 + lm) * Tn + lkk;
    const float* Bv = g_v + (size_t)bh * (Tn * HDn) + bn4;
    const int kmax = (bm + 1) * 128;

    for (int k0 = 0; k0 < kmax; k0 += 16) {
        float4 a0 = *(const float4*)(Ap + k0);
        float4 a1 = *(const float4*)(Ap + k0 + 4);
        float4 b0 = *(const float4*)(Bv + (size_t)(k0 + bkk) * HDn);
        __syncthreads();
        *(uint4*)(As + lm * APAD + lkk)     = tf4(a0);
        *(uint4*)(As + lm * APAD + lkk + 4) = tf4(a1);
        *(uint4*)(Bs + bkk * BPAD2 + bn4)   = tf4(b0);
        __syncthreads();
        mma_step<4, BPAD2>(As, Bs, c, m0, n0, g, tig);
    }

    const int b2 = bh >> 4, hh = bh & 15;   // kc = hh
#pragma unroll
    for (int mt = 0; mt < 2; mt++)
#pragma unroll
        for (int nt = 0; nt < 4; nt++) {
            int r0 = bm * 128 + m0 + mt * 16 + g;
            int cl = n0 + nt * 8 + 2 * tig;
#pragma unroll
            for (int e = 0; e < 4; e++) {
                int rr = r0 + ((e >= 2) ? 8 : 0);
                int cc = cl + (e & 1);
                int row = b2 * Tn + rr;           // 0..2047
                int bma = row >> 7, r = row & 127;
                size_t chunkB = (((size_t)bma * 16 + hh) * (128 * 64)) * 2;
                uint32_t off = (uint32_t)r * 128 +
                               ((unsigned)(((cc >> 3) ^ (r & 7))) << 4) + (cc & 7) * 2;
                *(__half*)((char*)g_ah + chunkB + off) = __float2half_rn(c[mt][nt][e]);
            }
        }
}

// ---------------------------------------------------------------------------
// 6) LM head: fp16 bulk pipeline (unchanged structure from R7 winner)
__global__ __launch_bounds__(256, 1) void k_logits_b(const float* __restrict__ blm,
                                                     float* __restrict__ out) {
    extern __shared__ __align__(128) char sm[];
    __shared__ float s_bias[256];
    __shared__ __align__(8) unsigned long long s_mb[3];
    const int tid = threadIdx.x, lane = tid & 31, wid = tid >> 5;
    const int bm = blockIdx.x, bn = blockIdx.y;
    const uint32_t sbase = smem_u32(sm);
    const uint32_t mb0 = smem_u32(&s_mb[0]);

    {
        int gc = bn * 256 + tid;
        s_bias[tid] = (gc < Vn) ? blm[gc] : 0.f;
    }
    if (tid == 0) {
        MBAR_INIT(mb0, 1);
        MBAR_INIT(mb0 + 8, 1);
        MBAR_INIT(mb0 + 16, 1);
    }
    __syncthreads();

    const char* gA = (const char*)g_ah + ((size_t)bm * LKCH) * A_CH_BYTES;
    const char* gB = (const char*)g_wh + ((size_t)bn * LKCH) * B_CH_BYTES;

    if (tid == 0) {
#pragma unroll
        for (int s = 0; s < 3; s++) {
            uint32_t m = mb0 + s * 8;
            uint32_t dst = sbase + s * LSTG_BYTES;
            MBAR_EXPECT(m, LSTG_BYTES);
            bulk_g2s(dst, gA + (size_t)s * A_CH_BYTES, A_CH_BYTES, m);
            bulk_g2s(dst + A_CH_BYTES, gB + (size_t)s * B_CH_BYTES, B_CH_BYTES, m);
        }
    }

    float c[4][8][4];
#pragma unroll
    for (int mt = 0; mt < 4; mt++)
#pragma unroll
        for (int nt = 0; nt < 8; nt++)
#pragma unroll
            for (int e = 0; e < 4; e++) c[mt][nt][e] = 0.f;

    const int wm0 = (wid >> 2) * 64, wn0 = (wid & 3) * 64;
    const int l7 = lane & 7;
    const uint32_t aAddr0 = (uint32_t)(wm0 + (lane & 15)) * 128;
    const uint32_t bAddr0 = A_CH_BYTES +
                            (uint32_t)(wn0 + ((lane >> 4) << 3) + l7) * 128;
    const int gA16 = lane >> 4, gB16 = (lane >> 3) & 1;

    gemm_mainloop(c, sbase, mb0, gA, gB, tid, aAddr0, bAddr0, gA16, gB16, l7);

    // epilogue: stage accum (+bias) in SMEM, then coalesced stores
    __syncthreads();
    float* so = (float*)sm;
    const int g = lane >> 2, tig = lane & 3;
#pragma unroll
    for (int mt = 0; mt < 4; mt++)
#pragma unroll
        for (int e2 = 0; e2 < 2; e2++) {
            int rl = wm0 + mt * 16 + g + e2 * 8;
#pragma unroll
            for (int nt = 0; nt < 8; nt++) {
                int cl = wn0 + nt * 8 + 2 * tig;
                float2 w;
                w.x = c[mt][nt][e2 * 2 + 0] + s_bias[cl];
                w.y = c[mt][nt][e2 * 2 + 1] + s_bias[cl + 1];
                *(float2*)(so + rl * OPITCH + cl) = w;
            }
        }
    __syncthreads();
#pragma unroll 1
    for (int rr = 0; rr < 16; rr++) {
        int rl = wid * 16 + rr;
        int row = bm * 128 + rl;
        float* orow = out + (size_t)row * Vn;
        const float* srow = so + rl * OPITCH;
#pragma unroll
        for (int j = 0; j < 8; j++) {
            int cl = lane + j * 32;
            int col = bn * 256 + cl;
            if (col < Vn) orow[col] = srow[cl];
        }
    }
}

// ---------------------------------------------------------------------------
extern "C" void kernel_launch(void* const* d_in, const int* in_sizes, int n_in,
                              void* d_out, int out_size) {
    (void)in_sizes; (void)n_in; (void)out_size;
    const int*   idx = (const int*)d_in[0];
    const float* tok = (const float*)d_in[1];
    const float* pos = (const float*)d_in[2];
    const float* Wq  = (const float*)d_in[3];
    const float* Wk  = (const float*)d_in[4];
    const float* Wv  = (const float*)d_in[5];
    const float* Wlm = (const float*)d_in[6];
    const float* blm = (const float*)d_in[7];
    float* out = (float*)d_out;

    cudaFuncSetAttribute(k_logits_b, cudaFuncAttributeMaxDynamicSharedMemorySize,
                         LOG_SMEM);
    cudaFuncSetAttribute(k_qkv_h, cudaFuncAttributeMaxDynamicSharedMemorySize,
                         LOG_SMEM);

    k_w2h<<<(Vn * 128 + 255) / 256, 256>>>(Wlm);
    k_wqkv<<<1536, 256>>>(Wq, Wk, Wv);
    k_embed<<<BTn, 256>>>(idx, tok, pos);
    k_qkv_h<<<dim3(16, 12), 256, LOG_SMEM>>>();
    k_scores<<<dim3(36, 1, NBH), 256>>>();
    k_softmax<<<NBH * Tn, 256>>>();
    k_pv<<<dim3(8, 1, NBH), 256>>>();
    k_logits_b<<<dim3(16, NBN), 256, LOG_SMEM>>>(blm, out);
}

// round 9
// speedup vs baseline: 4.8547x; 1.2510x over previous
#include <cuda_runtime.h>
#include <cuda_fp16.h>
#include <cstdint>

// Problem constants
#define Bsz  2
#define Tn   1024
#define Cn   1024
#define Hn   16
#define HDn  64
#define Vn   50257
#define BTn  2048
#define NBH  32          // B*H
#define NBN  197         // ceil(Vn/256)

// Chunked, pre-swizzled fp16 operands.
// A-chunks: [.. ][kc][row:128][64 halves], B-chunks: [..][kc][row:256][64 halves]
__device__ __align__(128) __half g_xh[BTn * Cn];                 // embed out (A of QKV)
__device__ __align__(128) __half g_wqkvh[3 * 4 * 16 * 256 * 64]; // Wq/Wk/Wv (B of QKV)
__device__ __align__(128) __half g_qh[NBH * 8 * 128 * 64];       // Q [bh][sb][r][d]
__device__ __align__(128) __half g_kh[NBH * 8 * 128 * 64];       // K [bh][sb][r][d]
__device__ __align__(128) __half g_vt[NBH * 16 * 64 * 64];       // V^T [bh][skc][d][s]
__device__ __align__(128) __half g_ah[BTn * Cn];                 // attn out (A of logits)
__device__ __align__(128) __half g_wh[(size_t)NBN * 16 * 256 * 64]; // W_lm (B of logits)

// ===========================================================================
// helpers (sm_80/sm_90 baseline ISA)
// ===========================================================================
__device__ __forceinline__ uint32_t smem_u32(const void* p) {
    return (uint32_t)__cvta_generic_to_shared(p);
}
__device__ __forceinline__ void mma16(float* c, const unsigned* a, const unsigned* b) {
    asm volatile(
        "mma.sync.aligned.m16n8k16.row.col.f32.f16.f16.f32 "
        "{%0,%1,%2,%3},{%4,%5,%6,%7},{%8,%9},{%0,%1,%2,%3};"
        : "+f"(c[0]), "+f"(c[1]), "+f"(c[2]), "+f"(c[3])
        : "r"(a[0]), "r"(a[1]), "r"(a[2]), "r"(a[3]), "r"(b[0]), "r"(b[1]));
}
__device__ __forceinline__ void ldsm4(unsigned& r0, unsigned& r1, unsigned& r2,
                                      unsigned& r3, uint32_t addr) {
    asm volatile("ldmatrix.sync.aligned.m8n8.x4.shared.b16 {%0,%1,%2,%3}, [%4];"
                 : "=r"(r0), "=r"(r1), "=r"(r2), "=r"(r3) : "r"(addr));
}
__device__ __forceinline__ void bulk_g2s(uint32_t dst, const void* src, int bytes,
                                         uint32_t mbar) {
    asm volatile(
        "cp.async.bulk.shared::cluster.global.mbarrier::complete_tx::bytes "
        "[%0], [%1], %2, [%3];"
        :: "r"(dst), "l"(src), "r"(bytes), "r"(mbar) : "memory");
}
#define MBAR_INIT(mbar, cnt) \
    asm volatile("mbarrier.init.shared.b64 [%0], %1;" \
                 :: "r"((uint32_t)(mbar)), "r"((uint32_t)(cnt)) : "memory")
#define MBAR_EXPECT(mbar, tx) \
    asm volatile("mbarrier.arrive.expect_tx.shared.b64 _, [%0], %1;" \
                 :: "r"((uint32_t)(mbar)), "r"((uint32_t)(tx)) : "memory")
#define MBAR_WAIT(mbar, parity) do {                                          \
    uint32_t _m = (uint32_t)(mbar);                                           \
    uint32_t _p = (uint32_t)(parity);                                         \
    asm volatile(                                                             \
        "{\n\t.reg .pred P1;\n\t"                                             \
        "WAIT_LOOP_%=:\n\t"                                                   \
        "mbarrier.try_wait.parity.acquire.cta.shared::cta.b64 P1, [%0], %1, 0x989680;\n\t" \
        "@P1 bra.uni WAIT_DONE_%=;\n\t"                                       \
        "bra.uni WAIT_LOOP_%=;\n\t"                                           \
        "WAIT_DONE_%=:\n\t}"                                                  \
        :: "r"(_m), "r"(_p) : "memory");                                      \
} while (0)

__device__ __forceinline__ unsigned packh2(float x, float y) {
    __half2 h = __floats2half2_rn(x, y);
    return *(unsigned*)&h;
}

// ---------------------------------------------------------------------------
// 1) Embedding -> fp16 chunked+swizzled A layout (g_xh)
__global__ __launch_bounds__(256) void k_embed(const int* __restrict__ idx,
                                               const float* __restrict__ tok,
                                               const float* __restrict__ pos) {
    int i = blockIdx.x;                   // bt row
    int t = i & (Tn - 1);
    int token = idx[i];
    const float4* te = (const float4*)(tok + (size_t)token * Cn);
    const float4* pe = (const float4*)(pos + (size_t)t * Cn);
    int tid = threadIdx.x;
    float4 a = te[tid], b = pe[tid];
    uint2 o;
    o.x = packh2(a.x + b.x, a.y + b.y);
    o.y = packh2(a.z + b.z, a.w + b.w);
    int r = i & 127, bm = i >> 7;
    int kc = tid >> 4;                    // k = tid*4; kc = k>>6
    int c16 = (tid >> 1) & 7;
    int hsel = tid & 1;
    size_t base = ((size_t)(bm * 16 + kc)) * 16384;
    uint32_t off = (uint32_t)r * 128 + ((unsigned)(c16 ^ (r & 7)) << 4) + hsel * 8;
    *(uint2*)((char*)g_xh + base + off) = o;
}

// ---------------------------------------------------------------------------
// 1b) W_lm -> fp16, tile-chunked + SW128-swizzled B layout.
__global__ __launch_bounds__(256) void k_w2h(const float* __restrict__ W) {
    int gid = blockIdx.x * 256 + threadIdx.x;     // one 8-half granule each
    if (gid >= Vn * 128) return;
    int v = gid >> 7, g8 = gid & 127;             // kk = g8*8
    const float4* s = (const float4*)(W + (size_t)v * Cn + g8 * 8);
    float4 x = s[0], y = s[1];
    uint4 o;
    o.x = packh2(x.x, x.y); o.y = packh2(x.z, x.w);
    o.z = packh2(y.x, y.y); o.w = packh2(y.z, y.w);
    int bn = v >> 8, r = v & 255;
    int kc = g8 >> 3, c16 = g8 & 7;
    size_t chunkB = (((size_t)bn * 16 + kc) * (256 * 64)) * 2;
    uint32_t off = (uint32_t)r * 128 + ((unsigned)(c16 ^ (r & 7)) << 4);
    *(uint4*)((char*)g_wh + chunkB + off) = o;
}

// ---------------------------------------------------------------------------
// 1c) Wq/Wk/Wv -> transposed fp16 chunked B layout (n=(h,d) rows, k=c).
__global__ __launch_bounds__(256) void k_wqkv(const float* __restrict__ Wq,
                                              const float* __restrict__ Wk,
                                              const float* __restrict__ Wv) {
    int u = blockIdx.x * 4 + (threadIdx.x >> 6);   // 0..6143
    int d = threadIdx.x & 63;
    int mat = u >> 11;
    int rem = u & 2047;
    int h = rem >> 7;
    int kc = (rem >> 3) & 15;
    int c16 = rem & 7;
    const float* W = (mat == 0) ? Wq : (mat == 1) ? Wk : Wv;
    const float* Wb = W + (size_t)h * (Cn * HDn) + d;
    float vals[8];
#pragma unroll
    for (int j = 0; j < 8; j++) {
        int c = kc * 64 + c16 * 8 + j;
        vals[j] = Wb[(size_t)c * HDn];
    }
    uint4 o;
    o.x = packh2(vals[0], vals[1]); o.y = packh2(vals[2], vals[3]);
    o.z = packh2(vals[4], vals[5]); o.w = packh2(vals[6], vals[7]);
    int bnAll = mat * 4 + (h >> 2);
    int r = (h & 3) * 64 + d;
    size_t chunkB = (((size_t)bnAll * 16 + kc) * (256 * 64)) * 2;
    uint32_t off = (uint32_t)r * 128 + ((unsigned)(c16 ^ (r & 7)) << 4);
    *(uint4*)((char*)g_wqkvh + chunkB + off) = o;
}

// ===========================================================================
// Shared fp16 bulk-pipeline GEMM pieces
// ===========================================================================
#define LKCH 16                          // K chunks of 64
#define A_CH_BYTES (128 * 128)           // 16KB
#define B_CH_BYTES (256 * 128)           // 32KB
#define LSTG_BYTES (A_CH_BYTES + B_CH_BYTES)   // 49152
#define LOG_SMEM (3 * LSTG_BYTES)        // 147456
#define OPITCH 264                       // f32 pitch for epilogue staging

struct Frags { unsigned a[4][4]; unsigned b[8][2]; };

__device__ __forceinline__ void load_frags(Frags& f, uint32_t sb, int kt,
                                           uint32_t aAddr0, uint32_t bAddr0,
                                           int gA16, int gB16, int l7) {
    const uint32_t xA = ((uint32_t)((kt * 2 + gA16) ^ l7)) << 4;
    const uint32_t xB = ((uint32_t)((kt * 2 + gB16) ^ l7)) << 4;
#pragma unroll
    for (int mt = 0; mt < 4; mt++)
        ldsm4(f.a[mt][0], f.a[mt][1], f.a[mt][2], f.a[mt][3],
              sb + aAddr0 + mt * (16 * 128) + xA);
#pragma unroll
    for (int np = 0; np < 4; np++)
        ldsm4(f.b[2 * np][0], f.b[2 * np][1], f.b[2 * np + 1][0], f.b[2 * np + 1][1],
              sb + bAddr0 + np * (16 * 128) + xB);
}

__device__ __forceinline__ void gemm_mainloop(float (&c)[4][8][4], uint32_t sbase,
                                              uint32_t mb0, const char* gA,
                                              const char* gB, int tid,
                                              uint32_t aAddr0, uint32_t bAddr0,
                                              int gA16, int gB16, int l7) {
    Frags fr[2];
    MBAR_WAIT(mb0, 0);
    load_frags(fr[0], sbase, 0, aAddr0, bAddr0, gA16, gB16, l7);

    for (int kc = 0; kc < LKCH; kc++) {
        const uint32_t sb = sbase + (kc % 3) * LSTG_BYTES;
#pragma unroll
        for (int kt = 0; kt < 4; kt++) {
            const int cur = kt & 1;
            if (kt < 3)
                load_frags(fr[cur ^ 1], sb, kt + 1, aAddr0, bAddr0, gA16, gB16, l7);
#pragma unroll
            for (int mt = 0; mt < 4; mt++)
#pragma unroll
                for (int nt = 0; nt < 8; nt++) mma16(c[mt][nt], fr[cur].a[mt], fr[cur].b[nt]);
        }
        __syncthreads();
        if (tid == 0 && kc + 3 < LKCH) {
            int s = kc % 3;
            uint32_t m = mb0 + s * 8;
            uint32_t dst = sbase + s * LSTG_BYTES;
            MBAR_EXPECT(m, LSTG_BYTES);
            bulk_g2s(dst, gA + (size_t)(kc + 3) * A_CH_BYTES, A_CH_BYTES, m);
            bulk_g2s(dst + A_CH_BYTES, gB + (size_t)(kc + 3) * B_CH_BYTES, B_CH_BYTES, m);
        }
        if (kc + 1 < LKCH) {
            MBAR_WAIT(mb0 + ((kc + 1) % 3) * 8, ((kc + 1) / 3) & 1);
            load_frags(fr[0], sbase + ((kc + 1) % 3) * LSTG_BYTES, 0,
                       aAddr0, bAddr0, gA16, gB16, l7);
        }
    }
}

// ---------------------------------------------------------------------------
// 2) QKV via fp16 bulk pipeline. grid (16, 12): bn 0-3 -> q, 4-7 -> k, 8-11 -> v.
//    Epilogue emits fp16 Q/K (row=s chunks) and V^T (row=d chunks).
__global__ __launch_bounds__(256, 1) void k_qkv_h() {
    extern __shared__ __align__(128) char sm[];
    __shared__ __align__(8) unsigned long long s_mb[3];
    const int tid = threadIdx.x, lane = tid & 31, wid = tid >> 5;
    const int bm = blockIdx.x, bnAll = blockIdx.y;
    const uint32_t sbase = smem_u32(sm);
    const uint32_t mb0 = smem_u32(&s_mb[0]);

    if (tid == 0) {
        MBAR_INIT(mb0, 1);
        MBAR_INIT(mb0 + 8, 1);
        MBAR_INIT(mb0 + 16, 1);
    }
    __syncthreads();

    const char* gA = (const char*)g_xh + ((size_t)bm * LKCH) * A_CH_BYTES;
    const char* gB = (const char*)g_wqkvh + ((size_t)bnAll * LKCH) * B_CH_BYTES;

    if (tid == 0) {
#pragma unroll
        for (int s = 0; s < 3; s++) {
            uint32_t m = mb0 + s * 8;
            uint32_t dst = sbase + s * LSTG_BYTES;
            MBAR_EXPECT(m, LSTG_BYTES);
            bulk_g2s(dst, gA + (size_t)s * A_CH_BYTES, A_CH_BYTES, m);
            bulk_g2s(dst + A_CH_BYTES, gB + (size_t)s * B_CH_BYTES, B_CH_BYTES, m);
        }
    }

    float c[4][8][4];
#pragma unroll
    for (int mt = 0; mt < 4; mt++)
#pragma unroll
        for (int nt = 0; nt < 8; nt++)
#pragma unroll
            for (int e = 0; e < 4; e++) c[mt][nt][e] = 0.f;

    const int wm0 = (wid >> 2) * 64, wn0 = (wid & 3) * 64;
    const int l7 = lane & 7;
    const uint32_t aAddr0 = (uint32_t)(wm0 + (lane & 15)) * 128;
    const uint32_t bAddr0 = A_CH_BYTES +
                            (uint32_t)(wn0 + ((lane >> 4) << 3) + l7) * 128;
    const int gA16 = lane >> 4, gB16 = (lane >> 3) & 1;

    gemm_mainloop(c, sbase, mb0, gA, gB, tid, aAddr0, bAddr0, gA16, gB16, l7);

    // stage (scaled) accum to SMEM f32
    const int mat = bnAll >> 2;
    const float sc = (mat == 0) ? 0.03125f : 1.0f;
    __syncthreads();
    float* so = (float*)sm;
    const int g = lane >> 2, tig = lane & 3;
#pragma unroll
    for (int mt = 0; mt < 4; mt++)
#pragma unroll
        for (int e2 = 0; e2 < 2; e2++) {
            int rl = wm0 + mt * 16 + g + e2 * 8;
#pragma unroll
            for (int nt = 0; nt < 8; nt++) {
                int cl = wn0 + nt * 8 + 2 * tig;
                float2 w;
                w.x = c[mt][nt][e2 * 2 + 0] * sc;
                w.y = c[mt][nt][e2 * 2 + 1] * sc;
                *(float2*)(so + rl * OPITCH + cl) = w;
            }
        }
    __syncthreads();

    const int b = bm >> 3;            // batch of this 128-row tile
    if (mat < 2) {
        // Q/K: [bh][sb][r:128][64] chunks; warp handles rows wid*16..+15
        __half* dst = (mat == 0) ? g_qh : g_kh;
        const int seg = lane >> 3, g8 = lane & 7;
        const int h = (bnAll & 3) * 4 + seg;
        const int sb = bm & 7;
#pragma unroll 1
        for (int rr = 0; rr < 16; rr++) {
            int rl = wid * 16 + rr;
            const float* srow = so + rl * OPITCH + seg * 64 + g8 * 8;
            uint4 o;
            o.x = packh2(srow[0], srow[1]); o.y = packh2(srow[2], srow[3]);
            o.z = packh2(srow[4], srow[5]); o.w = packh2(srow[6], srow[7]);
            size_t chunk = ((size_t)((b * 16 + h) * 8 + sb)) * 16384;
            uint32_t off = (uint32_t)rl * 128 + ((unsigned)(g8 ^ (rl & 7)) << 4);
            *(uint4*)((char*)dst + chunk + off) = o;
        }
    } else {
        // V^T: [bh][skc:16][d:64][64 s] chunks of 8KB
#pragma unroll 1
        for (int it = 0; it < 16; it++) {
            int u = tid * 16 + it;
            int seg = u >> 10;
            int d = (u >> 4) & 63;
            int sg = u & 15;              // s granule of 8 within 128 rows
            const float* scol = so + (sg * 8) * OPITCH + seg * 64 + d;
            uint4 o;
            o.x = packh2(scol[0], scol[OPITCH]);
            o.y = packh2(scol[2 * OPITCH], scol[3 * OPITCH]);
            o.z = packh2(scol[4 * OPITCH], scol[5 * OPITCH]);
            o.w = packh2(scol[6 * OPITCH], scol[7 * OPITCH]);
            int h = (bnAll & 3) * 4 + seg;
            int skc = (bm & 7) * 2 + (sg >> 3);
            size_t chunk = ((size_t)((b * 16 + h) * 16 + skc)) * 8192;
            uint32_t off = (uint32_t)d * 128 + ((unsigned)((sg & 7) ^ (d & 7)) << 4);
            *(uint4*)((char*)g_vt + chunk + off) = o;
        }
    }
}

// ---------------------------------------------------------------------------
// 3) Fused flash attention: S=QK^T, online softmax, O=PV. One CTA per (bh, bm).
//    8 warps x m16 rows; kv blocks of 128; double-buffered bulk K/V staging.
#define FQ_BYTES 16384
#define FKV_BYTES 32768                  // K 16KB + V^T 16KB
#define FLASH_SMEM (FQ_BYTES + 2 * FKV_BYTES)   // 81920

__global__ __launch_bounds__(256, 1) void k_flash() {
    extern __shared__ __align__(128) char sm[];
    __shared__ __align__(8) unsigned long long s_mb[3];   // Q, stage0, stage1
    const int tid = threadIdx.x, lane = tid & 31, wid = tid >> 5;
    const int bm = 7 - (blockIdx.x & 7);      // heavy tiles first
    const int bh = blockIdx.x >> 3;
    const uint32_t sbase = smem_u32(sm);
    const uint32_t mbQ = smem_u32(&s_mb[0]);

    const char* gQ = (const char*)g_qh + ((size_t)bh * 8 + bm) * 16384;
    const char* gK = (const char*)g_kh + ((size_t)bh * 8) * 16384;
    const char* gV = (const char*)g_vt + ((size_t)bh * 16) * 8192;

    if (tid == 0) {
        MBAR_INIT(mbQ, 1);
        MBAR_INIT(mbQ + 8, 1);
        MBAR_INIT(mbQ + 16, 1);
    }
    __syncthreads();
    if (tid == 0) {
        MBAR_EXPECT(mbQ, FQ_BYTES);
        bulk_g2s(sbase, gQ, FQ_BYTES, mbQ);
        MBAR_EXPECT(mbQ + 8, FKV_BYTES);
        bulk_g2s(sbase + FQ_BYTES, gK, 16384, mbQ + 8);
        bulk_g2s(sbase + FQ_BYTES + 16384, gV, 16384, mbQ + 8);
        if (bm >= 1) {
            MBAR_EXPECT(mbQ + 16, FKV_BYTES);
            bulk_g2s(sbase + FQ_BYTES + FKV_BYTES, gK + 16384, 16384, mbQ + 16);
            bulk_g2s(sbase + FQ_BYTES + FKV_BYTES + 16384, gV + 16384, 16384, mbQ + 16);
        }
    }

    const int wm = wid * 16;
    const int l7 = lane & 7;
    const int g = lane >> 2, tig = lane & 3;
    const uint32_t aAddr0 = (uint32_t)(wm + (lane & 15)) * 128;
    const uint32_t rowBB = (uint32_t)(((lane >> 4) << 3) + l7) * 128;
    const int gA16 = lane >> 4, gB16 = (lane >> 3) & 1;

    float m0 = -1e30f, m1 = -1e30f, l0 = 0.f, l1 = 0.f;
    float o[8][4];
#pragma unroll
    for (int nt = 0; nt < 8; nt++)
#pragma unroll
        for (int e = 0; e < 4; e++) o[nt][e] = 0.f;

    unsigned aq[4][4];
    MBAR_WAIT(mbQ, 0);
#pragma unroll
    for (int kt = 0; kt < 4; kt++) {
        uint32_t xA = ((uint32_t)((kt * 2 + gA16) ^ l7)) << 4;
        ldsm4(aq[kt][0], aq[kt][1], aq[kt][2], aq[kt][3], sbase + aAddr0 + xA);
    }

    for (int j = 0; j <= bm; j++) {
        const uint32_t stg = sbase + FQ_BYTES + (j & 1) * FKV_BYTES;
        MBAR_WAIT(mbQ + 8 + (j & 1) * 8, (j >> 1) & 1);

        float s[16][4];
#pragma unroll
        for (int nt = 0; nt < 16; nt++)
#pragma unroll
            for (int e = 0; e < 4; e++) s[nt][e] = 0.f;

#pragma unroll
        for (int kt = 0; kt < 4; kt++) {
            uint32_t xB = ((uint32_t)((kt * 2 + gB16) ^ l7)) << 4;
            unsigned bk[16][2];
#pragma unroll
            for (int np = 0; np < 8; np++)
                ldsm4(bk[2 * np][0], bk[2 * np][1], bk[2 * np + 1][0], bk[2 * np + 1][1],
                      stg + rowBB + np * (16 * 128) + xB);
#pragma unroll
            for (int nt = 0; nt < 16; nt++) mma16(s[nt], aq[kt], bk[nt]);
        }

        if (j == bm) {   // causal mask within diagonal block
#pragma unroll
            for (int nt = 0; nt < 16; nt++) {
                int col = nt * 8 + 2 * tig;
                int r0 = wm + g, r1 = wm + g + 8;
                if (col > r0)     s[nt][0] = -1e30f;
                if (col + 1 > r0) s[nt][1] = -1e30f;
                if (col > r1)     s[nt][2] = -1e30f;
                if (col + 1 > r1) s[nt][3] = -1e30f;
            }
        }

        // online softmax
        float v0 = -1e30f, v1 = -1e30f;
#pragma unroll
        for (int nt = 0; nt < 16; nt++) {
            v0 = fmaxf(v0, fmaxf(s[nt][0], s[nt][1]));
            v1 = fmaxf(v1, fmaxf(s[nt][2], s[nt][3]));
        }
#pragma unroll
        for (int off = 1; off <= 2; off <<= 1) {
            v0 = fmaxf(v0, __shfl_xor_sync(0xffffffffu, v0, off));
            v1 = fmaxf(v1, __shfl_xor_sync(0xffffffffu, v1, off));
        }
        float mn0 = fmaxf(m0, v0), mn1 = fmaxf(m1, v1);
        float sc0 = __expf(m0 - mn0), sc1 = __expf(m1 - mn1);
        float sum0 = 0.f, sum1 = 0.f;
#pragma unroll
        for (int nt = 0; nt < 16; nt++) {
            s[nt][0] = __expf(s[nt][0] - mn0);
            s[nt][1] = __expf(s[nt][1] - mn0);
            s[nt][2] = __expf(s[nt][2] - mn1);
            s[nt][3] = __expf(s[nt][3] - mn1);
            sum0 += s[nt][0] + s[nt][1];
            sum1 += s[nt][2] + s[nt][3];
        }
#pragma unroll
        for (int off = 1; off <= 2; off <<= 1) {
            sum0 += __shfl_xor_sync(0xffffffffu, sum0, off);
            sum1 += __shfl_xor_sync(0xffffffffu, sum1, off);
        }
        l0 = l0 * sc0 + sum0; l1 = l1 * sc1 + sum1;
        m0 = mn0; m1 = mn1;
#pragma unroll
        for (int nt = 0; nt < 8; nt++) {
            o[nt][0] *= sc0; o[nt][1] *= sc0;
            o[nt][2] *= sc1; o[nt][3] *= sc1;
        }

        // pack P as A-fragments
        unsigned pa[8][4];
#pragma unroll
        for (int kt = 0; kt < 8; kt++) {
            pa[kt][0] = packh2(s[2 * kt][0], s[2 * kt][1]);
            pa[kt][1] = packh2(s[2 * kt][2], s[2 * kt][3]);
            pa[kt][2] = packh2(s[2 * kt + 1][0], s[2 * kt + 1][1]);
            pa[kt][3] = packh2(s[2 * kt + 1][2], s[2 * kt + 1][3]);
        }

        // PV: V^T tiles (n=d 64, k=s 128 in two 64-k chunks)
#pragma unroll
        for (int kt = 0; kt < 8; kt++) {
            const uint32_t vb = stg + 16384 + (kt >> 2) * 8192;
            const int kt2 = kt & 3;
            uint32_t xV = ((uint32_t)((kt2 * 2 + gB16) ^ l7)) << 4;
            unsigned bv[8][2];
#pragma unroll
            for (int np = 0; np < 4; np++)
                ldsm4(bv[2 * np][0], bv[2 * np][1], bv[2 * np + 1][0], bv[2 * np + 1][1],
                      vb + rowBB + np * (16 * 128) + xV);
#pragma unroll
            for (int nt = 0; nt < 8; nt++) mma16(o[nt], pa[kt], bv[nt]);
        }

        __syncthreads();
        if (tid == 0 && j + 2 <= bm) {
            int st = j & 1;
            uint32_t m = mbQ + 8 + st * 8;
            uint32_t dst = sbase + FQ_BYTES + st * FKV_BYTES;
            MBAR_EXPECT(m, FKV_BYTES);
            bulk_g2s(dst, gK + (size_t)(j + 2) * 16384, 16384, m);
            bulk_g2s(dst + 16384, gV + (size_t)(j + 2) * 16384, 16384, m);
        }
    }

    // finalize + write fp16 to g_ah chunk [bma][kc=h][r][d]
    const float inv0 = 1.0f / l0, inv1 = 1.0f / l1;
    const int b = bh >> 4, h = bh & 15;
    const size_t chunkB = ((size_t)((b * 8 + bm) * 16 + h)) * 16384;
#pragma unroll
    for (int nt = 0; nt < 8; nt++)
#pragma unroll
        for (int e = 0; e < 4; e++) {
            int rl = wm + g + ((e >= 2) ? 8 : 0);
            int d = nt * 8 + 2 * tig + (e & 1);
            float val = o[nt][e] * ((e >= 2) ? inv1 : inv0);
            uint32_t off = (uint32_t)rl * 128 +
                           ((unsigned)(((d >> 3) ^ (rl & 7))) << 4) + (d & 7) * 2;
            *(__half*)((char*)g_ah + chunkB + off) = __float2half_rn(val);
        }
}

// ---------------------------------------------------------------------------
// 4) LM head: fp16 bulk pipeline (unchanged from R8 winner)
__global__ __launch_bounds__(256, 1) void k_logits_b(const float* __restrict__ blm,
                                                     float* __restrict__ out) {
    extern __shared__ __align__(128) char sm[];
    __shared__ float s_bias[256];
    __shared__ __align__(8) unsigned long long s_mb[3];
    const int tid = threadIdx.x, lane = tid & 31, wid = tid >> 5;
    const int bm = blockIdx.x, bn = blockIdx.y;
    const uint32_t sbase = smem_u32(sm);
    const uint32_t mb0 = smem_u32(&s_mb[0]);

    {
        int gc = bn * 256 + tid;
        s_bias[tid] = (gc < Vn) ? blm[gc] : 0.f;
    }
    if (tid == 0) {
        MBAR_INIT(mb0, 1);
        MBAR_INIT(mb0 + 8, 1);
        MBAR_INIT(mb0 + 16, 1);
    }
    __syncthreads();

    const char* gA = (const char*)g_ah + ((size_t)bm * LKCH) * A_CH_BYTES;
    const char* gB = (const char*)g_wh + ((size_t)bn * LKCH) * B_CH_BYTES;

    if (tid == 0) {
#pragma unroll
        for (int s = 0; s < 3; s++) {
            uint32_t m = mb0 + s * 8;
            uint32_t dst = sbase + s * LSTG_BYTES;
            MBAR_EXPECT(m, LSTG_BYTES);
            bulk_g2s(dst, gA + (size_t)s * A_CH_BYTES, A_CH_BYTES, m);
            bulk_g2s(dst + A_CH_BYTES, gB + (size_t)s * B_CH_BYTES, B_CH_BYTES, m);
        }
    }

    float c[4][8][4];
#pragma unroll
    for (int mt = 0; mt < 4; mt++)
#pragma unroll
        for (int nt = 0; nt < 8; nt++)
#pragma unroll
            for (int e = 0; e < 4; e++) c[mt][nt][e] = 0.f;

    const int wm0 = (wid >> 2) * 64, wn0 = (wid & 3) * 64;
    const int l7 = lane & 7;
    const uint32_t aAddr0 = (uint32_t)(wm0 + (lane & 15)) * 128;
    const uint32_t bAddr0 = A_CH_BYTES +
                            (uint32_t)(wn0 + ((lane >> 4) << 3) + l7) * 128;
    const int gA16 = lane >> 4, gB16 = (lane >> 3) & 1;

    gemm_mainloop(c, sbase, mb0, gA, gB, tid, aAddr0, bAddr0, gA16, gB16, l7);

    __syncthreads();
    float* so = (float*)sm;
    const int g = lane >> 2, tig = lane & 3;
#pragma unroll
    for (int mt = 0; mt < 4; mt++)
#pragma unroll
        for (int e2 = 0; e2 < 2; e2++) {
            int rl = wm0 + mt * 16 + g + e2 * 8;
#pragma unroll
            for (int nt = 0; nt < 8; nt++) {
                int cl = wn0 + nt * 8 + 2 * tig;
                float2 w;
                w.x = c[mt][nt][e2 * 2 + 0] + s_bias[cl];
                w.y = c[mt][nt][e2 * 2 + 1] + s_bias[cl + 1];
                *(float2*)(so + rl * OPITCH + cl) = w;
            }
        }
    __syncthreads();
#pragma unroll 1
    for (int rr = 0; rr < 16; rr++) {
        int rl = wid * 16 + rr;
        int row = bm * 128 + rl;
        float* orow = out + (size_t)row * Vn;
        const float* srow = so + rl * OPITCH;
#pragma unroll
        for (int j = 0; j < 8; j++) {
            int cl = lane + j * 32;
            int col = bn * 256 + cl;
            if (col < Vn) orow[col] = srow[cl];
        }
    }
}

// ---------------------------------------------------------------------------
extern "C" void kernel_launch(void* const* d_in, const int* in_sizes, int n_in,
                              void* d_out, int out_size) {
    (void)in_sizes; (void)n_in; (void)out_size;
    const int*   idx = (const int*)d_in[0];
    const float* tok = (const float*)d_in[1];
    const float* pos = (const float*)d_in[2];
    const float* Wq  = (const float*)d_in[3];
    const float* Wk  = (const float*)d_in[4];
    const float* Wv  = (const float*)d_in[5];
    const float* Wlm = (const float*)d_in[6];
    const float* blm = (const float*)d_in[7];
    float* out = (float*)d_out;

    cudaFuncSetAttribute(k_logits_b, cudaFuncAttributeMaxDynamicSharedMemorySize,
                         LOG_SMEM);
    cudaFuncSetAttribute(k_qkv_h, cudaFuncAttributeMaxDynamicSharedMemorySize,
                         LOG_SMEM);
    cudaFuncSetAttribute(k_flash, cudaFuncAttributeMaxDynamicSharedMemorySize,
                         FLASH_SMEM);

    k_w2h<<<(Vn * 128 + 255) / 256, 256>>>(Wlm);
    k_wqkv<<<1536, 256>>>(Wq, Wk, Wv);
    k_embed<<<BTn, 256>>>(idx, tok, pos);
    k_qkv_h<<<dim3(16, 12), 256, LOG_SMEM>>>();
    k_flash<<<256, 256, FLASH_SMEM>>>();
    k_logits_b<<<dim3(16, NBN), 256, LOG_SMEM>>>(blm, out);
}

// round 11
// speedup vs baseline: 4.9339x; 1.0163x over previous
#include <cuda_runtime.h>
#include <cuda_fp16.h>
#include <cstdint>

// Problem constants
#define Bsz  2
#define Tn   1024
#define Cn   1024
#define Hn   16
#define HDn  64
#define Vn   50257
#define BTn  2048
#define NBH  32          // B*H
#define NBN  197         // ceil(Vn/256)

// Chunked, pre-swizzled fp16 operands.
// A-chunks: [.. ][kc][row:128][64 halves], B-chunks: [..][kc][row:256][64 halves]
__device__ __align__(128) __half g_xh[BTn * Cn];                 // embed out (A of QKV)
__device__ __align__(128) __half g_wqkvh[3 * 4 * 16 * 256 * 64]; // Wq/Wk/Wv (B of QKV)
__device__ __align__(128) __half g_qh[NBH * 8 * 128 * 64];       // Q [bh][sb][r][d]
__device__ __align__(128) __half g_kh[NBH * 8 * 128 * 64];       // K [bh][sb][r][d]
__device__ __align__(128) __half g_vt[NBH * 16 * 64 * 64];       // V^T [bh][skc][d][s]
__device__ __align__(128) __half g_ah[BTn * Cn];                 // attn out (A of logits)
__device__ __align__(128) __half g_wh[(size_t)NBN * 16 * 256 * 64]; // W_lm (B of logits)

// ===========================================================================
// helpers (sm_80/sm_90 baseline ISA)
// ===========================================================================
__device__ __forceinline__ uint32_t smem_u32(const void* p) {
    return (uint32_t)__cvta_generic_to_shared(p);
}
__device__ __forceinline__ void mma16(float* c, const unsigned* a, const unsigned* b) {
    asm volatile(
        "mma.sync.aligned.m16n8k16.row.col.f32.f16.f16.f32 "
        "{%0,%1,%2,%3},{%4,%5,%6,%7},{%8,%9},{%0,%1,%2,%3};"
        : "+f"(c[0]), "+f"(c[1]), "+f"(c[2]), "+f"(c[3])
        : "r"(a[0]), "r"(a[1]), "r"(a[2]), "r"(a[3]), "r"(b[0]), "r"(b[1]));
}
__device__ __forceinline__ void ldsm4(unsigned& r0, unsigned& r1, unsigned& r2,
                                      unsigned& r3, uint32_t addr) {
    asm volatile("ldmatrix.sync.aligned.m8n8.x4.shared.b16 {%0,%1,%2,%3}, [%4];"
                 : "=r"(r0), "=r"(r1), "=r"(r2), "=r"(r3) : "r"(addr));
}
__device__ __forceinline__ void bulk_g2s(uint32_t dst, const void* src, int bytes,
                                         uint32_t mbar) {
    asm volatile(
        "cp.async.bulk.shared::cluster.global.mbarrier::complete_tx::bytes "
        "[%0], [%1], %2, [%3];"
        :: "r"(dst), "l"(src), "r"(bytes), "r"(mbar) : "memory");
}
#define MBAR_INIT(mbar, cnt) \
    asm volatile("mbarrier.init.shared.b64 [%0], %1;" \
                 :: "r"((uint32_t)(mbar)), "r"((uint32_t)(cnt)) : "memory")
#define MBAR_EXPECT(mbar, tx) \
    asm volatile("mbarrier.arrive.expect_tx.shared.b64 _, [%0], %1;" \
                 :: "r"((uint32_t)(mbar)), "r"((uint32_t)(tx)) : "memory")
#define MBAR_WAIT(mbar, parity) do {                                          \
    uint32_t _m = (uint32_t)(mbar);                                           \
    uint32_t _p = (uint32_t)(parity);                                         \
    asm volatile(                                                             \
        "{\n\t.reg .pred P1;\n\t"                                             \
        "WAIT_LOOP_%=:\n\t"                                                   \
        "mbarrier.try_wait.parity.acquire.cta.shared::cta.b64 P1, [%0], %1, 0x989680;\n\t" \
        "@P1 bra.uni WAIT_DONE_%=;\n\t"                                       \
        "bra.uni WAIT_LOOP_%=;\n\t"                                           \
        "WAIT_DONE_%=:\n\t}"                                                  \
        :: "r"(_m), "r"(_p) : "memory");                                      \
} while (0)

__device__ __forceinline__ unsigned packh2(float x, float y) {
    __half2 h = __floats2half2_rn(x, y);
    return *(unsigned*)&h;
}

// ---------------------------------------------------------------------------
// 1) Embedding -> fp16 chunked+swizzled A layout (g_xh)
__global__ __launch_bounds__(256) void k_embed(const int* __restrict__ idx,
                                               const float* __restrict__ tok,
                                               const float* __restrict__ pos) {
    int i = blockIdx.x;                   // bt row
    int t = i & (Tn - 1);
    int token = idx[i];
    const float4* te = (const float4*)(tok + (size_t)token * Cn);
    const float4* pe = (const float4*)(pos + (size_t)t * Cn);
    int tid = threadIdx.x;
    float4 a = te[tid], b = pe[tid];
    uint2 o;
    o.x = packh2(a.x + b.x, a.y + b.y);
    o.y = packh2(a.z + b.z, a.w + b.w);
    int r = i & 127, bm = i >> 7;
    int kc = tid >> 4;                    // k = tid*4; kc = k>>6
    int c16 = (tid >> 1) & 7;
    int hsel = tid & 1;
    size_t base = ((size_t)(bm * 16 + kc)) * 16384;
    uint32_t off = (uint32_t)r * 128 + ((unsigned)(c16 ^ (r & 7)) << 4) + hsel * 8;
    *(uint2*)((char*)g_xh + base + off) = o;
}

// ---------------------------------------------------------------------------
// 1b) W_lm -> fp16, tile-chunked + SW128-swizzled B layout.
__global__ __launch_bounds__(256) void k_w2h(const float* __restrict__ W) {
    int gid = blockIdx.x * 256 + threadIdx.x;     // one 8-half granule each
    if (gid >= Vn * 128) return;
    int v = gid >> 7, g8 = gid & 127;             // kk = g8*8
    const float4* s = (const float4*)(W + (size_t)v * Cn + g8 * 8);
    float4 x = s[0], y = s[1];
    uint4 o;
    o.x = packh2(x.x, x.y); o.y = packh2(x.z, x.w);
    o.z = packh2(y.x, y.y); o.w = packh2(y.z, y.w);
    int bn = v >> 8, r = v & 255;
    int kc = g8 >> 3, c16 = g8 & 7;
    size_t chunkB = (((size_t)bn * 16 + kc) * (256 * 64)) * 2;
    uint32_t off = (uint32_t)r * 128 + ((unsigned)(c16 ^ (r & 7)) << 4);
    *(uint4*)((char*)g_wh + chunkB + off) = o;
}

// ---------------------------------------------------------------------------
// 1c) Wq/Wk/Wv -> transposed fp16 chunked B layout (n=(h,d) rows, k=c).
__global__ __launch_bounds__(256) void k_wqkv(const float* __restrict__ Wq,
                                              const float* __restrict__ Wk,
                                              const float* __restrict__ Wv) {
    int u = blockIdx.x * 4 + (threadIdx.x >> 6);   // 0..6143
    int d = threadIdx.x & 63;
    int mat = u >> 11;
    int rem = u & 2047;
    int h = rem >> 7;
    int kc = (rem >> 3) & 15;
    int c16 = rem & 7;
    const float* W = (mat == 0) ? Wq : (mat == 1) ? Wk : Wv;
    const float* Wb = W + (size_t)h * (Cn * HDn) + d;
    float vals[8];
#pragma unroll
    for (int j = 0; j < 8; j++) {
        int c = kc * 64 + c16 * 8 + j;
        vals[j] = Wb[(size_t)c * HDn];
    }
    uint4 o;
    o.x = packh2(vals[0], vals[1]); o.y = packh2(vals[2], vals[3]);
    o.z = packh2(vals[4], vals[5]); o.w = packh2(vals[6], vals[7]);
    int bnAll = mat * 4 + (h >> 2);
    int r = (h & 3) * 64 + d;
    size_t chunkB = (((size_t)bnAll * 16 + kc) * (256 * 64)) * 2;
    uint32_t off = (uint32_t)r * 128 + ((unsigned)(c16 ^ (r & 7)) << 4);
    *(uint4*)((char*)g_wqkvh + chunkB + off) = o;
}

// ===========================================================================
// Shared fp16 bulk-pipeline GEMM pieces
// ===========================================================================
#define LKCH 16                          // K chunks of 64
#define A_CH_BYTES (128 * 128)           // 16KB
#define B_CH_BYTES (256 * 128)           // 32KB
#define LSTG_BYTES (A_CH_BYTES + B_CH_BYTES)   // 49152
#define LOG_SMEM (3 * LSTG_BYTES)        // 147456
#define OPITCH 264                       // f32 pitch for epilogue staging

struct Frags { unsigned a[4][4]; unsigned b[8][2]; };

__device__ __forceinline__ void load_frags(Frags& f, uint32_t sb, int kt,
                                           uint32_t aAddr0, uint32_t bAddr0,
                                           int gA16, int gB16, int l7) {
    const uint32_t xA = ((uint32_t)((kt * 2 + gA16) ^ l7)) << 4;
    const uint32_t xB = ((uint32_t)((kt * 2 + gB16) ^ l7)) << 4;
#pragma unroll
    for (int mt = 0; mt < 4; mt++)
        ldsm4(f.a[mt][0], f.a[mt][1], f.a[mt][2], f.a[mt][3],
              sb + aAddr0 + mt * (16 * 128) + xA);
#pragma unroll
    for (int np = 0; np < 4; np++)
        ldsm4(f.b[2 * np][0], f.b[2 * np][1], f.b[2 * np + 1][0], f.b[2 * np + 1][1],
              sb + bAddr0 + np * (16 * 128) + xB);
}

__device__ __forceinline__ void gemm_mainloop(float (&c)[4][8][4], uint32_t sbase,
                                              uint32_t mb0, const char* gA,
                                              const char* gB, int tid,
                                              uint32_t aAddr0, uint32_t bAddr0,
                                              int gA16, int gB16, int l7) {
    Frags fr[2];
    MBAR_WAIT(mb0, 0);
    load_frags(fr[0], sbase, 0, aAddr0, bAddr0, gA16, gB16, l7);

    for (int kc = 0; kc < LKCH; kc++) {
        const uint32_t sb = sbase + (kc % 3) * LSTG_BYTES;
#pragma unroll
        for (int kt = 0; kt < 4; kt++) {
            const int cur = kt & 1;
            if (kt < 3)
                load_frags(fr[cur ^ 1], sb, kt + 1, aAddr0, bAddr0, gA16, gB16, l7);
#pragma unroll
            for (int mt = 0; mt < 4; mt++)
#pragma unroll
                for (int nt = 0; nt < 8; nt++) mma16(c[mt][nt], fr[cur].a[mt], fr[cur].b[nt]);
        }
        __syncthreads();
        if (tid == 0 && kc + 3 < LKCH) {
            int s = kc % 3;
            uint32_t m = mb0 + s * 8;
            uint32_t dst = sbase + s * LSTG_BYTES;
            MBAR_EXPECT(m, LSTG_BYTES);
            bulk_g2s(dst, gA + (size_t)(kc + 3) * A_CH_BYTES, A_CH_BYTES, m);
            bulk_g2s(dst + A_CH_BYTES, gB + (size_t)(kc + 3) * B_CH_BYTES, B_CH_BYTES, m);
        }
        if (kc + 1 < LKCH) {
            MBAR_WAIT(mb0 + ((kc + 1) % 3) * 8, ((kc + 1) / 3) & 1);
            load_frags(fr[0], sbase + ((kc + 1) % 3) * LSTG_BYTES, 0,
                       aAddr0, bAddr0, gA16, gB16, l7);
        }
    }
}

// ---------------------------------------------------------------------------
// 2) QKV via fp16 bulk pipeline. grid (16, 12): bn 0-3 -> q, 4-7 -> k, 8-11 -> v.
//    Epilogue emits fp16 Q/K (row=s chunks) and V^T (row=d chunks).
__global__ __launch_bounds__(256, 1) void k_qkv_h() {
    extern __shared__ __align__(128) char sm[];
    __shared__ __align__(8) unsigned long long s_mb[3];
    const int tid = threadIdx.x, lane = tid & 31, wid = tid >> 5;
    const int bm = blockIdx.x, bnAll = blockIdx.y;
    const uint32_t sbase = smem_u32(sm);
    const uint32_t mb0 = smem_u32(&s_mb[0]);

    if (tid == 0) {
        MBAR_INIT(mb0, 1);
        MBAR_INIT(mb0 + 8, 1);
        MBAR_INIT(mb0 + 16, 1);
    }
    __syncthreads();

    const char* gA = (const char*)g_xh + ((size_t)bm * LKCH) * A_CH_BYTES;
    const char* gB = (const char*)g_wqkvh + ((size_t)bnAll * LKCH) * B_CH_BYTES;

    if (tid == 0) {
#pragma unroll
        for (int s = 0; s < 3; s++) {
            uint32_t m = mb0 + s * 8;
            uint32_t dst = sbase + s * LSTG_BYTES;
            MBAR_EXPECT(m, LSTG_BYTES);
            bulk_g2s(dst, gA + (size_t)s * A_CH_BYTES, A_CH_BYTES, m);
            bulk_g2s(dst + A_CH_BYTES, gB + (size_t)s * B_CH_BYTES, B_CH_BYTES, m);
        }
    }

    float c[4][8][4];
#pragma unroll
    for (int mt = 0; mt < 4; mt++)
#pragma unroll
        for (int nt = 0; nt < 8; nt++)
#pragma unroll
            for (int e = 0; e < 4; e++) c[mt][nt][e] = 0.f;

    const int wm0 = (wid >> 2) * 64, wn0 = (wid & 3) * 64;
    const int l7 = lane & 7;
    const uint32_t aAddr0 = (uint32_t)(wm0 + (lane & 15)) * 128;
    const uint32_t bAddr0 = A_CH_BYTES +
                            (uint32_t)(wn0 + ((lane >> 4) << 3) + l7) * 128;
    const int gA16 = lane >> 4, gB16 = (lane >> 3) & 1;

    gemm_mainloop(c, sbase, mb0, gA, gB, tid, aAddr0, bAddr0, gA16, gB16, l7);

    // stage (scaled) accum to SMEM f32
    const int mat = bnAll >> 2;
    const float sc = (mat == 0) ? 0.03125f : 1.0f;
    __syncthreads();
    float* so = (float*)sm;
    const int g = lane >> 2, tig = lane & 3;
#pragma unroll
    for (int mt = 0; mt < 4; mt++)
#pragma unroll
        for (int e2 = 0; e2 < 2; e2++) {
            int rl = wm0 + mt * 16 + g + e2 * 8;
#pragma unroll
            for (int nt = 0; nt < 8; nt++) {
                int cl = wn0 + nt * 8 + 2 * tig;
                float2 w;
                w.x = c[mt][nt][e2 * 2 + 0] * sc;
                w.y = c[mt][nt][e2 * 2 + 1] * sc;
                *(float2*)(so + rl * OPITCH + cl) = w;
            }
        }
    __syncthreads();

    const int b = bm >> 3;            // batch of this 128-row tile
    if (mat < 2) {
        // Q/K: [bh][sb][r:128][64] chunks; warp handles rows wid*16..+15
        __half* dst = (mat == 0) ? g_qh : g_kh;
        const int seg = lane >> 3, g8 = lane & 7;
        const int h = (bnAll & 3) * 4 + seg;
        const int sb = bm & 7;
#pragma unroll 1
        for (int rr = 0; rr < 16; rr++) {
            int rl = wid * 16 + rr;
            const float* srow = so + rl * OPITCH + seg * 64 + g8 * 8;
            uint4 o;
            o.x = packh2(srow[0], srow[1]); o.y = packh2(srow[2], srow[3]);
            o.z = packh2(srow[4], srow[5]); o.w = packh2(srow[6], srow[7]);
            size_t chunk = ((size_t)((b * 16 + h) * 8 + sb)) * 16384;
            uint32_t off = (uint32_t)rl * 128 + ((unsigned)(g8 ^ (rl & 7)) << 4);
            *(uint4*)((char*)dst + chunk + off) = o;
        }
    } else {
        // V^T: [bh][skc:16][d:64][64 s] chunks of 8KB
#pragma unroll 1
        for (int it = 0; it < 16; it++) {
            int u = tid * 16 + it;
            int seg = u >> 10;
            int d = (u >> 4) & 63;
            int sg = u & 15;              // s granule of 8 within 128 rows
            const float* scol = so + (sg * 8) * OPITCH + seg * 64 + d;
            uint4 o;
            o.x = packh2(scol[0], scol[OPITCH]);
            o.y = packh2(scol[2 * OPITCH], scol[3 * OPITCH]);
            o.z = packh2(scol[4 * OPITCH], scol[5 * OPITCH]);
            o.w = packh2(scol[6 * OPITCH], scol[7 * OPITCH]);
            int h = (bnAll & 3) * 4 + seg;
            int skc = (bm & 7) * 2 + (sg >> 3);
            size_t chunk = ((size_t)((b * 16 + h) * 16 + skc)) * 8192;
            uint32_t off = (uint32_t)d * 128 + ((unsigned)((sg & 7) ^ (d & 7)) << 4);
            *(uint4*)((char*)g_vt + chunk + off) = o;
        }
    }
}

// ---------------------------------------------------------------------------
// 3) Fused flash attention: S=QK^T, online softmax, O=PV. One CTA per (bh, bm).
//    Heavy-first grid: bm = 7 - (bid>>5) so all 8-block CTAs start in wave 1.
#define FQ_BYTES 16384
#define FKV_BYTES 32768                  // K 16KB + V^T 16KB
#define FLASH_SMEM (FQ_BYTES + 2 * FKV_BYTES)   // 81920

__global__ __launch_bounds__(256, 1) void k_flash() {
    extern __shared__ __align__(128) char sm[];
    __shared__ __align__(8) unsigned long long s_mb[3];   // Q, stage0, stage1
    const int tid = threadIdx.x, lane = tid & 31, wid = tid >> 5;
    const int bm = 7 - (blockIdx.x >> 5);     // heavy tiles occupy wave 1
    const int bh = blockIdx.x & 31;
    const uint32_t sbase = smem_u32(sm);
    const uint32_t mbQ = smem_u32(&s_mb[0]);

    const char* gQ = (const char*)g_qh + ((size_t)bh * 8 + bm) * 16384;
    const char* gK = (const char*)g_kh + ((size_t)bh * 8) * 16384;
    const char* gV = (const char*)g_vt + ((size_t)bh * 16) * 8192;

    if (tid == 0) {
        MBAR_INIT(mbQ, 1);
        MBAR_INIT(mbQ + 8, 1);
        MBAR_INIT(mbQ + 16, 1);
    }
    __syncthreads();
    if (tid == 0) {
        MBAR_EXPECT(mbQ, FQ_BYTES);
        bulk_g2s(sbase, gQ, FQ_BYTES, mbQ);
        MBAR_EXPECT(mbQ + 8, FKV_BYTES);
        bulk_g2s(sbase + FQ_BYTES, gK, 16384, mbQ + 8);
        bulk_g2s(sbase + FQ_BYTES + 16384, gV, 16384, mbQ + 8);
        if (bm >= 1) {
            MBAR_EXPECT(mbQ + 16, FKV_BYTES);
            bulk_g2s(sbase + FQ_BYTES + FKV_BYTES, gK + 16384, 16384, mbQ + 16);
            bulk_g2s(sbase + FQ_BYTES + FKV_BYTES + 16384, gV + 16384, 16384, mbQ + 16);
        }
    }

    const int wm = wid * 16;
    const int l7 = lane & 7;
    const int g = lane >> 2, tig = lane & 3;
    const uint32_t aAddr0 = (uint32_t)(wm + (lane & 15)) * 128;
    const uint32_t rowBB = (uint32_t)(((lane >> 4) << 3) + l7) * 128;
    const int gA16 = lane >> 4, gB16 = (lane >> 3) & 1;

    float m0 = -1e30f, m1 = -1e30f, l0 = 0.f, l1 = 0.f;
    float o[8][4];
#pragma unroll
    for (int nt = 0; nt < 8; nt++)
#pragma unroll
        for (int e = 0; e < 4; e++) o[nt][e] = 0.f;

    unsigned aq[4][4];
    MBAR_WAIT(mbQ, 0);
#pragma unroll
    for (int kt = 0; kt < 4; kt++) {
        uint32_t xA = ((uint32_t)((kt * 2 + gA16) ^ l7)) << 4;
        ldsm4(aq[kt][0], aq[kt][1], aq[kt][2], aq[kt][3], sbase + aAddr0 + xA);
    }

    for (int j = 0; j <= bm; j++) {
        const uint32_t stg = sbase + FQ_BYTES + (j & 1) * FKV_BYTES;
        MBAR_WAIT(mbQ + 8 + (j & 1) * 8, (j >> 1) & 1);

        float s[16][4];
#pragma unroll
        for (int nt = 0; nt < 16; nt++)
#pragma unroll
            for (int e = 0; e < 4; e++) s[nt][e] = 0.f;

#pragma unroll
        for (int kt = 0; kt < 4; kt++) {
            uint32_t xB = ((uint32_t)((kt * 2 + gB16) ^ l7)) << 4;
            unsigned bk[16][2];
#pragma unroll
            for (int np = 0; np < 8; np++)
                ldsm4(bk[2 * np][0], bk[2 * np][1], bk[2 * np + 1][0], bk[2 * np + 1][1],
                      stg + rowBB + np * (16 * 128) + xB);
#pragma unroll
            for (int nt = 0; nt < 16; nt++) mma16(s[nt], aq[kt], bk[nt]);
        }

        if (j == bm) {   // causal mask within diagonal block
#pragma unroll
            for (int nt = 0; nt < 16; nt++) {
                int col = nt * 8 + 2 * tig;
                int r0 = wm + g, r1 = wm + g + 8;
                if (col > r0)     s[nt][0] = -1e30f;
                if (col + 1 > r0) s[nt][1] = -1e30f;
                if (col > r1)     s[nt][2] = -1e30f;
                if (col + 1 > r1) s[nt][3] = -1e30f;
            }
        }

        // online softmax
        float v0 = -1e30f, v1 = -1e30f;
#pragma unroll
        for (int nt = 0; nt < 16; nt++) {
            v0 = fmaxf(v0, fmaxf(s[nt][0], s[nt][1]));
            v1 = fmaxf(v1, fmaxf(s[nt][2], s[nt][3]));
        }
#pragma unroll
        for (int off = 1; off <= 2; off <<= 1) {
            v0 = fmaxf(v0, __shfl_xor_sync(0xffffffffu, v0, off));
            v1 = fmaxf(v1, __shfl_xor_sync(0xffffffffu, v1, off));
        }
        float mn0 = fmaxf(m0, v0), mn1 = fmaxf(m1, v1);
        float sc0 = __expf(m0 - mn0), sc1 = __expf(m1 - mn1);
        float sum0 = 0.f, sum1 = 0.f;
#pragma unroll
        for (int nt = 0; nt < 16; nt++) {
            s[nt][0] = __expf(s[nt][0] - mn0);
            s[nt][1] = __expf(s[nt][1] - mn0);
            s[nt][2] = __expf(s[nt][2] - mn1);
            s[nt][3] = __expf(s[nt][3] - mn1);
            sum0 += s[nt][0] + s[nt][1];
            sum1 += s[nt][2] + s[nt][3];
        }
#pragma unroll
        for (int off = 1; off <= 2; off <<= 1) {
            sum0 += __shfl_xor_sync(0xffffffffu, sum0, off);
            sum1 += __shfl_xor_sync(0xffffffffu, sum1, off);
        }
        l0 = l0 * sc0 + sum0; l1 = l1 * sc1 + sum1;
        m0 = mn0; m1 = mn1;
#pragma unroll
        for (int nt = 0; nt < 8; nt++) {
            o[nt][0] *= sc0; o[nt][1] *= sc0;
            o[nt][2] *= sc1; o[nt][3] *= sc1;
        }

        // pack P as A-fragments
        unsigned pa[8][4];
#pragma unroll
        for (int kt = 0; kt < 8; kt++) {
            pa[kt][0] = packh2(s[2 * kt][0], s[2 * kt][1]);
            pa[kt][1] = packh2(s[2 * kt][2], s[2 * kt][3]);
            pa[kt][2] = packh2(s[2 * kt + 1][0], s[2 * kt + 1][1]);
            pa[kt][3] = packh2(s[2 * kt + 1][2], s[2 * kt + 1][3]);
        }

        // PV: V^T tiles (n=d 64, k=s 128 in two 64-k chunks)
#pragma unroll
        for (int kt = 0; kt < 8; kt++) {
            const uint32_t vb = stg + 16384 + (kt >> 2) * 8192;
            const int kt2 = kt & 3;
            uint32_t xV = ((uint32_t)((kt2 * 2 + gB16) ^ l7)) << 4;
            unsigned bv[8][2];
#pragma unroll
            for (int np = 0; np < 4; np++)
                ldsm4(bv[2 * np][0], bv[2 * np][1], bv[2 * np + 1][0], bv[2 * np + 1][1],
                      vb + rowBB + np * (16 * 128) + xV);
#pragma unroll
            for (int nt = 0; nt < 8; nt++) mma16(o[nt], pa[kt], bv[nt]);
        }

        __syncthreads();
        if (tid == 0 && j + 2 <= bm) {
            int st = j & 1;
            uint32_t m = mbQ + 8 + st * 8;
            uint32_t dst = sbase + FQ_BYTES + st * FKV_BYTES;
            MBAR_EXPECT(m, FKV_BYTES);
            bulk_g2s(dst, gK + (size_t)(j + 2) * 16384, 16384, m);
            bulk_g2s(dst + 16384, gV + (size_t)(j + 2) * 16384, 16384, m);
        }
    }

    // finalize + write fp16 to g_ah chunk [bma][kc=h][r][d]
    const float inv0 = 1.0f / l0, inv1 = 1.0f / l1;
    const int b = bh >> 4, h = bh & 15;
    const size_t chunkB = ((size_t)((b * 8 + bm) * 16 + h)) * 16384;
#pragma unroll
    for (int nt = 0; nt < 8; nt++)
#pragma unroll
        for (int e = 0; e < 4; e++) {
            int rl = wm + g + ((e >= 2) ? 8 : 0);
            int d = nt * 8 + 2 * tig + (e & 1);
            float val = o[nt][e] * ((e >= 2) ? inv1 : inv0);
            uint32_t off = (uint32_t)rl * 128 +
                           ((unsigned)(((d >> 3) ^ (rl & 7))) << 4) + (d & 7) * 2;
            *(__half*)((char*)g_ah + chunkB + off) = __float2half_rn(val);
        }
}

// ---------------------------------------------------------------------------
// 4) LM head: fp16 bulk pipeline (unchanged from R9 winner)
__global__ __launch_bounds__(256, 1) void k_logits_b(const float* __restrict__ blm,
                                                     float* __restrict__ out) {
    extern __shared__ __align__(128) char sm[];
    __shared__ float s_bias[256];
    __shared__ __align__(8) unsigned long long s_mb[3];
    const int tid = threadIdx.x, lane = tid & 31, wid = tid >> 5;
    const int bm = blockIdx.x, bn = blockIdx.y;
    const uint32_t sbase = smem_u32(sm);
    const uint32_t mb0 = smem_u32(&s_mb[0]);

    {
        int gc = bn * 256 + tid;
        s_bias[tid] = (gc < Vn) ? blm[gc] : 0.f;
    }
    if (tid == 0) {
        MBAR_INIT(mb0, 1);
        MBAR_INIT(mb0 + 8, 1);
        MBAR_INIT(mb0 + 16, 1);
    }
    __syncthreads();

    const char* gA = (const char*)g_ah + ((size_t)bm * LKCH) * A_CH_BYTES;
    const char* gB = (const char*)g_wh + ((size_t)bn * LKCH) * B_CH_BYTES;

    if (tid == 0) {
#pragma unroll
        for (int s = 0; s < 3; s++) {
            uint32_t m = mb0 + s * 8;
            uint32_t dst = sbase + s * LSTG_BYTES;
            MBAR_EXPECT(m, LSTG_BYTES);
            bulk_g2s(dst, gA + (size_t)s * A_CH_BYTES, A_CH_BYTES, m);
            bulk_g2s(dst + A_CH_BYTES, gB + (size_t)s * B_CH_BYTES, B_CH_BYTES, m);
        }
    }

    float c[4][8][4];
#pragma unroll
    for (int mt = 0; mt < 4; mt++)
#pragma unroll
        for (int nt = 0; nt < 8; nt++)
#pragma unroll
            for (int e = 0; e < 4; e++) c[mt][nt][e] = 0.f;

    const int wm0 = (wid >> 2) * 64, wn0 = (wid & 3) * 64;
    const int l7 = lane & 7;
    const uint32_t aAddr0 = (uint32_t)(wm0 + (lane & 15)) * 128;
    const uint32_t bAddr0 = A_CH_BYTES +
                            (uint32_t)(wn0 + ((lane >> 4) << 3) + l7) * 128;
    const int gA16 = lane >> 4, gB16 = (lane >> 3) & 1;

    gemm_mainloop(c, sbase, mb0, gA, gB, tid, aAddr0, bAddr0, gA16, gB16, l7);

    __syncthreads();
    float* so = (float*)sm;
    const int g = lane >> 2, tig = lane & 3;
#pragma unroll
    for (int mt = 0; mt < 4; mt++)
#pragma unroll
        for (int e2 = 0; e2 < 2; e2++) {
            int rl = wm0 + mt * 16 + g + e2 * 8;
#pragma unroll
            for (int nt = 0; nt < 8; nt++) {
                int cl = wn0 + nt * 8 + 2 * tig;
                float2 w;
                w.x = c[mt][nt][e2 * 2 + 0] + s_bias[cl];
                w.y = c[mt][nt][e2 * 2 + 1] + s_bias[cl + 1];
                *(float2*)(so + rl * OPITCH + cl) = w;
            }
        }
    __syncthreads();
#pragma unroll 1
    for (int rr = 0; rr < 16; rr++) {
        int rl = wid * 16 + rr;
        int row = bm * 128 + rl;
        float* orow = out + (size_t)row * Vn;
        const float* srow = so + rl * OPITCH;
#pragma unroll
        for (int j = 0; j < 8; j++) {
            int cl = lane + j * 32;
            int col = bn * 256 + cl;
            if (col < Vn) orow[col] = srow[cl];
        }
    }
}

// ---------------------------------------------------------------------------
extern "C" void kernel_launch(void* const* d_in, const int* in_sizes, int n_in,
                              void* d_out, int out_size) {
    (void)in_sizes; (void)n_in; (void)out_size;
    const int*   idx = (const int*)d_in[0];
    const float* tok = (const float*)d_in[1];
    const float* pos = (const float*)d_in[2];
    const float* Wq  = (const float*)d_in[3];
    const float* Wk  = (const float*)d_in[4];
    const float* Wv  = (const float*)d_in[5];
    const float* Wlm = (const float*)d_in[6];
    const float* blm = (const float*)d_in[7];
    float* out = (float*)d_out;

    cudaFuncSetAttribute(k_logits_b, cudaFuncAttributeMaxDynamicSharedMemorySize,
                         LOG_SMEM);
    cudaFuncSetAttribute(k_qkv_h, cudaFuncAttributeMaxDynamicSharedMemorySize,
                         LOG_SMEM);
    cudaFuncSetAttribute(k_flash, cudaFuncAttributeMaxDynamicSharedMemorySize,
                         FLASH_SMEM);

    // One-time stream/event setup (runs on the first, non-captured call).
    static cudaStream_t s_side = nullptr;
    static cudaEvent_t ev_fork = nullptr, ev_join = nullptr;
    if (!s_side) {
        cudaStreamCreateWithFlags(&s_side, cudaStreamNonBlocking);
        cudaEventCreateWithFlags(&ev_fork, cudaEventDisableTiming);
        cudaEventCreateWithFlags(&ev_join, cudaEventDisableTiming);
    }

    // Fork: W_lm fp16 conversion runs concurrently with the attention chain;
    // only k_logits_b consumes g_wh, so join right before it.
    cudaEventRecord(ev_fork, 0);
    cudaStreamWaitEvent(s_side, ev_fork, 0);
    k_w2h<<<(Vn * 128 + 255) / 256, 256, 0, s_side>>>(Wlm);
    cudaEventRecord(ev_join, s_side);

    k_wqkv<<<1536, 256>>>(Wq, Wk, Wv);
    k_embed<<<BTn, 256>>>(idx, tok, pos);
    k_qkv_h<<<dim3(16, 12), 256, LOG_SMEM>>>();
    k_flash<<<256, 256, FLASH_SMEM>>>();

    cudaStreamWaitEvent(0, ev_join, 0);
    k_logits_b<<<dim3(16, NBN), 256, LOG_SMEM>>>(blm, out);
}

// round 12
// speedup vs baseline: 4.9402x; 1.0013x over previous
#include <cuda_runtime.h>
#include <cuda_fp16.h>
#include <cstdint>

// Problem constants
#define Bsz  2
#define Tn   1024
#define Cn   1024
#define Hn   16
#define HDn  64
#define Vn   50257
#define BTn  2048
#define NBH  32          // B*H
#define NBN  197         // ceil(Vn/256)

// Chunked, pre-swizzled fp16 operands.
// A-chunks: [.. ][kc][row:128][64 halves], B-chunks: [..][kc][row:256][64 halves]
__device__ __align__(128) __half g_xh[BTn * Cn];                 // embed out (A of QKV)
__device__ __align__(128) __half g_wqkvh[3 * 4 * 16 * 256 * 64]; // Wq/Wk/Wv (B of QKV)
__device__ __align__(128) __half g_qh[NBH * 8 * 128 * 64];       // Q [bh][sb][r][d]
__device__ __align__(128) __half g_kh[NBH * 8 * 128 * 64];       // K [bh][sb][r][d]
__device__ __align__(128) __half g_vt[NBH * 16 * 64 * 64];       // V^T [bh][skc][d][s]
__device__ __align__(128) __half g_ah[BTn * Cn];                 // attn out (A of logits)
__device__ __align__(128) __half g_wh[(size_t)NBN * 16 * 256 * 64]; // W_lm (B of logits)

// ===========================================================================
// helpers (sm_80/sm_90 baseline ISA)
// ===========================================================================
__device__ __forceinline__ uint32_t smem_u32(const void* p) {
    return (uint32_t)__cvta_generic_to_shared(p);
}
__device__ __forceinline__ void mma16(float* c, const unsigned* a, const unsigned* b) {
    asm volatile(
        "mma.sync.aligned.m16n8k16.row.col.f32.f16.f16.f32 "
        "{%0,%1,%2,%3},{%4,%5,%6,%7},{%8,%9},{%0,%1,%2,%3};"
        : "+f"(c[0]), "+f"(c[1]), "+f"(c[2]), "+f"(c[3])
        : "r"(a[0]), "r"(a[1]), "r"(a[2]), "r"(a[3]), "r"(b[0]), "r"(b[1]));
}
__device__ __forceinline__ void ldsm4(unsigned& r0, unsigned& r1, unsigned& r2,
                                      unsigned& r3, uint32_t addr) {
    asm volatile("ldmatrix.sync.aligned.m8n8.x4.shared.b16 {%0,%1,%2,%3}, [%4];"
                 : "=r"(r0), "=r"(r1), "=r"(r2), "=r"(r3) : "r"(addr));
}
__device__ __forceinline__ void bulk_g2s(uint32_t dst, const void* src, int bytes,
                                         uint32_t mbar) {
    asm volatile(
        "cp.async.bulk.shared::cluster.global.mbarrier::complete_tx::bytes "
        "[%0], [%1], %2, [%3];"
        :: "r"(dst), "l"(src), "r"(bytes), "r"(mbar) : "memory");
}
#define MBAR_INIT(mbar, cnt) \
    asm volatile("mbarrier.init.shared.b64 [%0], %1;" \
                 :: "r"((uint32_t)(mbar)), "r"((uint32_t)(cnt)) : "memory")
#define MBAR_EXPECT(mbar, tx) \
    asm volatile("mbarrier.arrive.expect_tx.shared.b64 _, [%0], %1;" \
                 :: "r"((uint32_t)(mbar)), "r"((uint32_t)(tx)) : "memory")
#define MBAR_WAIT(mbar, parity) do {                                          \
    uint32_t _m = (uint32_t)(mbar);                                           \
    uint32_t _p = (uint32_t)(parity);                                         \
    asm volatile(                                                             \
        "{\n\t.reg .pred P1;\n\t"                                             \
        "WAIT_LOOP_%=:\n\t"                                                   \
        "mbarrier.try_wait.parity.acquire.cta.shared::cta.b64 P1, [%0], %1, 0x989680;\n\t" \
        "@P1 bra.uni WAIT_DONE_%=;\n\t"                                       \
        "bra.uni WAIT_LOOP_%=;\n\t"                                           \
        "WAIT_DONE_%=:\n\t}"                                                  \
        :: "r"(_m), "r"(_p) : "memory");                                      \
} while (0)

__device__ __forceinline__ unsigned packh2(float x, float y) {
    __half2 h = __floats2half2_rn(x, y);
    return *(unsigned*)&h;
}

// ---------------------------------------------------------------------------
// 1) Embedding -> fp16 chunked+swizzled A layout (g_xh)
__global__ __launch_bounds__(256) void k_embed(const int* __restrict__ idx,
                                               const float* __restrict__ tok,
                                               const float* __restrict__ pos) {
    int i = blockIdx.x;                   // bt row
    int t = i & (Tn - 1);
    int token = idx[i];
    const float4* te = (const float4*)(tok + (size_t)token * Cn);
    const float4* pe = (const float4*)(pos + (size_t)t * Cn);
    int tid = threadIdx.x;
    float4 a = te[tid], b = pe[tid];
    uint2 o;
    o.x = packh2(a.x + b.x, a.y + b.y);
    o.y = packh2(a.z + b.z, a.w + b.w);
    int r = i & 127, bm = i >> 7;
    int kc = tid >> 4;                    // k = tid*4; kc = k>>6
    int c16 = (tid >> 1) & 7;
    int hsel = tid & 1;
    size_t base = ((size_t)(bm * 16 + kc)) * 16384;
    uint32_t off = (uint32_t)r * 128 + ((unsigned)(c16 ^ (r & 7)) << 4) + hsel * 8;
    *(uint2*)((char*)g_xh + base + off) = o;
}

// ---------------------------------------------------------------------------
// 1b) W_lm -> fp16, tile-chunked + SW128-swizzled B layout. Grid-stride so it
//     trickles alongside the attention chain on the side stream.
__global__ __launch_bounds__(256) void k_w2h(const float* __restrict__ W) {
    for (int gid = blockIdx.x * 256 + threadIdx.x; gid < Vn * 128;
         gid += gridDim.x * 256) {
        int v = gid >> 7, g8 = gid & 127;             // kk = g8*8
        const float4* s = (const float4*)(W + (size_t)v * Cn + g8 * 8);
        float4 x = s[0], y = s[1];
        uint4 o;
        o.x = packh2(x.x, x.y); o.y = packh2(x.z, x.w);
        o.z = packh2(y.x, y.y); o.w = packh2(y.z, y.w);
        int bn = v >> 8, r = v & 255;
        int kc = g8 >> 3, c16 = g8 & 7;
        size_t chunkB = (((size_t)bn * 16 + kc) * (256 * 64)) * 2;
        uint32_t off = (uint32_t)r * 128 + ((unsigned)(c16 ^ (r & 7)) << 4);
        *(uint4*)((char*)g_wh + chunkB + off) = o;
    }
}

// ---------------------------------------------------------------------------
// 1c) Wq/Wk/Wv -> transposed fp16 chunked B layout (n=(h,d) rows, k=c).
__global__ __launch_bounds__(256) void k_wqkv(const float* __restrict__ Wq,
                                              const float* __restrict__ Wk,
                                              const float* __restrict__ Wv) {
    int u = blockIdx.x * 4 + (threadIdx.x >> 6);   // 0..6143
    int d = threadIdx.x & 63;
    int mat = u >> 11;
    int rem = u & 2047;
    int h = rem >> 7;
    int kc = (rem >> 3) & 15;
    int c16 = rem & 7;
    const float* W = (mat == 0) ? Wq : (mat == 1) ? Wk : Wv;
    const float* Wb = W + (size_t)h * (Cn * HDn) + d;
    float vals[8];
#pragma unroll
    for (int j = 0; j < 8; j++) {
        int c = kc * 64 + c16 * 8 + j;
        vals[j] = Wb[(size_t)c * HDn];
    }
    uint4 o;
    o.x = packh2(vals[0], vals[1]); o.y = packh2(vals[2], vals[3]);
    o.z = packh2(vals[4], vals[5]); o.w = packh2(vals[6], vals[7]);
    int bnAll = mat * 4 + (h >> 2);
    int r = (h & 3) * 64 + d;
    size_t chunkB = (((size_t)bnAll * 16 + kc) * (256 * 64)) * 2;
    uint32_t off = (uint32_t)r * 128 + ((unsigned)(c16 ^ (r & 7)) << 4);
    *(uint4*)((char*)g_wqkvh + chunkB + off) = o;
}

// ===========================================================================
// Shared fp16 bulk-pipeline GEMM pieces
// ===========================================================================
#define LKCH 16                          // K chunks of 64
#define A_CH_BYTES (128 * 128)           // 16KB
#define B_CH_BYTES (256 * 128)           // 32KB
#define LSTG_BYTES (A_CH_BYTES + B_CH_BYTES)   // 49152
#define LOG_SMEM (3 * LSTG_BYTES)        // 147456
#define OPITCH 264                       // f32 pitch for epilogue staging

struct Frags { unsigned a[4][4]; unsigned b[8][2]; };

__device__ __forceinline__ void load_frags(Frags& f, uint32_t sb, int kt,
                                           uint32_t aAddr0, uint32_t bAddr0,
                                           int gA16, int gB16, int l7) {
    const uint32_t xA = ((uint32_t)((kt * 2 + gA16) ^ l7)) << 4;
    const uint32_t xB = ((uint32_t)((kt * 2 + gB16) ^ l7)) << 4;
#pragma unroll
    for (int mt = 0; mt < 4; mt++)
        ldsm4(f.a[mt][0], f.a[mt][1], f.a[mt][2], f.a[mt][3],
              sb + aAddr0 + mt * (16 * 128) + xA);
#pragma unroll
    for (int np = 0; np < 4; np++)
        ldsm4(f.b[2 * np][0], f.b[2 * np][1], f.b[2 * np + 1][0], f.b[2 * np + 1][1],
              sb + bAddr0 + np * (16 * 128) + xB);
}

__device__ __forceinline__ void gemm_mainloop(float (&c)[4][8][4], uint32_t sbase,
                                              uint32_t mb0, const char* gA,
                                              const char* gB, int tid,
                                              uint32_t aAddr0, uint32_t bAddr0,
                                              int gA16, int gB16, int l7) {
    Frags fr[2];
    MBAR_WAIT(mb0, 0);
    load_frags(fr[0], sbase, 0, aAddr0, bAddr0, gA16, gB16, l7);

    for (int kc = 0; kc < LKCH; kc++) {
        const uint32_t sb = sbase + (kc % 3) * LSTG_BYTES;
#pragma unroll
        for (int kt = 0; kt < 4; kt++) {
            const int cur = kt & 1;
            if (kt < 3)
                load_frags(fr[cur ^ 1], sb, kt + 1, aAddr0, bAddr0, gA16, gB16, l7);
#pragma unroll
            for (int mt = 0; mt < 4; mt++)
#pragma unroll
                for (int nt = 0; nt < 8; nt++) mma16(c[mt][nt], fr[cur].a[mt], fr[cur].b[nt]);
        }
        __syncthreads();
        if (tid == 0 && kc + 3 < LKCH) {
            int s = kc % 3;
            uint32_t m = mb0 + s * 8;
            uint32_t dst = sbase + s * LSTG_BYTES;
            MBAR_EXPECT(m, LSTG_BYTES);
            bulk_g2s(dst, gA + (size_t)(kc + 3) * A_CH_BYTES, A_CH_BYTES, m);
            bulk_g2s(dst + A_CH_BYTES, gB + (size_t)(kc + 3) * B_CH_BYTES, B_CH_BYTES, m);
        }
        if (kc + 1 < LKCH) {
            MBAR_WAIT(mb0 + ((kc + 1) % 3) * 8, ((kc + 1) / 3) & 1);
            load_frags(fr[0], sbase + ((kc + 1) % 3) * LSTG_BYTES, 0,
                       aAddr0, bAddr0, gA16, gB16, l7);
        }
    }
}

// ---------------------------------------------------------------------------
// 2) QKV via fp16 bulk pipeline. grid (16, 12): bn 0-3 -> q, 4-7 -> k, 8-11 -> v.
__global__ __launch_bounds__(256, 1) void k_qkv_h() {
    extern __shared__ __align__(128) char sm[];
    __shared__ __align__(8) unsigned long long s_mb[3];
    const int tid = threadIdx.x, lane = tid & 31, wid = tid >> 5;
    const int bm = blockIdx.x, bnAll = blockIdx.y;
    const uint32_t sbase = smem_u32(sm);
    const uint32_t mb0 = smem_u32(&s_mb[0]);

    if (tid == 0) {
        MBAR_INIT(mb0, 1);
        MBAR_INIT(mb0 + 8, 1);
        MBAR_INIT(mb0 + 16, 1);
    }
    __syncthreads();

    const char* gA = (const char*)g_xh + ((size_t)bm * LKCH) * A_CH_BYTES;
    const char* gB = (const char*)g_wqkvh + ((size_t)bnAll * LKCH) * B_CH_BYTES;

    if (tid == 0) {
#pragma unroll
        for (int s = 0; s < 3; s++) {
            uint32_t m = mb0 + s * 8;
            uint32_t dst = sbase + s * LSTG_BYTES;
            MBAR_EXPECT(m, LSTG_BYTES);
            bulk_g2s(dst, gA + (size_t)s * A_CH_BYTES, A_CH_BYTES, m);
            bulk_g2s(dst + A_CH_BYTES, gB + (size_t)s * B_CH_BYTES, B_CH_BYTES, m);
        }
    }

    float c[4][8][4];
#pragma unroll
    for (int mt = 0; mt < 4; mt++)
#pragma unroll
        for (int nt = 0; nt < 8; nt++)
#pragma unroll
            for (int e = 0; e < 4; e++) c[mt][nt][e] = 0.f;

    const int wm0 = (wid >> 2) * 64, wn0 = (wid & 3) * 64;
    const int l7 = lane & 7;
    const uint32_t aAddr0 = (uint32_t)(wm0 + (lane & 15)) * 128;
    const uint32_t bAddr0 = A_CH_BYTES +
                            (uint32_t)(wn0 + ((lane >> 4) << 3) + l7) * 128;
    const int gA16 = lane >> 4, gB16 = (lane >> 3) & 1;

    gemm_mainloop(c, sbase, mb0, gA, gB, tid, aAddr0, bAddr0, gA16, gB16, l7);

    // stage (scaled) accum to SMEM f32
    const int mat = bnAll >> 2;
    const float sc = (mat == 0) ? 0.03125f : 1.0f;
    __syncthreads();
    float* so = (float*)sm;
    const int g = lane >> 2, tig = lane & 3;
#pragma unroll
    for (int mt = 0; mt < 4; mt++)
#pragma unroll
        for (int e2 = 0; e2 < 2; e2++) {
            int rl = wm0 + mt * 16 + g + e2 * 8;
#pragma unroll
            for (int nt = 0; nt < 8; nt++) {
                int cl = wn0 + nt * 8 + 2 * tig;
                float2 w;
                w.x = c[mt][nt][e2 * 2 + 0] * sc;
                w.y = c[mt][nt][e2 * 2 + 1] * sc;
                *(float2*)(so + rl * OPITCH + cl) = w;
            }
        }
    __syncthreads();

    const int b = bm >> 3;            // batch of this 128-row tile
    if (mat < 2) {
        // Q/K: [bh][sb][r:128][64] chunks; warp handles rows wid*16..+15
        __half* dst = (mat == 0) ? g_qh : g_kh;
        const int seg = lane >> 3, g8 = lane & 7;
        const int h = (bnAll & 3) * 4 + seg;
        const int sb = bm & 7;
#pragma unroll 1
        for (int rr = 0; rr < 16; rr++) {
            int rl = wid * 16 + rr;
            const float* srow = so + rl * OPITCH + seg * 64 + g8 * 8;
            uint4 o;
            o.x = packh2(srow[0], srow[1]); o.y = packh2(srow[2], srow[3]);
            o.z = packh2(srow[4], srow[5]); o.w = packh2(srow[6], srow[7]);
            size_t chunk = ((size_t)((b * 16 + h) * 8 + sb)) * 16384;
            uint32_t off = (uint32_t)rl * 128 + ((unsigned)(g8 ^ (rl & 7)) << 4);
            *(uint4*)((char*)dst + chunk + off) = o;
        }
    } else {
        // V^T: [bh][skc:16][d:64][64 s] chunks of 8KB
#pragma unroll 1
        for (int it = 0; it < 16; it++) {
            int u = tid * 16 + it;
            int seg = u >> 10;
            int d = (u >> 4) & 63;
            int sg = u & 15;              // s granule of 8 within 128 rows
            const float* scol = so + (sg * 8) * OPITCH + seg * 64 + d;
            uint4 o;
            o.x = packh2(scol[0], scol[OPITCH]);
            o.y = packh2(scol[2 * OPITCH], scol[3 * OPITCH]);
            o.z = packh2(scol[4 * OPITCH], scol[5 * OPITCH]);
            o.w = packh2(scol[6 * OPITCH], scol[7 * OPITCH]);
            int h = (bnAll & 3) * 4 + seg;
            int skc = (bm & 7) * 2 + (sg >> 3);
            size_t chunk = ((size_t)((b * 16 + h) * 16 + skc)) * 8192;
            uint32_t off = (uint32_t)d * 128 + ((unsigned)((sg & 7) ^ (d & 7)) << 4);
            *(uint4*)((char*)g_vt + chunk + off) = o;
        }
    }
}

// ---------------------------------------------------------------------------
// 3) Fused flash attention with PAIRED tiles: CTA (pair, bh) handles
//    bm_hi = 7-pair then bm_lo = pair -> exactly 9 kv-blocks per CTA.
//    grid = 128 CTAs = one balanced wave.
#define FQ_BYTES 16384
#define FKV_BYTES 32768                  // K 16KB + V^T 16KB
#define FLASH_SMEM (FQ_BYTES + 2 * FKV_BYTES)   // 81920

__global__ __launch_bounds__(256, 1) void k_flash() {
    extern __shared__ __align__(128) char sm[];
    __shared__ __align__(8) unsigned long long s_mb[3];   // Q, stage0, stage1
    const int tid = threadIdx.x, lane = tid & 31, wid = tid >> 5;
    const int pair = blockIdx.x >> 5;         // 0..3
    const int bh = blockIdx.x & 31;
    const int bm_hi = 7 - pair, bm_lo = pair; // (bm_hi+1)+(bm_lo+1) = 9
    const uint32_t sbase = smem_u32(sm);
    const uint32_t mbQ = smem_u32(&s_mb[0]);

    const char* gQb = (const char*)g_qh + ((size_t)bh * 8) * 16384;
    const char* gK = (const char*)g_kh + ((size_t)bh * 8) * 16384;
    const char* gV = (const char*)g_vt + ((size_t)bh * 16) * 8192;

    if (tid == 0) {
        MBAR_INIT(mbQ, 1);
        MBAR_INIT(mbQ + 8, 1);
        MBAR_INIT(mbQ + 16, 1);
    }
    __syncthreads();
    if (tid == 0) {
        MBAR_EXPECT(mbQ, FQ_BYTES);
        bulk_g2s(sbase, gQb + (size_t)bm_hi * 16384, FQ_BYTES, mbQ);
        // items 0 and 1 (j = 0, 1; bm_hi >= 4 so both are tileA blocks)
        MBAR_EXPECT(mbQ + 8, FKV_BYTES);
        bulk_g2s(sbase + FQ_BYTES, gK, 16384, mbQ + 8);
        bulk_g2s(sbase + FQ_BYTES + 16384, gV, 16384, mbQ + 8);
        MBAR_EXPECT(mbQ + 16, FKV_BYTES);
        bulk_g2s(sbase + FQ_BYTES + FKV_BYTES, gK + 16384, 16384, mbQ + 16);
        bulk_g2s(sbase + FQ_BYTES + FKV_BYTES + 16384, gV + 16384, 16384, mbQ + 16);
    }

    const int wm = wid * 16;
    const int l7 = lane & 7;
    const int g = lane >> 2, tig = lane & 3;
    const uint32_t aAddr0 = (uint32_t)(wm + (lane & 15)) * 128;
    const uint32_t rowBB = (uint32_t)(((lane >> 4) << 3) + l7) * 128;
    const int gA16 = lane >> 4, gB16 = (lane >> 3) & 1;

    float m0 = -1e30f, m1 = -1e30f, l0 = 0.f, l1 = 0.f;
    float o[8][4];
#pragma unroll
    for (int nt = 0; nt < 8; nt++)
#pragma unroll
        for (int e = 0; e < 4; e++) o[nt][e] = 0.f;

    unsigned aq[4][4];
    MBAR_WAIT(mbQ, 0);
#pragma unroll
    for (int kt = 0; kt < 4; kt++) {
        uint32_t xA = ((uint32_t)((kt * 2 + gA16) ^ l7)) << 4;
        ldsm4(aq[kt][0], aq[kt][1], aq[kt][2], aq[kt][3], sbase + aAddr0 + xA);
    }
    __syncthreads();                 // all warps have read Q_hi from smem
    if (tid == 0) {                  // prefetch Q_lo into the (now free) Q buffer
        MBAR_EXPECT(mbQ, FQ_BYTES);
        bulk_g2s(sbase, gQb + (size_t)bm_lo * 16384, FQ_BYTES, mbQ);
    }

    const int b = bh >> 4, h = bh & 15;
    const float inv_dummy = 0.f; (void)inv_dummy;

    // epilogue writer for current accumulator state
    auto write_out = [&](int bm_out) {
        const float inv0 = 1.0f / l0, inv1 = 1.0f / l1;
        const size_t chunkB = ((size_t)((b * 8 + bm_out) * 16 + h)) * 16384;
#pragma unroll
        for (int nt = 0; nt < 8; nt++)
#pragma unroll
            for (int e = 0; e < 4; e++) {
                int rl = wm + g + ((e >= 2) ? 8 : 0);
                int d = nt * 8 + 2 * tig + (e & 1);
                float val = o[nt][e] * ((e >= 2) ? inv1 : inv0);
                uint32_t off = (uint32_t)rl * 128 +
                               ((unsigned)(((d >> 3) ^ (rl & 7))) << 4) + (d & 7) * 2;
                *(__half*)((char*)g_ah + chunkB + off) = __float2half_rn(val);
            }
    };

    for (int i = 0; i < 9; i++) {
        const int in_hi = (i <= bm_hi);
        const int cur_bm = in_hi ? bm_hi : bm_lo;
        const int j = in_hi ? i : (i - bm_hi - 1);
        const uint32_t stg = sbase + FQ_BYTES + (i & 1) * FKV_BYTES;
        MBAR_WAIT(mbQ + 8 + (i & 1) * 8, (i >> 1) & 1);

        float s[16][4];
#pragma unroll
        for (int nt = 0; nt < 16; nt++)
#pragma unroll
            for (int e = 0; e < 4; e++) s[nt][e] = 0.f;

#pragma unroll
        for (int kt = 0; kt < 4; kt++) {
            uint32_t xB = ((uint32_t)((kt * 2 + gB16) ^ l7)) << 4;
            unsigned bk[16][2];
#pragma unroll
            for (int np = 0; np < 8; np++)
                ldsm4(bk[2 * np][0], bk[2 * np][1], bk[2 * np + 1][0], bk[2 * np + 1][1],
                      stg + rowBB + np * (16 * 128) + xB);
#pragma unroll
            for (int nt = 0; nt < 16; nt++) mma16(s[nt], aq[kt], bk[nt]);
        }

        if (j == cur_bm) {   // causal mask on diagonal block
#pragma unroll
            for (int nt = 0; nt < 16; nt++) {
                int col = nt * 8 + 2 * tig;
                int r0 = wm + g, r1 = wm + g + 8;
                if (col > r0)     s[nt][0] = -1e30f;
                if (col + 1 > r0) s[nt][1] = -1e30f;
                if (col > r1)     s[nt][2] = -1e30f;
                if (col + 1 > r1) s[nt][3] = -1e30f;
            }
        }

        // online softmax
        float v0 = -1e30f, v1 = -1e30f;
#pragma unroll
        for (int nt = 0; nt < 16; nt++) {
            v0 = fmaxf(v0, fmaxf(s[nt][0], s[nt][1]));
            v1 = fmaxf(v1, fmaxf(s[nt][2], s[nt][3]));
        }
#pragma unroll
        for (int off = 1; off <= 2; off <<= 1) {
            v0 = fmaxf(v0, __shfl_xor_sync(0xffffffffu, v0, off));
            v1 = fmaxf(v1, __shfl_xor_sync(0xffffffffu, v1, off));
        }
        float mn0 = fmaxf(m0, v0), mn1 = fmaxf(m1, v1);
        float sc0 = __expf(m0 - mn0), sc1 = __expf(m1 - mn1);
        float sum0 = 0.f, sum1 = 0.f;
#pragma unroll
        for (int nt = 0; nt < 16; nt++) {
            s[nt][0] = __expf(s[nt][0] - mn0);
            s[nt][1] = __expf(s[nt][1] - mn0);
            s[nt][2] = __expf(s[nt][2] - mn1);
            s[nt][3] = __expf(s[nt][3] - mn1);
            sum0 += s[nt][0] + s[nt][1];
            sum1 += s[nt][2] + s[nt][3];
        }
#pragma unroll
        for (int off = 1; off <= 2; off <<= 1) {
            sum0 += __shfl_xor_sync(0xffffffffu, sum0, off);
            sum1 += __shfl_xor_sync(0xffffffffu, sum1, off);
        }
        l0 = l0 * sc0 + sum0; l1 = l1 * sc1 + sum1;
        m0 = mn0; m1 = mn1;
#pragma unroll
        for (int nt = 0; nt < 8; nt++) {
            o[nt][0] *= sc0; o[nt][1] *= sc0;
            o[nt][2] *= sc1; o[nt][3] *= sc1;
        }

        // pack P as A-fragments
        unsigned pa[8][4];
#pragma unroll
        for (int kt = 0; kt < 8; kt++) {
            pa[kt][0] = packh2(s[2 * kt][0], s[2 * kt][1]);
            pa[kt][1] = packh2(s[2 * kt][2], s[2 * kt][3]);
            pa[kt][2] = packh2(s[2 * kt + 1][0], s[2 * kt + 1][1]);
            pa[kt][3] = packh2(s[2 * kt + 1][2], s[2 * kt + 1][3]);
        }

        // PV: V^T tiles (n=d 64, k=s 128 in two 64-k chunks)
#pragma unroll
        for (int kt = 0; kt < 8; kt++) {
            const uint32_t vb = stg + 16384 + (kt >> 2) * 8192;
            const int kt2 = kt & 3;
            uint32_t xV = ((uint32_t)((kt2 * 2 + gB16) ^ l7)) << 4;
            unsigned bv[8][2];
#pragma unroll
            for (int np = 0; np < 4; np++)
                ldsm4(bv[2 * np][0], bv[2 * np][1], bv[2 * np + 1][0], bv[2 * np + 1][1],
                      vb + rowBB + np * (16 * 128) + xV);
#pragma unroll
            for (int nt = 0; nt < 8; nt++) mma16(o[nt], pa[kt], bv[nt]);
        }

        __syncthreads();
        if (tid == 0 && i + 2 < 9) {
            int jn = (i + 2 <= bm_hi) ? (i + 2) : (i + 2 - bm_hi - 1);
            int st = i & 1;
            uint32_t m = mbQ + 8 + st * 8;
            uint32_t dst = sbase + FQ_BYTES + st * FKV_BYTES;
            MBAR_EXPECT(m, FKV_BYTES);
            bulk_g2s(dst, gK + (size_t)jn * 16384, 16384, m);
            bulk_g2s(dst + 16384, gV + (size_t)jn * 16384, 16384, m);
        }

        if (i == bm_hi) {
            // tile A complete: emit it, reset state, switch to Q_lo
            write_out(bm_hi);
            m0 = -1e30f; m1 = -1e30f; l0 = 0.f; l1 = 0.f;
#pragma unroll
            for (int nt = 0; nt < 8; nt++)
#pragma unroll
                for (int e = 0; e < 4; e++) o[nt][e] = 0.f;
            MBAR_WAIT(mbQ, 1);
#pragma unroll
            for (int kt = 0; kt < 4; kt++) {
                uint32_t xA = ((uint32_t)((kt * 2 + gA16) ^ l7)) << 4;
                ldsm4(aq[kt][0], aq[kt][1], aq[kt][2], aq[kt][3], sbase + aAddr0 + xA);
            }
        }
    }

    write_out(bm_lo);
}

// ---------------------------------------------------------------------------
// 4) LM head: fp16 bulk pipeline (unchanged from R9 winner)
__global__ __launch_bounds__(256, 1) void k_logits_b(const float* __restrict__ blm,
                                                     float* __restrict__ out) {
    extern __shared__ __align__(128) char sm[];
    __shared__ float s_bias[256];
    __shared__ __align__(8) unsigned long long s_mb[3];
    const int tid = threadIdx.x, lane = tid & 31, wid = tid >> 5;
    const int bm = blockIdx.x, bn = blockIdx.y;
    const uint32_t sbase = smem_u32(sm);
    const uint32_t mb0 = smem_u32(&s_mb[0]);

    {
        int gc = bn * 256 + tid;
        s_bias[tid] = (gc < Vn) ? blm[gc] : 0.f;
    }
    if (tid == 0) {
        MBAR_INIT(mb0, 1);
        MBAR_INIT(mb0 + 8, 1);
        MBAR_INIT(mb0 + 16, 1);
    }
    __syncthreads();

    const char* gA = (const char*)g_ah + ((size_t)bm * LKCH) * A_CH_BYTES;
    const char* gB = (const char*)g_wh + ((size_t)bn * LKCH) * B_CH_BYTES;

    if (tid == 0) {
#pragma unroll
        for (int s = 0; s < 3; s++) {
            uint32_t m = mb0 + s * 8;
            uint32_t dst = sbase + s * LSTG_BYTES;
            MBAR_EXPECT(m, LSTG_BYTES);
            bulk_g2s(dst, gA + (size_t)s * A_CH_BYTES, A_CH_BYTES, m);
            bulk_g2s(dst + A_CH_BYTES, gB + (size_t)s * B_CH_BYTES, B_CH_BYTES, m);
        }
    }

    float c[4][8][4];
#pragma unroll
    for (int mt = 0; mt < 4; mt++)
#pragma unroll
        for (int nt = 0; nt < 8; nt++)
#pragma unroll
            for (int e = 0; e < 4; e++) c[mt][nt][e] = 0.f;

    const int wm0 = (wid >> 2) * 64, wn0 = (wid & 3) * 64;
    const int l7 = lane & 7;
    const uint32_t aAddr0 = (uint32_t)(wm0 + (lane & 15)) * 128;
    const uint32_t bAddr0 = A_CH_BYTES +
                            (uint32_t)(wn0 + ((lane >> 4) << 3) + l7) * 128;
    const int gA16 = lane >> 4, gB16 = (lane >> 3) & 1;

    gemm_mainloop(c, sbase, mb0, gA, gB, tid, aAddr0, bAddr0, gA16, gB16, l7);

    __syncthreads();
    float* so = (float*)sm;
    const int g = lane >> 2, tig = lane & 3;
#pragma unroll
    for (int mt = 0; mt < 4; mt++)
#pragma unroll
        for (int e2 = 0; e2 < 2; e2++) {
            int rl = wm0 + mt * 16 + g + e2 * 8;
#pragma unroll
            for (int nt = 0; nt < 8; nt++) {
                int cl = wn0 + nt * 8 + 2 * tig;
                float2 w;
                w.x = c[mt][nt][e2 * 2 + 0] + s_bias[cl];
                w.y = c[mt][nt][e2 * 2 + 1] + s_bias[cl + 1];
                *(float2*)(so + rl * OPITCH + cl) = w;
            }
        }
    __syncthreads();
#pragma unroll 1
    for (int rr = 0; rr < 16; rr++) {
        int rl = wid * 16 + rr;
        int row = bm * 128 + rl;
        float* orow = out + (size_t)row * Vn;
        const float* srow = so + rl * OPITCH;
#pragma unroll
        for (int j = 0; j < 8; j++) {
            int cl = lane + j * 32;
            int col = bn * 256 + cl;
            if (col < Vn) orow[col] = srow[cl];
        }
    }
}

// ---------------------------------------------------------------------------
extern "C" void kernel_launch(void* const* d_in, const int* in_sizes, int n_in,
                              void* d_out, int out_size) {
    (void)in_sizes; (void)n_in; (void)out_size;
    const int*   idx = (const int*)d_in[0];
    const float* tok = (const float*)d_in[1];
    const float* pos = (const float*)d_in[2];
    const float* Wq  = (const float*)d_in[3];
    const float* Wk  = (const float*)d_in[4];
    const float* Wv  = (const float*)d_in[5];
    const float* Wlm = (const float*)d_in[6];
    const float* blm = (const float*)d_in[7];
    float* out = (float*)d_out;

    cudaFuncSetAttribute(k_logits_b, cudaFuncAttributeMaxDynamicSharedMemorySize,
                         LOG_SMEM);
    cudaFuncSetAttribute(k_qkv_h, cudaFuncAttributeMaxDynamicSharedMemorySize,
                         LOG_SMEM);
    cudaFuncSetAttribute(k_flash, cudaFuncAttributeMaxDynamicSharedMemorySize,
                         FLASH_SMEM);

    // One-time stream/event setup (runs on the first, non-captured call).
    static cudaStream_t s_side = nullptr;
    static cudaEvent_t ev_fork = nullptr, ev_join = nullptr;
    if (!s_side) {
        cudaStreamCreateWithFlags(&s_side, cudaStreamNonBlocking);
        cudaEventCreateWithFlags(&ev_fork, cudaEventDisableTiming);
        cudaEventCreateWithFlags(&ev_join, cudaEventDisableTiming);
    }

    // Fork: W_lm fp16 conversion trickles (grid-stride, 592 CTAs) alongside the
    // attention chain; only k_logits_b consumes g_wh, so join right before it.
    cudaEventRecord(ev_fork, 0);
    cudaStreamWaitEvent(s_side, ev_fork, 0);
    k_w2h<<<592, 256, 0, s_side>>>(Wlm);
    cudaEventRecord(ev_join, s_side);

    k_wqkv<<<1536, 256>>>(Wq, Wk, Wv);
    k_embed<<<BTn, 256>>>(idx, tok, pos);
    k_qkv_h<<<dim3(16, 12), 256, LOG_SMEM>>>();
    k_flash<<<128, 256, FLASH_SMEM>>>();

    cudaStreamWaitEvent(0, ev_join, 0);
    k_logits_b<<<dim3(16, NBN), 256, LOG_SMEM>>>(blm, out);
}